// round 10
// baseline (speedup 1.0000x reference)
#include <cuda_runtime.h>
#include <math.h>
#include <stdint.h>

#define E_DIM   1024
#define S_LEN   2048
#define N_BATCH 2
#define N_HEADS 16
#define H_DIM   64
#define M_ROWS  (N_BATCH * S_LEN)   // 4096
#define ME      ((size_t)M_ROWS * E_DIM)   // 4M elems
#define EE      ((size_t)E_DIM * E_DIM)    // 1M elems

// ---------- global scratch (allocation-free) ----------
__device__ uint32_t s_xq_hi[ME], s_xq_lo[ME];
__device__ uint32_t s_xk_hi[ME], s_xk_lo[ME];
__device__ uint32_t s_xv_hi[ME], s_xv_lo[ME];
__device__ uint32_t s_wq_hi[EE], s_wq_lo[EE];
__device__ uint32_t s_wk_hi[EE], s_wk_lo[EE];
__device__ uint32_t s_wv_hi[EE], s_wv_lo[EE];
__device__ uint32_t s_wo_hi[EE], s_wo_lo[EE];
__device__ uint32_t s_q_hi[ME], s_q_lo[ME];
__device__ uint32_t s_k_hi[ME], s_k_lo[ME];
__device__ uint32_t s_vt_hi[ME], s_vt_lo[ME];   // [bh][d][s]
__device__ uint32_t s_o_hi[ME], s_o_lo[ME];

// ===================== helpers =====================
__device__ __forceinline__ uint32_t smem_u32(const void* p) {
    uint32_t a;
    asm("{ .reg .u64 t; cvta.to.shared.u64 t, %1; cvt.u32.u64 %0, t; }" : "=r"(a) : "l"(p));
    return a;
}
__device__ __forceinline__ uint32_t cvt_tf32(float f) {
    uint32_t u;
    asm("cvt.rna.tf32.f32 %0, %1;" : "=r"(u) : "f"(f));
    return u;
}
__device__ __forceinline__ void split2(float f, uint32_t& hi, uint32_t& lo) {
    hi = cvt_tf32(f);
    lo = cvt_tf32(f - __uint_as_float(hi));
}
__device__ __forceinline__ void split4(float4 v, uint4& hi, uint4& lo) {
    split2(v.x, hi.x, lo.x);
    split2(v.y, hi.y, lo.y);
    split2(v.z, hi.z, lo.z);
    split2(v.w, hi.w, lo.w);
}

#define CP16(dst, src) \
    asm volatile("cp.async.cg.shared.global [%0], [%1], 16;" :: "r"(dst), "l"(src))
#define CPCOMMIT() asm volatile("cp.async.commit_group;" ::: "memory")
#define CPWAIT1()  asm volatile("cp.async.wait_group 1;" ::: "memory")
#define CPWAIT0()  asm volatile("cp.async.wait_group 0;" ::: "memory")

#define LDSM_X4(r0, r1, r2, r3, addr)                                          \
    asm volatile("ldmatrix.sync.aligned.m8n8.x4.shared.b16 {%0,%1,%2,%3}, [%4];" \
                 : "=r"(r0), "=r"(r1), "=r"(r2), "=r"(r3) : "r"(addr))
#define LDSM_X2(r0, r1, addr)                                                  \
    asm volatile("ldmatrix.sync.aligned.m8n8.x2.shared.b16 {%0,%1}, [%2];"     \
                 : "=r"(r0), "=r"(r1) : "r"(addr))

#define MMA_TF32(d, A, b0v, b1v)                                               \
    asm volatile("mma.sync.aligned.m16n8k8.row.col.f32.tf32.tf32.f32 "         \
                 "{%0,%1,%2,%3}, {%4,%5,%6,%7}, {%8,%9}, {%0,%1,%2,%3};"       \
                 : "+f"((d)[0]), "+f"((d)[1]), "+f"((d)[2]), "+f"((d)[3])      \
                 : "r"((A)[0]), "r"((A)[1]), "r"((A)[2]), "r"((A)[3]),         \
                   "r"(b0v), "r"(b1v))

#define STS64(addr, v0, v1) \
    asm volatile("st.shared.v2.f32 [%0], {%1,%2};" :: "r"(addr), "f"(v0), "f"(v1))
#define BARP(id) asm volatile("bar.sync %0, 64;" :: "r"(id) : "memory")

// ===================== fused pre-split kernels =====================
__global__ __launch_bounds__(256) void split_me_kernel(
    const float4* __restrict__ q, const float4* __restrict__ k, const float4* __restrict__ v)
{
    const int t = blockIdx.y;
    const float4* src = (t == 0) ? q : ((t == 1) ? k : v);
    uint4* hi = (t == 0) ? (uint4*)s_xq_hi : ((t == 1) ? (uint4*)s_xk_hi : (uint4*)s_xv_hi);
    uint4* lo = (t == 0) ? (uint4*)s_xq_lo : ((t == 1) ? (uint4*)s_xk_lo : (uint4*)s_xv_lo);
    int i = blockIdx.x * 256 + threadIdx.x;
    uint4 h, l;
    split4(src[i], h, l);
    hi[i] = h;
    lo[i] = l;
}
__global__ __launch_bounds__(256) void split_w_kernel(
    const float4* __restrict__ wq, const float4* __restrict__ wk,
    const float4* __restrict__ wv, const float4* __restrict__ wo)
{
    const int t = blockIdx.y;
    const float4* src = (t == 0) ? wq : ((t == 1) ? wk : ((t == 2) ? wv : wo));
    uint4* hi = (t == 0) ? (uint4*)s_wq_hi : ((t == 1) ? (uint4*)s_wk_hi
              : ((t == 2) ? (uint4*)s_wv_hi : (uint4*)s_wo_hi));
    uint4* lo = (t == 0) ? (uint4*)s_wq_lo : ((t == 1) ? (uint4*)s_wk_lo
              : ((t == 2) ? (uint4*)s_wv_lo : (uint4*)s_wo_lo));
    int i = blockIdx.x * 256 + threadIdx.x;
    uint4 h, l;
    split4(src[i], h, l);
    hi[i] = h;
    lo[i] = l;
}

// ===================== GEMM (identical to R9) =====================
#define NCHUNK   (E_DIM / 16)
#define ROWB     80
#define AHI_OFF  0u
#define ALO_OFF  10240u
#define BHI_OFF  20480u
#define BLO_OFF  30720u
#define STAGE_B  40960u
#define GEMM_SMEM (2 * 40960)

__global__ __launch_bounds__(256, 2) void gemm_tc_kernel(
    const float* __restrict__ bq, const float* __restrict__ bk,
    const float* __restrict__ bv, const float* __restrict__ bo,
    float* __restrict__ out, int is_out)
{
    extern __shared__ char smem[];
    const int z = blockIdx.z;
    const uint32_t *Xhi, *Xlo, *Whi, *Wlo;
    const float* Bv;
    int mode;
    if (is_out) { Xhi = s_o_hi;  Xlo = s_o_lo;  Whi = s_wo_hi; Wlo = s_wo_lo; Bv = bo; mode = 3; }
    else if (z == 0) { Xhi = s_xq_hi; Xlo = s_xq_lo; Whi = s_wq_hi; Wlo = s_wq_lo; Bv = bq; mode = 0; }
    else if (z == 1) { Xhi = s_xk_hi; Xlo = s_xk_lo; Whi = s_wk_hi; Wlo = s_wk_lo; Bv = bk; mode = 1; }
    else             { Xhi = s_xv_hi; Xlo = s_xv_lo; Whi = s_wv_hi; Wlo = s_wv_lo; Bv = bv; mode = 2; }

    const int tid  = threadIdx.x;
    const int lane = tid & 31;
    const int wid  = tid >> 5;
    const int wm   = wid >> 2;
    const int wn   = wid & 3;
    const int m0 = blockIdx.y * 128;
    const int n0 = blockIdx.x * 128;

    const uint32_t sb = smem_u32(smem);

    const int prow = tid >> 2;
    const int pc4  = tid & 3;
    const size_t xoff = (size_t)(m0 + prow) * E_DIM + pc4 * 4;
    const size_t woff = (size_t)(n0 + prow) * E_DIM + pc4 * 4;
    const uint32_t pd = (uint32_t)prow * ROWB + (uint32_t)pc4 * 16;

    #define GCP_CHUNK(c, st) do {                                              \
        uint32_t base_ = sb + (uint32_t)(st) * STAGE_B + pd;                   \
        size_t ko_ = (size_t)(c) * 16;                                         \
        _Pragma("unroll")                                                      \
        for (int r = 0; r < 2; ++r) {                                          \
            size_t sx_ = xoff + (size_t)r * 64 * E_DIM + ko_;                  \
            size_t sw_ = woff + (size_t)r * 64 * E_DIM + ko_;                  \
            uint32_t dd_ = base_ + (uint32_t)r * 5120;                         \
            CP16(dd_ + AHI_OFF, Xhi + sx_);                                    \
            CP16(dd_ + ALO_OFF, Xlo + sx_);                                    \
            CP16(dd_ + BHI_OFF, Whi + sw_);                                    \
            CP16(dd_ + BLO_OFF, Wlo + sw_);                                    \
        }                                                                      \
    } while (0)

    GCP_CHUNK(0, 0); CPCOMMIT();
    GCP_CHUNK(1, 1); CPCOMMIT();

    const int i4 = lane >> 3, r8 = lane & 7;
    const uint32_t a_off = (uint32_t)(wm * 64 + ((i4 & 1) << 3) + r8) * ROWB
                         + (uint32_t)((i4 >> 1) << 4);
    const uint32_t b_off = (uint32_t)(wn * 32 + r8) * ROWB
                         + (uint32_t)((i4 & 1) << 4);

    float acc[4][4][4];
#pragma unroll
    for (int mt = 0; mt < 4; ++mt)
#pragma unroll
        for (int nt = 0; nt < 4; ++nt)
#pragma unroll
            for (int r = 0; r < 4; ++r) acc[mt][nt][r] = 0.f;

    for (int c = 0; c < NCHUNK; ++c) {
        CPWAIT1();
        __syncthreads();
        const uint32_t stb = sb + (uint32_t)(c & 1) * STAGE_B;

#pragma unroll
        for (int ks = 0; ks < 2; ++ks) {
            uint32_t bhv[4][2], blv[4][2];
#pragma unroll
            for (int nt = 0; nt < 4; ++nt) {
                const uint32_t ba = stb + b_off + nt * (8 * ROWB) + ks * 32;
                LDSM_X2(bhv[nt][0], bhv[nt][1], ba + BHI_OFF);
                LDSM_X2(blv[nt][0], blv[nt][1], ba + BLO_OFF);
            }
#pragma unroll
            for (int mt = 0; mt < 4; ++mt) {
                const uint32_t aa = stb + a_off + mt * (16 * ROWB) + ks * 32;
                uint32_t ah[4], al[4];
                LDSM_X4(ah[0], ah[1], ah[2], ah[3], aa + AHI_OFF);
                LDSM_X4(al[0], al[1], al[2], al[3], aa + ALO_OFF);
#pragma unroll
                for (int nt = 0; nt < 4; ++nt) {
                    MMA_TF32(acc[mt][nt], ah, blv[nt][0], blv[nt][1]);
                    MMA_TF32(acc[mt][nt], al, bhv[nt][0], bhv[nt][1]);
                    MMA_TF32(acc[mt][nt], ah, bhv[nt][0], bhv[nt][1]);
                }
            }
        }

        __syncthreads();
        if (c + 2 < NCHUNK) GCP_CHUNK(c + 2, c & 1);
        CPCOMMIT();
    }

    if (mode == 3) {
#pragma unroll
        for (int nt = 0; nt < 4; ++nt) {
            const int col = n0 + wn * 32 + nt * 8 + 2 * (lane & 3);
            const float bx = __ldg(&Bv[col]);
            const float by = __ldg(&Bv[col + 1]);
#pragma unroll
            for (int mt = 0; mt < 4; ++mt) {
                const int r0i = m0 + wm * 64 + mt * 16 + (lane >> 2);
                *(float2*)&out[(size_t)r0i * E_DIM + col] =
                    make_float2(acc[mt][nt][0] + bx, acc[mt][nt][1] + by);
                *(float2*)&out[(size_t)(r0i + 8) * E_DIM + col] =
                    make_float2(acc[mt][nt][2] + bx, acc[mt][nt][3] + by);
            }
        }
    } else if (mode == 2) {
        const int bq2 = m0 >> 11;
#pragma unroll
        for (int nt = 0; nt < 4; ++nt) {
            const int col = n0 + wn * 32 + nt * 8 + 2 * (lane & 3);
            const int hh = col >> 6, dd = col & 63;
            const float bx = __ldg(&Bv[col]);
            const float by = __ldg(&Bv[col + 1]);
            const size_t b0i = ((size_t)(bq2 * 16 + hh) * 64 + dd) * S_LEN;
            const size_t b1i = b0i + S_LEN;
#pragma unroll
            for (int mt = 0; mt < 4; ++mt) {
                const int s = (m0 & 2047) + wm * 64 + mt * 16 + (lane >> 2);
                uint32_t h0, l0, h1, l1;
                split2(acc[mt][nt][0] + bx, h0, l0);
                split2(acc[mt][nt][1] + by, h1, l1);
                s_vt_hi[b0i + s] = h0; s_vt_lo[b0i + s] = l0;
                s_vt_hi[b1i + s] = h1; s_vt_lo[b1i + s] = l1;
                split2(acc[mt][nt][2] + bx, h0, l0);
                split2(acc[mt][nt][3] + by, h1, l1);
                s_vt_hi[b0i + s + 8] = h0; s_vt_lo[b0i + s + 8] = l0;
                s_vt_hi[b1i + s + 8] = h1; s_vt_lo[b1i + s + 8] = l1;
            }
        }
    } else {
        uint32_t* Yh = (mode == 0) ? s_q_hi : s_k_hi;
        uint32_t* Yl = (mode == 0) ? s_q_lo : s_k_lo;
#pragma unroll
        for (int nt = 0; nt < 4; ++nt) {
            const int col = n0 + wn * 32 + nt * 8 + 2 * (lane & 3);
            const float bx = __ldg(&Bv[col]);
            const float by = __ldg(&Bv[col + 1]);
#pragma unroll
            for (int mt = 0; mt < 4; ++mt) {
                const int r0i = m0 + wm * 64 + mt * 16 + (lane >> 2);
                uint32_t h0, l0, h1, l1;
                split2(acc[mt][nt][0] + bx, h0, l0);
                split2(acc[mt][nt][1] + by, h1, l1);
                *(uint2*)&Yh[(size_t)r0i * E_DIM + col] = make_uint2(h0, h1);
                *(uint2*)&Yl[(size_t)r0i * E_DIM + col] = make_uint2(l0, l1);
                split2(acc[mt][nt][2] + bx, h0, l0);
                split2(acc[mt][nt][3] + by, h1, l1);
                *(uint2*)&Yh[(size_t)(r0i + 8) * E_DIM + col] = make_uint2(h0, h1);
                *(uint2*)&Yl[(size_t)(r0i + 8) * E_DIM + col] = make_uint2(l0, l1);
            }
        }
    }
}

// ===================== Causal flash attention: 128-row q-tiles =====================
// CTA: 128 q-rows x (b,h); 8 warps: rg=w&3 (32 rows = 2 mt frags), cn=w>>2 (32 of 64 cols).
// smem: Qhi|Qlo 64K | K 2-stage hi/lo 64K | VT 1-stage hi/lo 32K | P hi/lo 64K | red 2K
#define AQH   0u
#define AQL   32768u
#define AKB   65536u      // + stage*32768; lo at +16384
#define AVH   131072u
#define AVL   147456u
#define APH   163840u     // + rg*8192
#define APL   196608u
#define ARED  229376u
#define ATTN_SMEM 231424

__global__ __launch_bounds__(256) void attn_tc_kernel(void)
{
    extern __shared__ char smem[];
    const uint32_t sb = smem_u32(smem);
    float* red_m = (float*)(smem + ARED);          // [2][128]
    float* red_l = (float*)(smem + ARED + 1024);   // [2][128]

    const int tid = threadIdx.x, lane = tid & 31, w = tid >> 5;
    const int rg = w & 3, cn = w >> 2;
    const int i = blockIdx.x, bh = blockIdx.y;
    const int b = bh >> 4, h = bh & 15;

    const size_t qbase  = ((size_t)b * S_LEN + i * 128) * E_DIM + h * 64;
    const size_t kbase  = (size_t)b * S_LEN * E_DIM + h * 64;
    const size_t vtbase = (size_t)bh * 64 * S_LEN;

    // Q: 128 rows x 16 slots, hi+lo
#pragma unroll
    for (int l = 0; l < 8; ++l) {
        int idx = tid + l * 256, row = idx >> 4, sl = idx & 15;
        uint32_t sw = (uint32_t)(row * 256 + ((sl ^ (row & 7)) << 4));
        size_t src = qbase + (size_t)row * E_DIM + sl * 4;
        CP16(sb + AQH + sw, s_q_hi + src);
        CP16(sb + AQL + sw, s_q_lo + src);
    }

    #define ISSUE_K(j_, st_) do {                                              \
        uint32_t kb_ = sb + AKB + (uint32_t)(st_) * 32768u;                    \
        _Pragma("unroll")                                                      \
        for (int l = 0; l < 4; ++l) {                                          \
            int idx_ = tid + l * 256, row_ = idx_ >> 4, sl_ = idx_ & 15;       \
            uint32_t sw_ = (uint32_t)(row_ * 256 + ((sl_ ^ (row_ & 7)) << 4)); \
            size_t ks_ = kbase + (size_t)((j_) * 64 + row_) * E_DIM + sl_ * 4; \
            CP16(kb_ + sw_, s_k_hi + ks_);                                     \
            CP16(kb_ + 16384u + sw_, s_k_lo + ks_);                            \
        }                                                                      \
    } while (0)

    #define ISSUE_VT(j_) do {                                                  \
        _Pragma("unroll")                                                      \
        for (int l = 0; l < 4; ++l) {                                          \
            int idx_ = tid + l * 256, row_ = idx_ >> 4, sl_ = idx_ & 15;       \
            uint32_t sw_ = (uint32_t)(row_ * 256 + ((sl_ ^ (row_ & 7)) << 4)); \
            size_t vs_ = vtbase + (size_t)row_ * S_LEN + (j_) * 64 + sl_ * 4;  \
            CP16(sb + AVH + sw_, s_vt_hi + vs_);                               \
            CP16(sb + AVL + sw_, s_vt_lo + vs_);                               \
        }                                                                      \
    } while (0)

    const int jmax = 2 * i + 1;

    ISSUE_K(0, 0);
    CPCOMMIT();                 // group: Q + K0
    ISSUE_VT(0);
    ISSUE_K(1, 1);
    CPCOMMIT();                 // group: VT0 + K1
    CPWAIT1();                  // Q + K0 ready
    __syncthreads();

    const int i4 = lane >> 3, r8 = lane & 7;
    const int lr = lane >> 2;
    const int lc0 = 2 * (lane & 3);
    const int arow = ((i4 & 1) << 3) + r8;     // row-within-16 for A-frag ldmatrix
    const int aslot_hi = i4 >> 1;              // slot low bit for A
    const int bslot_lo = i4 & 1;               // slot low bit for B
    const int pslot_lo = (lane & 3) >> 1;
    const uint32_t pword = (uint32_t)((lane & 1) << 3);
    const uint32_t pgbase_h = sb + APH + (uint32_t)rg * 8192;
    const uint32_t pgbase_l = sb + APL + (uint32_t)rg * 8192;

    float m_prev[2][2], lsum[2][2];
#pragma unroll
    for (int mt = 0; mt < 2; ++mt)
#pragma unroll
        for (int h2 = 0; h2 < 2; ++h2) { m_prev[mt][h2] = -INFINITY; lsum[mt][h2] = 0.f; }
    float o[2][4][4];
#pragma unroll
    for (int mt = 0; mt < 2; ++mt)
#pragma unroll
        for (int nt = 0; nt < 4; ++nt)
#pragma unroll
            for (int r = 0; r < 4; ++r) o[mt][nt][r] = 0.f;

    for (int j = 0; j <= jmax; ++j) {
        const uint32_t kb = sb + AKB + (uint32_t)(j & 1) * 32768u;

        // ---- S = Q K^T ----
        float sacc[2][4][4];
#pragma unroll
        for (int mt = 0; mt < 2; ++mt)
#pragma unroll
            for (int nt = 0; nt < 4; ++nt)
#pragma unroll
                for (int r = 0; r < 4; ++r) sacc[mt][nt][r] = 0.f;

#pragma unroll
        for (int ks = 0; ks < 8; ++ks) {
            uint32_t khv[4][2], klv[4][2];
#pragma unroll
            for (int nt = 0; nt < 4; ++nt) {
                const int brow = cn * 32 + (nt << 3) + r8;
                const uint32_t boff = (uint32_t)(brow * 256
                    + ((((ks << 1) | bslot_lo) ^ (brow & 7)) << 4));
                LDSM_X2(khv[nt][0], khv[nt][1], kb + boff);
                LDSM_X2(klv[nt][0], klv[nt][1], kb + 16384u + boff);
            }
#pragma unroll
            for (int mt = 0; mt < 2; ++mt) {
                const int qrow = rg * 32 + mt * 16 + arow;
                const uint32_t aoff = (uint32_t)(qrow * 256
                    + ((((ks << 1) | aslot_hi) ^ (qrow & 7)) << 4));
                uint32_t ah[4], al[4];
                LDSM_X4(ah[0], ah[1], ah[2], ah[3], sb + AQH + aoff);
                LDSM_X4(al[0], al[1], al[2], al[3], sb + AQL + aoff);
#pragma unroll
                for (int nt = 0; nt < 4; ++nt) {
                    MMA_TF32(sacc[mt][nt], ah, klv[nt][0], klv[nt][1]);
                    MMA_TF32(sacc[mt][nt], al, khv[nt][0], khv[nt][1]);
                    MMA_TF32(sacc[mt][nt], ah, khv[nt][0], khv[nt][1]);
                }
            }
        }

        // ---- mask + softmax ----
        float mloc[2][2] = {{-INFINITY, -INFINITY}, {-INFINITY, -INFINITY}};
#pragma unroll
        for (int mt = 0; mt < 2; ++mt) {
            const int qr0 = i * 128 + rg * 32 + mt * 16 + lr;
#pragma unroll
            for (int nt = 0; nt < 4; ++nt) {
                const int c0 = j * 64 + cn * 32 + (nt << 3) + lc0;
                float s0 = sacc[mt][nt][0] * 0.125f, s1 = sacc[mt][nt][1] * 0.125f;
                float s2 = sacc[mt][nt][2] * 0.125f, s3 = sacc[mt][nt][3] * 0.125f;
                if (c0     > qr0)     s0 = -INFINITY;
                if (c0 + 1 > qr0)     s1 = -INFINITY;
                if (c0     > qr0 + 8) s2 = -INFINITY;
                if (c0 + 1 > qr0 + 8) s3 = -INFINITY;
                sacc[mt][nt][0] = s0; sacc[mt][nt][1] = s1;
                sacc[mt][nt][2] = s2; sacc[mt][nt][3] = s3;
                mloc[mt][0] = fmaxf(mloc[mt][0], fmaxf(s0, s1));
                mloc[mt][1] = fmaxf(mloc[mt][1], fmaxf(s2, s3));
            }
#pragma unroll
            for (int h2 = 0; h2 < 2; ++h2) {
                mloc[mt][h2] = fmaxf(mloc[mt][h2], __shfl_xor_sync(0xffffffffu, mloc[mt][h2], 1));
                mloc[mt][h2] = fmaxf(mloc[mt][h2], __shfl_xor_sync(0xffffffffu, mloc[mt][h2], 2));
            }
        }
        if ((lane & 3) == 0) {
#pragma unroll
            for (int mt = 0; mt < 2; ++mt) {
                red_m[cn * 128 + rg * 32 + mt * 16 + lr]     = mloc[mt][0];
                red_m[cn * 128 + rg * 32 + mt * 16 + lr + 8] = mloc[mt][1];
            }
        }
        BARP(rg + 1);

        float fac[2][2], m_new[2][2];
#pragma unroll
        for (int mt = 0; mt < 2; ++mt)
#pragma unroll
            for (int h2 = 0; h2 < 2; ++h2) {
                const int row = rg * 32 + mt * 16 + lr + h2 * 8;
                const float mo = red_m[(cn ^ 1) * 128 + row];
                m_new[mt][h2] = fmaxf(m_prev[mt][h2], fmaxf(mloc[mt][h2], mo));
                fac[mt][h2] = (m_prev[mt][h2] == -INFINITY)
                            ? 0.f : __expf(m_prev[mt][h2] - m_new[mt][h2]);
                m_prev[mt][h2] = m_new[mt][h2];
            }

        float ls[2][2] = {{0.f, 0.f}, {0.f, 0.f}};
#pragma unroll
        for (int mt = 0; mt < 2; ++mt) {
            const int rA = mt * 16 + lr, rB = rA + 8;
            const uint32_t rowA_h = pgbase_h + rA * 256, rowB_h = pgbase_h + rB * 256;
            const uint32_t rowA_l = pgbase_l + rA * 256, rowB_l = pgbase_l + rB * 256;
#pragma unroll
            for (int nt = 0; nt < 4; ++nt) {
                float p0 = __expf(sacc[mt][nt][0] - m_new[mt][0]);
                float p1 = __expf(sacc[mt][nt][1] - m_new[mt][0]);
                float p2 = __expf(sacc[mt][nt][2] - m_new[mt][1]);
                float p3 = __expf(sacc[mt][nt][3] - m_new[mt][1]);
                ls[mt][0] += p0 + p1;
                ls[mt][1] += p2 + p3;
                const uint32_t slot = (uint32_t)((cn << 3) | (nt << 1) | pslot_lo);
                uint32_t h0, l0, h1, l1;
                split2(p0, h0, l0); split2(p1, h1, l1);
                STS64(rowA_h + ((slot ^ (rA & 7)) << 4) + pword,
                      __uint_as_float(h0), __uint_as_float(h1));
                STS64(rowA_l + ((slot ^ (rA & 7)) << 4) + pword,
                      __uint_as_float(l0), __uint_as_float(l1));
                split2(p2, h0, l0); split2(p3, h1, l1);
                STS64(rowB_h + ((slot ^ (rB & 7)) << 4) + pword,
                      __uint_as_float(h0), __uint_as_float(h1));
                STS64(rowB_l + ((slot ^ (rB & 7)) << 4) + pword,
                      __uint_as_float(l0), __uint_as_float(l1));
            }
#pragma unroll
            for (int h2 = 0; h2 < 2; ++h2) {
                ls[mt][h2] += __shfl_xor_sync(0xffffffffu, ls[mt][h2], 1);
                ls[mt][h2] += __shfl_xor_sync(0xffffffffu, ls[mt][h2], 2);
            }
        }
        if ((lane & 3) == 0) {
#pragma unroll
            for (int mt = 0; mt < 2; ++mt) {
                red_l[cn * 128 + rg * 32 + mt * 16 + lr]     = ls[mt][0];
                red_l[cn * 128 + rg * 32 + mt * 16 + lr + 8] = ls[mt][1];
            }
        }
        BARP(rg + 1);
#pragma unroll
        for (int mt = 0; mt < 2; ++mt)
#pragma unroll
            for (int h2 = 0; h2 < 2; ++h2) {
                const int row = rg * 32 + mt * 16 + lr + h2 * 8;
                lsum[mt][h2] = lsum[mt][h2] * fac[mt][h2] + red_l[row] + red_l[128 + row];
            }

#pragma unroll
        for (int mt = 0; mt < 2; ++mt)
#pragma unroll
            for (int nt = 0; nt < 4; ++nt) {
                o[mt][nt][0] *= fac[mt][0]; o[mt][nt][1] *= fac[mt][0];
                o[mt][nt][2] *= fac[mt][1]; o[mt][nt][3] *= fac[mt][1];
            }

        // VT(j) + K(j+1) must be resident; also publishes P stores CTA-wide
        CPWAIT0();
        __syncthreads();

        // ---- O += P V ----
#pragma unroll
        for (int ks = 0; ks < 8; ++ks) {
            uint32_t vhv[4][2], vlv[4][2];
#pragma unroll
            for (int nt = 0; nt < 4; ++nt) {
                const int vrow = cn * 32 + (nt << 3) + r8;
                const uint32_t voff = (uint32_t)(vrow * 256
                    + ((((ks << 1) | bslot_lo) ^ (vrow & 7)) << 4));
                LDSM_X2(vhv[nt][0], vhv[nt][1], sb + AVH + voff);
                LDSM_X2(vlv[nt][0], vlv[nt][1], sb + AVL + voff);
            }
#pragma unroll
            for (int mt = 0; mt < 2; ++mt) {
                const int prow_ = mt * 16 + arow;
                const uint32_t poff = (uint32_t)(prow_ * 256
                    + ((((ks << 1) | aslot_hi) ^ (prow_ & 7)) << 4));
                uint32_t ph[4], pl[4];
                LDSM_X4(ph[0], ph[1], ph[2], ph[3], pgbase_h + poff);
                LDSM_X4(pl[0], pl[1], pl[2], pl[3], pgbase_l + poff);
#pragma unroll
                for (int nt = 0; nt < 4; ++nt) {
                    MMA_TF32(o[mt][nt], ph, vlv[nt][0], vlv[nt][1]);
                    MMA_TF32(o[mt][nt], pl, vhv[nt][0], vhv[nt][1]);
                    MMA_TF32(o[mt][nt], ph, vhv[nt][0], vhv[nt][1]);
                }
            }
        }

        __syncthreads();   // PV reads (VT, P) done before refill / next P writes
        if (j < jmax) {
            ISSUE_VT(j + 1);
            if (j + 1 < jmax) ISSUE_K(j + 2, j & 1);
            CPCOMMIT();
        }
    }

    // ---- epilogue: split O for out-projection ----
#pragma unroll
    for (int mt = 0; mt < 2; ++mt) {
        const float inv0 = 1.f / lsum[mt][0];
        const float inv1 = 1.f / lsum[mt][1];
        const size_t rowA = ((size_t)b * S_LEN + i * 128 + rg * 32 + mt * 16 + lr) * E_DIM;
        const size_t rowB = rowA + (size_t)8 * E_DIM;
#pragma unroll
        for (int nt = 0; nt < 4; ++nt) {
            const int col = h * 64 + cn * 32 + (nt << 3) + lc0;
            uint32_t h0, l0, h1, l1;
            split2(o[mt][nt][0] * inv0, h0, l0);
            split2(o[mt][nt][1] * inv0, h1, l1);
            *(uint2*)&s_o_hi[rowA + col] = make_uint2(h0, h1);
            *(uint2*)&s_o_lo[rowA + col] = make_uint2(l0, l1);
            split2(o[mt][nt][2] * inv1, h0, l0);
            split2(o[mt][nt][3] * inv1, h1, l1);
            *(uint2*)&s_o_hi[rowB + col] = make_uint2(h0, h1);
            *(uint2*)&s_o_lo[rowB + col] = make_uint2(l0, l1);
        }
    }
}

// ===================== launch =====================
extern "C" void kernel_launch(void* const* d_in, const int* in_sizes, int n_in,
                              void* d_out, int out_size)
{
    (void)in_sizes; (void)n_in; (void)out_size;
    const float* q  = (const float*)d_in[0];
    const float* k  = (const float*)d_in[1];
    const float* v  = (const float*)d_in[2];
    const float* Wq = (const float*)d_in[3];
    const float* bq = (const float*)d_in[4];
    const float* Wk = (const float*)d_in[5];
    const float* bk = (const float*)d_in[6];
    const float* Wv = (const float*)d_in[7];
    const float* bv = (const float*)d_in[8];
    const float* Wo = (const float*)d_in[9];
    const float* bo = (const float*)d_in[10];
    float* out = (float*)d_out;

    cudaFuncSetAttribute(gemm_tc_kernel, cudaFuncAttributeMaxDynamicSharedMemorySize, GEMM_SMEM);
    cudaFuncSetAttribute(attn_tc_kernel, cudaFuncAttributeMaxDynamicSharedMemorySize, ATTN_SMEM);

    // fused pre-split (2 launches)
    dim3 gridSM((unsigned)(ME / 4 / 256), 3);
    split_me_kernel<<<gridSM, 256>>>((const float4*)q, (const float4*)k, (const float4*)v);
    dim3 gridSW((unsigned)(EE / 4 / 256), 4);
    split_w_kernel<<<gridSW, 256>>>((const float4*)Wq, (const float4*)Wk,
                                    (const float4*)Wv, (const float4*)Wo);

    // Q/K/V projections (epilogues emit split attention operands)
    dim3 gridP(E_DIM / 128, M_ROWS / 128, 3);
    gemm_tc_kernel<<<gridP, 256, GEMM_SMEM>>>(bq, bk, bv, bo, out, 0);

    // causal flash attention, 128-row q-tiles (emits split O)
    dim3 gridA(S_LEN / 128, N_BATCH * N_HEADS);
    attn_tc_kernel<<<gridA, 256, ATTN_SMEM>>>();

    // output projection
    dim3 gridO(E_DIM / 128, M_ROWS / 128, 1);
    gemm_tc_kernel<<<gridO, 256, GEMM_SMEM>>>(bq, bk, bv, bo, out, 1);
}

// round 11
// speedup vs baseline: 1.0771x; 1.0771x over previous
#include <cuda_runtime.h>
#include <math.h>
#include <stdint.h>

#define E_DIM   1024
#define S_LEN   2048
#define N_BATCH 2
#define N_HEADS 16
#define H_DIM   64
#define M_ROWS  (N_BATCH * S_LEN)   // 4096
#define ME      ((size_t)M_ROWS * E_DIM)   // 4M elems
#define EE      ((size_t)E_DIM * E_DIM)    // 1M elems

// ---------- global scratch (allocation-free) ----------
__device__ uint32_t s_xq_hi[ME], s_xq_lo[ME];
__device__ uint32_t s_xk_hi[ME], s_xk_lo[ME];
__device__ uint32_t s_xv_hi[ME], s_xv_lo[ME];
__device__ uint32_t s_wq_hi[EE], s_wq_lo[EE];
__device__ uint32_t s_wk_hi[EE], s_wk_lo[EE];
__device__ uint32_t s_wv_hi[EE], s_wv_lo[EE];
__device__ uint32_t s_wo_hi[EE], s_wo_lo[EE];
__device__ uint32_t s_q_hi[ME], s_q_lo[ME];
__device__ uint32_t s_k_hi[ME], s_k_lo[ME];
__device__ uint32_t s_vt_hi[ME], s_vt_lo[ME];   // [bh][d][s]
__device__ uint32_t s_o_hi[ME], s_o_lo[ME];

// ===================== helpers =====================
__device__ __forceinline__ uint32_t smem_u32(const void* p) {
    uint32_t a;
    asm("{ .reg .u64 t; cvta.to.shared.u64 t, %1; cvt.u32.u64 %0, t; }" : "=r"(a) : "l"(p));
    return a;
}
__device__ __forceinline__ uint32_t cvt_tf32(float f) {
    uint32_t u;
    asm("cvt.rna.tf32.f32 %0, %1;" : "=r"(u) : "f"(f));
    return u;
}
__device__ __forceinline__ void split2(float f, uint32_t& hi, uint32_t& lo) {
    hi = cvt_tf32(f);
    lo = cvt_tf32(f - __uint_as_float(hi));
}
__device__ __forceinline__ void split4(float4 v, uint4& hi, uint4& lo) {
    split2(v.x, hi.x, lo.x);
    split2(v.y, hi.y, lo.y);
    split2(v.z, hi.z, lo.z);
    split2(v.w, hi.w, lo.w);
}

#define CP16(dst, src) \
    asm volatile("cp.async.cg.shared.global [%0], [%1], 16;" :: "r"(dst), "l"(src))
#define CPCOMMIT() asm volatile("cp.async.commit_group;" ::: "memory")
#define CPWAIT1()  asm volatile("cp.async.wait_group 1;" ::: "memory")
#define CPWAIT0()  asm volatile("cp.async.wait_group 0;" ::: "memory")

#define LDSM_X4(r0, r1, r2, r3, addr)                                          \
    asm volatile("ldmatrix.sync.aligned.m8n8.x4.shared.b16 {%0,%1,%2,%3}, [%4];" \
                 : "=r"(r0), "=r"(r1), "=r"(r2), "=r"(r3) : "r"(addr))
#define LDSM_X2(r0, r1, addr)                                                  \
    asm volatile("ldmatrix.sync.aligned.m8n8.x2.shared.b16 {%0,%1}, [%2];"     \
                 : "=r"(r0), "=r"(r1) : "r"(addr))

#define MMA_TF32(d, A, b0v, b1v)                                               \
    asm volatile("mma.sync.aligned.m16n8k8.row.col.f32.tf32.tf32.f32 "         \
                 "{%0,%1,%2,%3}, {%4,%5,%6,%7}, {%8,%9}, {%0,%1,%2,%3};"       \
                 : "+f"((d)[0]), "+f"((d)[1]), "+f"((d)[2]), "+f"((d)[3])      \
                 : "r"((A)[0]), "r"((A)[1]), "r"((A)[2]), "r"((A)[3]),         \
                   "r"(b0v), "r"(b1v))

#define STS64(addr, v0, v1) \
    asm volatile("st.shared.v2.f32 [%0], {%1,%2};" :: "r"(addr), "f"(v0), "f"(v1))
#define BARP(id) asm volatile("bar.sync %0, 64;" :: "r"(id) : "memory")

// ===================== fused pre-split kernels =====================
__global__ __launch_bounds__(256) void split_me_kernel(
    const float4* __restrict__ q, const float4* __restrict__ k, const float4* __restrict__ v)
{
    const int t = blockIdx.y;
    const float4* src = (t == 0) ? q : ((t == 1) ? k : v);
    uint4* hi = (t == 0) ? (uint4*)s_xq_hi : ((t == 1) ? (uint4*)s_xk_hi : (uint4*)s_xv_hi);
    uint4* lo = (t == 0) ? (uint4*)s_xq_lo : ((t == 1) ? (uint4*)s_xk_lo : (uint4*)s_xv_lo);
    int i = blockIdx.x * 256 + threadIdx.x;
    uint4 h, l;
    split4(src[i], h, l);
    hi[i] = h;
    lo[i] = l;
}
__global__ __launch_bounds__(256) void split_w_kernel(
    const float4* __restrict__ wq, const float4* __restrict__ wk,
    const float4* __restrict__ wv, const float4* __restrict__ wo)
{
    const int t = blockIdx.y;
    const float4* src = (t == 0) ? wq : ((t == 1) ? wk : ((t == 2) ? wv : wo));
    uint4* hi = (t == 0) ? (uint4*)s_wq_hi : ((t == 1) ? (uint4*)s_wk_hi
              : ((t == 2) ? (uint4*)s_wv_hi : (uint4*)s_wo_hi));
    uint4* lo = (t == 0) ? (uint4*)s_wq_lo : ((t == 1) ? (uint4*)s_wk_lo
              : ((t == 2) ? (uint4*)s_wv_lo : (uint4*)s_wo_lo));
    int i = blockIdx.x * 256 + threadIdx.x;
    uint4 h, l;
    split4(src[i], h, l);
    hi[i] = h;
    lo[i] = l;
}

// ===================== GEMM (identical to R9/R10) =====================
#define NCHUNK   (E_DIM / 16)
#define ROWB     80
#define AHI_OFF  0u
#define ALO_OFF  10240u
#define BHI_OFF  20480u
#define BLO_OFF  30720u
#define STAGE_B  40960u
#define GEMM_SMEM (2 * 40960)

__global__ __launch_bounds__(256, 2) void gemm_tc_kernel(
    const float* __restrict__ bq, const float* __restrict__ bk,
    const float* __restrict__ bv, const float* __restrict__ bo,
    float* __restrict__ out, int is_out)
{
    extern __shared__ char smem[];
    const int z = blockIdx.z;
    const uint32_t *Xhi, *Xlo, *Whi, *Wlo;
    const float* Bv;
    int mode;
    if (is_out) { Xhi = s_o_hi;  Xlo = s_o_lo;  Whi = s_wo_hi; Wlo = s_wo_lo; Bv = bo; mode = 3; }
    else if (z == 0) { Xhi = s_xq_hi; Xlo = s_xq_lo; Whi = s_wq_hi; Wlo = s_wq_lo; Bv = bq; mode = 0; }
    else if (z == 1) { Xhi = s_xk_hi; Xlo = s_xk_lo; Whi = s_wk_hi; Wlo = s_wk_lo; Bv = bk; mode = 1; }
    else             { Xhi = s_xv_hi; Xlo = s_xv_lo; Whi = s_wv_hi; Wlo = s_wv_lo; Bv = bv; mode = 2; }

    const int tid  = threadIdx.x;
    const int lane = tid & 31;
    const int wid  = tid >> 5;
    const int wm   = wid >> 2;
    const int wn   = wid & 3;
    const int m0 = blockIdx.y * 128;
    const int n0 = blockIdx.x * 128;

    const uint32_t sb = smem_u32(smem);

    const int prow = tid >> 2;
    const int pc4  = tid & 3;
    const size_t xoff = (size_t)(m0 + prow) * E_DIM + pc4 * 4;
    const size_t woff = (size_t)(n0 + prow) * E_DIM + pc4 * 4;
    const uint32_t pd = (uint32_t)prow * ROWB + (uint32_t)pc4 * 16;

    #define GCP_CHUNK(c, st) do {                                              \
        uint32_t base_ = sb + (uint32_t)(st) * STAGE_B + pd;                   \
        size_t ko_ = (size_t)(c) * 16;                                         \
        _Pragma("unroll")                                                      \
        for (int r = 0; r < 2; ++r) {                                          \
            size_t sx_ = xoff + (size_t)r * 64 * E_DIM + ko_;                  \
            size_t sw_ = woff + (size_t)r * 64 * E_DIM + ko_;                  \
            uint32_t dd_ = base_ + (uint32_t)r * 5120;                         \
            CP16(dd_ + AHI_OFF, Xhi + sx_);                                    \
            CP16(dd_ + ALO_OFF, Xlo + sx_);                                    \
            CP16(dd_ + BHI_OFF, Whi + sw_);                                    \
            CP16(dd_ + BLO_OFF, Wlo + sw_);                                    \
        }                                                                      \
    } while (0)

    GCP_CHUNK(0, 0); CPCOMMIT();
    GCP_CHUNK(1, 1); CPCOMMIT();

    const int i4 = lane >> 3, r8 = lane & 7;
    const uint32_t a_off = (uint32_t)(wm * 64 + ((i4 & 1) << 3) + r8) * ROWB
                         + (uint32_t)((i4 >> 1) << 4);
    const uint32_t b_off = (uint32_t)(wn * 32 + r8) * ROWB
                         + (uint32_t)((i4 & 1) << 4);

    float acc[4][4][4];
#pragma unroll
    for (int mt = 0; mt < 4; ++mt)
#pragma unroll
        for (int nt = 0; nt < 4; ++nt)
#pragma unroll
            for (int r = 0; r < 4; ++r) acc[mt][nt][r] = 0.f;

    for (int c = 0; c < NCHUNK; ++c) {
        CPWAIT1();
        __syncthreads();
        const uint32_t stb = sb + (uint32_t)(c & 1) * STAGE_B;

#pragma unroll
        for (int ks = 0; ks < 2; ++ks) {
            uint32_t bhv[4][2], blv[4][2];
#pragma unroll
            for (int nt = 0; nt < 4; ++nt) {
                const uint32_t ba = stb + b_off + nt * (8 * ROWB) + ks * 32;
                LDSM_X2(bhv[nt][0], bhv[nt][1], ba + BHI_OFF);
                LDSM_X2(blv[nt][0], blv[nt][1], ba + BLO_OFF);
            }
#pragma unroll
            for (int mt = 0; mt < 4; ++mt) {
                const uint32_t aa = stb + a_off + mt * (16 * ROWB) + ks * 32;
                uint32_t ah[4], al[4];
                LDSM_X4(ah[0], ah[1], ah[2], ah[3], aa + AHI_OFF);
                LDSM_X4(al[0], al[1], al[2], al[3], aa + ALO_OFF);
#pragma unroll
                for (int nt = 0; nt < 4; ++nt) {
                    MMA_TF32(acc[mt][nt], ah, blv[nt][0], blv[nt][1]);
                    MMA_TF32(acc[mt][nt], al, bhv[nt][0], bhv[nt][1]);
                    MMA_TF32(acc[mt][nt], ah, bhv[nt][0], bhv[nt][1]);
                }
            }
        }

        __syncthreads();
        if (c + 2 < NCHUNK) GCP_CHUNK(c + 2, c & 1);
        CPCOMMIT();
    }

    if (mode == 3) {
#pragma unroll
        for (int nt = 0; nt < 4; ++nt) {
            const int col = n0 + wn * 32 + nt * 8 + 2 * (lane & 3);
            const float bx = __ldg(&Bv[col]);
            const float by = __ldg(&Bv[col + 1]);
#pragma unroll
            for (int mt = 0; mt < 4; ++mt) {
                const int r0i = m0 + wm * 64 + mt * 16 + (lane >> 2);
                *(float2*)&out[(size_t)r0i * E_DIM + col] =
                    make_float2(acc[mt][nt][0] + bx, acc[mt][nt][1] + by);
                *(float2*)&out[(size_t)(r0i + 8) * E_DIM + col] =
                    make_float2(acc[mt][nt][2] + bx, acc[mt][nt][3] + by);
            }
        }
    } else if (mode == 2) {
        const int bq2 = m0 >> 11;
#pragma unroll
        for (int nt = 0; nt < 4; ++nt) {
            const int col = n0 + wn * 32 + nt * 8 + 2 * (lane & 3);
            const int hh = col >> 6, dd = col & 63;
            const float bx = __ldg(&Bv[col]);
            const float by = __ldg(&Bv[col + 1]);
            const size_t b0i = ((size_t)(bq2 * 16 + hh) * 64 + dd) * S_LEN;
            const size_t b1i = b0i + S_LEN;
#pragma unroll
            for (int mt = 0; mt < 4; ++mt) {
                const int s = (m0 & 2047) + wm * 64 + mt * 16 + (lane >> 2);
                uint32_t h0, l0, h1, l1;
                split2(acc[mt][nt][0] + bx, h0, l0);
                split2(acc[mt][nt][1] + by, h1, l1);
                s_vt_hi[b0i + s] = h0; s_vt_lo[b0i + s] = l0;
                s_vt_hi[b1i + s] = h1; s_vt_lo[b1i + s] = l1;
                split2(acc[mt][nt][2] + bx, h0, l0);
                split2(acc[mt][nt][3] + by, h1, l1);
                s_vt_hi[b0i + s + 8] = h0; s_vt_lo[b0i + s + 8] = l0;
                s_vt_hi[b1i + s + 8] = h1; s_vt_lo[b1i + s + 8] = l1;
            }
        }
    } else {
        uint32_t* Yh = (mode == 0) ? s_q_hi : s_k_hi;
        uint32_t* Yl = (mode == 0) ? s_q_lo : s_k_lo;
#pragma unroll
        for (int nt = 0; nt < 4; ++nt) {
            const int col = n0 + wn * 32 + nt * 8 + 2 * (lane & 3);
            const float bx = __ldg(&Bv[col]);
            const float by = __ldg(&Bv[col + 1]);
#pragma unroll
            for (int mt = 0; mt < 4; ++mt) {
                const int r0i = m0 + wm * 64 + mt * 16 + (lane >> 2);
                uint32_t h0, l0, h1, l1;
                split2(acc[mt][nt][0] + bx, h0, l0);
                split2(acc[mt][nt][1] + by, h1, l1);
                *(uint2*)&Yh[(size_t)r0i * E_DIM + col] = make_uint2(h0, h1);
                *(uint2*)&Yl[(size_t)r0i * E_DIM + col] = make_uint2(l0, l1);
                split2(acc[mt][nt][2] + bx, h0, l0);
                split2(acc[mt][nt][3] + by, h1, l1);
                *(uint2*)&Yh[(size_t)(r0i + 8) * E_DIM + col] = make_uint2(h0, h1);
                *(uint2*)&Yl[(size_t)(r0i + 8) * E_DIM + col] = make_uint2(l0, l1);
            }
        }
    }
}

// ===================== Causal flash attention: 128-row q-tiles =====================
// 8 warps: rg=w&3 (32 rows), cn=w>>2 (32 of 64 cols). K and VT both 2-stage.
// P stored hi-only; softmax denominator accumulated from the SAME rounded P values
// (exact convex combination -> P-rounding error largely cancels).
// smem: Qhi|Qlo 64K | K 2st 64K | VT 2st 64K | Phi 32K | red 2K = 231424
#define AQH   0u
#define AQL   32768u
#define AKB   65536u      // + stage*32768; lo at +16384
#define AVB   131072u     // + stage*32768; lo at +16384
#define APH   196608u     // + rg*8192
#define ARED  229376u
#define ATTN_SMEM 231424

__global__ __launch_bounds__(256) void attn_tc_kernel(void)
{
    extern __shared__ char smem[];
    const uint32_t sb = smem_u32(smem);
    float* red_m = (float*)(smem + ARED);          // [2][128]
    float* red_l = (float*)(smem + ARED + 1024);   // [2][128]

    const int tid = threadIdx.x, lane = tid & 31, w = tid >> 5;
    const int rg = w & 3, cn = w >> 2;
    const int i = (int)gridDim.x - 1 - (int)blockIdx.x;   // heavy tiles first
    const int bh = blockIdx.y;
    const int b = bh >> 4, h = bh & 15;

    const size_t qbase  = ((size_t)b * S_LEN + i * 128) * E_DIM + h * 64;
    const size_t kbase  = (size_t)b * S_LEN * E_DIM + h * 64;
    const size_t vtbase = (size_t)bh * 64 * S_LEN;

    // Q: 128 rows x 16 slots, hi+lo (group 0)
#pragma unroll
    for (int l = 0; l < 8; ++l) {
        int idx = tid + l * 256, row = idx >> 4, sl = idx & 15;
        uint32_t sw = (uint32_t)(row * 256 + ((sl ^ (row & 7)) << 4));
        size_t src = qbase + (size_t)row * E_DIM + sl * 4;
        CP16(sb + AQH + sw, s_q_hi + src);
        CP16(sb + AQL + sw, s_q_lo + src);
    }

    #define ISSUE_K(j_, st_) do {                                              \
        uint32_t kb_ = sb + AKB + (uint32_t)(st_) * 32768u;                    \
        _Pragma("unroll")                                                      \
        for (int l = 0; l < 4; ++l) {                                          \
            int idx_ = tid + l * 256, row_ = idx_ >> 4, sl_ = idx_ & 15;       \
            uint32_t sw_ = (uint32_t)(row_ * 256 + ((sl_ ^ (row_ & 7)) << 4)); \
            size_t ks_ = kbase + (size_t)((j_) * 64 + row_) * E_DIM + sl_ * 4; \
            CP16(kb_ + sw_, s_k_hi + ks_);                                     \
            CP16(kb_ + 16384u + sw_, s_k_lo + ks_);                            \
        }                                                                      \
    } while (0)

    #define ISSUE_VT(j_, st_) do {                                             \
        uint32_t vb_ = sb + AVB + (uint32_t)(st_) * 32768u;                    \
        _Pragma("unroll")                                                      \
        for (int l = 0; l < 4; ++l) {                                          \
            int idx_ = tid + l * 256, row_ = idx_ >> 4, sl_ = idx_ & 15;       \
            uint32_t sw_ = (uint32_t)(row_ * 256 + ((sl_ ^ (row_ & 7)) << 4)); \
            size_t vs_ = vtbase + (size_t)row_ * S_LEN + (j_) * 64 + sl_ * 4;  \
            CP16(vb_ + sw_, s_vt_hi + vs_);                                    \
            CP16(vb_ + 16384u + sw_, s_vt_lo + vs_);                           \
        }                                                                      \
    } while (0)

    const int jmax = 2 * i + 1;

    ISSUE_K(0, 0);
    ISSUE_VT(0, 0);
    CPCOMMIT();                 // G0: Q + K0 + VT0
    ISSUE_K(1, 1);
    ISSUE_VT(1, 1);
    CPCOMMIT();                 // G1: K1 + VT1

    const int i4 = lane >> 3, r8 = lane & 7;
    const int lr = lane >> 2;
    const int lc0 = 2 * (lane & 3);
    const int arow = ((i4 & 1) << 3) + r8;
    const int aslot_hi = i4 >> 1;
    const int bslot_lo = i4 & 1;
    const int pslot_lo = (lane & 3) >> 1;
    const uint32_t pword = (uint32_t)((lane & 1) << 3);
    const uint32_t pgbase_h = sb + APH + (uint32_t)rg * 8192;

    float m_prev[2][2], lsum[2][2];
#pragma unroll
    for (int mt = 0; mt < 2; ++mt)
#pragma unroll
        for (int h2 = 0; h2 < 2; ++h2) { m_prev[mt][h2] = -INFINITY; lsum[mt][h2] = 0.f; }
    float o[2][4][4];
#pragma unroll
    for (int mt = 0; mt < 2; ++mt)
#pragma unroll
        for (int nt = 0; nt < 4; ++nt)
#pragma unroll
            for (int r = 0; r < 4; ++r) o[mt][nt][r] = 0.f;

    for (int j = 0; j <= jmax; ++j) {
        CPWAIT1();              // group j resident (K(j), VT(j); G0 includes Q)
        __syncthreads();
        const uint32_t kb  = sb + AKB + (uint32_t)(j & 1) * 32768u;
        const uint32_t vtb = sb + AVB + (uint32_t)(j & 1) * 32768u;

        // ---- S = Q K^T ----
        float sacc[2][4][4];
#pragma unroll
        for (int mt = 0; mt < 2; ++mt)
#pragma unroll
            for (int nt = 0; nt < 4; ++nt)
#pragma unroll
                for (int r = 0; r < 4; ++r) sacc[mt][nt][r] = 0.f;

#pragma unroll
        for (int ks = 0; ks < 8; ++ks) {
            uint32_t khv[4][2], klv[4][2];
#pragma unroll
            for (int nt = 0; nt < 4; ++nt) {
                const int brow = cn * 32 + (nt << 3) + r8;
                const uint32_t boff = (uint32_t)(brow * 256
                    + ((((ks << 1) | bslot_lo) ^ (brow & 7)) << 4));
                LDSM_X2(khv[nt][0], khv[nt][1], kb + boff);
                LDSM_X2(klv[nt][0], klv[nt][1], kb + 16384u + boff);
            }
#pragma unroll
            for (int mt = 0; mt < 2; ++mt) {
                const int qrow = rg * 32 + mt * 16 + arow;
                const uint32_t aoff = (uint32_t)(qrow * 256
                    + ((((ks << 1) | aslot_hi) ^ (qrow & 7)) << 4));
                uint32_t ah[4], al[4];
                LDSM_X4(ah[0], ah[1], ah[2], ah[3], sb + AQH + aoff);
                LDSM_X4(al[0], al[1], al[2], al[3], sb + AQL + aoff);
#pragma unroll
                for (int nt = 0; nt < 4; ++nt) {
                    MMA_TF32(sacc[mt][nt], ah, klv[nt][0], klv[nt][1]);
                    MMA_TF32(sacc[mt][nt], al, khv[nt][0], khv[nt][1]);
                    MMA_TF32(sacc[mt][nt], ah, khv[nt][0], khv[nt][1]);
                }
            }
        }

        // ---- mask + softmax ----
        float mloc[2][2] = {{-INFINITY, -INFINITY}, {-INFINITY, -INFINITY}};
#pragma unroll
        for (int mt = 0; mt < 2; ++mt) {
            const int qr0 = i * 128 + rg * 32 + mt * 16 + lr;
#pragma unroll
            for (int nt = 0; nt < 4; ++nt) {
                const int c0 = j * 64 + cn * 32 + (nt << 3) + lc0;
                float s0 = sacc[mt][nt][0] * 0.125f, s1 = sacc[mt][nt][1] * 0.125f;
                float s2 = sacc[mt][nt][2] * 0.125f, s3 = sacc[mt][nt][3] * 0.125f;
                if (c0     > qr0)     s0 = -INFINITY;
                if (c0 + 1 > qr0)     s1 = -INFINITY;
                if (c0     > qr0 + 8) s2 = -INFINITY;
                if (c0 + 1 > qr0 + 8) s3 = -INFINITY;
                sacc[mt][nt][0] = s0; sacc[mt][nt][1] = s1;
                sacc[mt][nt][2] = s2; sacc[mt][nt][3] = s3;
                mloc[mt][0] = fmaxf(mloc[mt][0], fmaxf(s0, s1));
                mloc[mt][1] = fmaxf(mloc[mt][1], fmaxf(s2, s3));
            }
#pragma unroll
            for (int h2 = 0; h2 < 2; ++h2) {
                mloc[mt][h2] = fmaxf(mloc[mt][h2], __shfl_xor_sync(0xffffffffu, mloc[mt][h2], 1));
                mloc[mt][h2] = fmaxf(mloc[mt][h2], __shfl_xor_sync(0xffffffffu, mloc[mt][h2], 2));
            }
        }
        if ((lane & 3) == 0) {
#pragma unroll
            for (int mt = 0; mt < 2; ++mt) {
                red_m[cn * 128 + rg * 32 + mt * 16 + lr]     = mloc[mt][0];
                red_m[cn * 128 + rg * 32 + mt * 16 + lr + 8] = mloc[mt][1];
            }
        }
        BARP(rg + 1);

        float fac[2][2], m_new[2][2];
#pragma unroll
        for (int mt = 0; mt < 2; ++mt)
#pragma unroll
            for (int h2 = 0; h2 < 2; ++h2) {
                const int row = rg * 32 + mt * 16 + lr + h2 * 8;
                const float mo = red_m[(cn ^ 1) * 128 + row];
                m_new[mt][h2] = fmaxf(m_prev[mt][h2], fmaxf(mloc[mt][h2], mo));
                fac[mt][h2] = (m_prev[mt][h2] == -INFINITY)
                            ? 0.f : __expf(m_prev[mt][h2] - m_new[mt][h2]);
                m_prev[mt][h2] = m_new[mt][h2];
            }

        // P rounded to tf32; denominator accumulated from the ROUNDED values.
        float ls[2][2] = {{0.f, 0.f}, {0.f, 0.f}};
#pragma unroll
        for (int mt = 0; mt < 2; ++mt) {
            const int rA = mt * 16 + lr, rB = rA + 8;
            const uint32_t rowA_h = pgbase_h + rA * 256, rowB_h = pgbase_h + rB * 256;
#pragma unroll
            for (int nt = 0; nt < 4; ++nt) {
                const uint32_t h0 = cvt_tf32(__expf(sacc[mt][nt][0] - m_new[mt][0]));
                const uint32_t h1 = cvt_tf32(__expf(sacc[mt][nt][1] - m_new[mt][0]));
                const uint32_t h2v = cvt_tf32(__expf(sacc[mt][nt][2] - m_new[mt][1]));
                const uint32_t h3 = cvt_tf32(__expf(sacc[mt][nt][3] - m_new[mt][1]));
                ls[mt][0] += __uint_as_float(h0) + __uint_as_float(h1);
                ls[mt][1] += __uint_as_float(h2v) + __uint_as_float(h3);
                const uint32_t slot = (uint32_t)((cn << 3) | (nt << 1) | pslot_lo);
                STS64(rowA_h + ((slot ^ (rA & 7)) << 4) + pword,
                      __uint_as_float(h0), __uint_as_float(h1));
                STS64(rowB_h + ((slot ^ (rB & 7)) << 4) + pword,
                      __uint_as_float(h2v), __uint_as_float(h3));
            }
#pragma unroll
            for (int h2 = 0; h2 < 2; ++h2) {
                ls[mt][h2] += __shfl_xor_sync(0xffffffffu, ls[mt][h2], 1);
                ls[mt][h2] += __shfl_xor_sync(0xffffffffu, ls[mt][h2], 2);
            }
        }
        if ((lane & 3) == 0) {
#pragma unroll
            for (int mt = 0; mt < 2; ++mt) {
                red_l[cn * 128 + rg * 32 + mt * 16 + lr]     = ls[mt][0];
                red_l[cn * 128 + rg * 32 + mt * 16 + lr + 8] = ls[mt][1];
            }
        }
        BARP(rg + 1);   // publishes red_l AND the pair's P tiles
#pragma unroll
        for (int mt = 0; mt < 2; ++mt)
#pragma unroll
            for (int h2 = 0; h2 < 2; ++h2) {
                const int row = rg * 32 + mt * 16 + lr + h2 * 8;
                lsum[mt][h2] = lsum[mt][h2] * fac[mt][h2] + red_l[row] + red_l[128 + row];
            }

#pragma unroll
        for (int mt = 0; mt < 2; ++mt)
#pragma unroll
            for (int nt = 0; nt < 4; ++nt) {
                o[mt][nt][0] *= fac[mt][0]; o[mt][nt][1] *= fac[mt][0];
                o[mt][nt][2] *= fac[mt][1]; o[mt][nt][3] *= fac[mt][1];
            }

        // ---- O += P V (P hi-only: 2 MMAs) ----
#pragma unroll
        for (int ks = 0; ks < 8; ++ks) {
            uint32_t vhv[4][2], vlv[4][2];
#pragma unroll
            for (int nt = 0; nt < 4; ++nt) {
                const int vrow = cn * 32 + (nt << 3) + r8;
                const uint32_t voff = (uint32_t)(vrow * 256
                    + ((((ks << 1) | bslot_lo) ^ (vrow & 7)) << 4));
                LDSM_X2(vhv[nt][0], vhv[nt][1], vtb + voff);
                LDSM_X2(vlv[nt][0], vlv[nt][1], vtb + 16384u + voff);
            }
#pragma unroll
            for (int mt = 0; mt < 2; ++mt) {
                const int prow_ = mt * 16 + arow;
                const uint32_t poff = (uint32_t)(prow_ * 256
                    + ((((ks << 1) | aslot_hi) ^ (prow_ & 7)) << 4));
                uint32_t ph[4];
                LDSM_X4(ph[0], ph[1], ph[2], ph[3], pgbase_h + poff);
#pragma unroll
                for (int nt = 0; nt < 4; ++nt) {
                    MMA_TF32(o[mt][nt], ph, vlv[nt][0], vlv[nt][1]);
                    MMA_TF32(o[mt][nt], ph, vhv[nt][0], vhv[nt][1]);
                }
            }
        }

        __syncthreads();   // all reads of stage (j&1) done before refill
        if (j + 2 <= jmax) {
            ISSUE_K(j + 2, j & 1);
            ISSUE_VT(j + 2, j & 1);
        }
        CPCOMMIT();        // one group per iteration keeps wait_group counts aligned
    }

    // ---- epilogue: split O for out-projection ----
#pragma unroll
    for (int mt = 0; mt < 2; ++mt) {
        const float inv0 = 1.f / lsum[mt][0];
        const float inv1 = 1.f / lsum[mt][1];
        const size_t rowA = ((size_t)b * S_LEN + i * 128 + rg * 32 + mt * 16 + lr) * E_DIM;
        const size_t rowB = rowA + (size_t)8 * E_DIM;
#pragma unroll
        for (int nt = 0; nt < 4; ++nt) {
            const int col = h * 64 + cn * 32 + (nt << 3) + lc0;
            uint32_t h0, l0, h1, l1;
            split2(o[mt][nt][0] * inv0, h0, l0);
            split2(o[mt][nt][1] * inv0, h1, l1);
            *(uint2*)&s_o_hi[rowA + col] = make_uint2(h0, h1);
            *(uint2*)&s_o_lo[rowA + col] = make_uint2(l0, l1);
            split2(o[mt][nt][2] * inv1, h0, l0);
            split2(o[mt][nt][3] * inv1, h1, l1);
            *(uint2*)&s_o_hi[rowB + col] = make_uint2(h0, h1);
            *(uint2*)&s_o_lo[rowB + col] = make_uint2(l0, l1);
        }
    }
}

// ===================== launch =====================
extern "C" void kernel_launch(void* const* d_in, const int* in_sizes, int n_in,
                              void* d_out, int out_size)
{
    (void)in_sizes; (void)n_in; (void)out_size;
    const float* q  = (const float*)d_in[0];
    const float* k  = (const float*)d_in[1];
    const float* v  = (const float*)d_in[2];
    const float* Wq = (const float*)d_in[3];
    const float* bq = (const float*)d_in[4];
    const float* Wk = (const float*)d_in[5];
    const float* bk = (const float*)d_in[6];
    const float* Wv = (const float*)d_in[7];
    const float* bv = (const float*)d_in[8];
    const float* Wo = (const float*)d_in[9];
    const float* bo = (const float*)d_in[10];
    float* out = (float*)d_out;

    cudaFuncSetAttribute(gemm_tc_kernel, cudaFuncAttributeMaxDynamicSharedMemorySize, GEMM_SMEM);
    cudaFuncSetAttribute(attn_tc_kernel, cudaFuncAttributeMaxDynamicSharedMemorySize, ATTN_SMEM);

    // fused pre-split (2 launches)
    dim3 gridSM((unsigned)(ME / 4 / 256), 3);
    split_me_kernel<<<gridSM, 256>>>((const float4*)q, (const float4*)k, (const float4*)v);
    dim3 gridSW((unsigned)(EE / 4 / 256), 4);
    split_w_kernel<<<gridSW, 256>>>((const float4*)Wq, (const float4*)Wk,
                                    (const float4*)Wv, (const float4*)Wo);

    // Q/K/V projections (epilogues emit split attention operands)
    dim3 gridP(E_DIM / 128, M_ROWS / 128, 3);
    gemm_tc_kernel<<<gridP, 256, GEMM_SMEM>>>(bq, bk, bv, bo, out, 0);

    // causal flash attention, 128-row q-tiles (emits split O)
    dim3 gridA(S_LEN / 128, N_BATCH * N_HEADS);
    attn_tc_kernel<<<gridA, 256, ATTN_SMEM>>>();

    // output projection
    dim3 gridO(E_DIM / 128, M_ROWS / 128, 1);
    gemm_tc_kernel<<<gridO, 256, GEMM_SMEM>>>(bq, bk, bv, bo, out, 1);
}

// round 12
// speedup vs baseline: 1.1257x; 1.0451x over previous
#include <cuda_runtime.h>
#include <math.h>
#include <stdint.h>

#define E_DIM   1024
#define S_LEN   2048
#define N_BATCH 2
#define N_HEADS 16
#define H_DIM   64
#define M_ROWS  (N_BATCH * S_LEN)   // 4096
#define ME      ((size_t)M_ROWS * E_DIM)   // 4M elems
#define EE      ((size_t)E_DIM * E_DIM)    // 1M elems

// ---------- global scratch (allocation-free) ----------
__device__ uint32_t s_xq_hi[ME], s_xq_lo[ME];
__device__ uint32_t s_xk_hi[ME], s_xk_lo[ME];
__device__ uint32_t s_xv_hi[ME], s_xv_lo[ME];
__device__ uint32_t s_wq_hi[EE], s_wq_lo[EE];
__device__ uint32_t s_wk_hi[EE], s_wk_lo[EE];
__device__ uint32_t s_wv_hi[EE], s_wv_lo[EE];
__device__ uint32_t s_wo_hi[EE], s_wo_lo[EE];
__device__ uint32_t s_q_hi[ME], s_q_lo[ME];
__device__ uint32_t s_k_hi[ME], s_k_lo[ME];
__device__ uint32_t s_vt_hi[ME], s_vt_lo[ME];   // [bh][d][s]
__device__ uint32_t s_o_hi[ME], s_o_lo[ME];

// ===================== helpers =====================
__device__ __forceinline__ uint32_t smem_u32(const void* p) {
    uint32_t a;
    asm("{ .reg .u64 t; cvta.to.shared.u64 t, %1; cvt.u32.u64 %0, t; }" : "=r"(a) : "l"(p));
    return a;
}
__device__ __forceinline__ uint32_t cvt_tf32(float f) {
    uint32_t u;
    asm("cvt.rna.tf32.f32 %0, %1;" : "=r"(u) : "f"(f));
    return u;
}
__device__ __forceinline__ void split2(float f, uint32_t& hi, uint32_t& lo) {
    hi = cvt_tf32(f);
    lo = cvt_tf32(f - __uint_as_float(hi));
}
__device__ __forceinline__ void split4(float4 v, uint4& hi, uint4& lo) {
    split2(v.x, hi.x, lo.x);
    split2(v.y, hi.y, lo.y);
    split2(v.z, hi.z, lo.z);
    split2(v.w, hi.w, lo.w);
}

#define CP16(dst, src) \
    asm volatile("cp.async.cg.shared.global [%0], [%1], 16;" :: "r"(dst), "l"(src))
#define CPCOMMIT() asm volatile("cp.async.commit_group;" ::: "memory")
#define CPWAIT1()  asm volatile("cp.async.wait_group 1;" ::: "memory")
#define CPWAIT0()  asm volatile("cp.async.wait_group 0;" ::: "memory")

#define LDSM_X4(r0, r1, r2, r3, addr)                                          \
    asm volatile("ldmatrix.sync.aligned.m8n8.x4.shared.b16 {%0,%1,%2,%3}, [%4];" \
                 : "=r"(r0), "=r"(r1), "=r"(r2), "=r"(r3) : "r"(addr))
#define LDSM_X2(r0, r1, addr)                                                  \
    asm volatile("ldmatrix.sync.aligned.m8n8.x2.shared.b16 {%0,%1}, [%2];"     \
                 : "=r"(r0), "=r"(r1) : "r"(addr))

#define MMA_TF32(d, A, b0v, b1v)                                               \
    asm volatile("mma.sync.aligned.m16n8k8.row.col.f32.tf32.tf32.f32 "         \
                 "{%0,%1,%2,%3}, {%4,%5,%6,%7}, {%8,%9}, {%0,%1,%2,%3};"       \
                 : "+f"((d)[0]), "+f"((d)[1]), "+f"((d)[2]), "+f"((d)[3])      \
                 : "r"((A)[0]), "r"((A)[1]), "r"((A)[2]), "r"((A)[3]),         \
                   "r"(b0v), "r"(b1v))

#define STS64(addr, v0, v1) \
    asm volatile("st.shared.v2.f32 [%0], {%1,%2};" :: "r"(addr), "f"(v0), "f"(v1))
#define BARP(id) asm volatile("bar.sync %0, 64;" :: "r"(id) : "memory")

// ===================== fused pre-split kernels =====================
__global__ __launch_bounds__(256) void split_me_kernel(
    const float4* __restrict__ q, const float4* __restrict__ k, const float4* __restrict__ v)
{
    const int t = blockIdx.y;
    const float4* src = (t == 0) ? q : ((t == 1) ? k : v);
    uint4* hi = (t == 0) ? (uint4*)s_xq_hi : ((t == 1) ? (uint4*)s_xk_hi : (uint4*)s_xv_hi);
    uint4* lo = (t == 0) ? (uint4*)s_xq_lo : ((t == 1) ? (uint4*)s_xk_lo : (uint4*)s_xv_lo);
    int i = blockIdx.x * 256 + threadIdx.x;
    uint4 h, l;
    split4(src[i], h, l);
    hi[i] = h;
    lo[i] = l;
}
__global__ __launch_bounds__(256) void split_w_kernel(
    const float4* __restrict__ wq, const float4* __restrict__ wk,
    const float4* __restrict__ wv, const float4* __restrict__ wo)
{
    const int t = blockIdx.y;
    const float4* src = (t == 0) ? wq : ((t == 1) ? wk : ((t == 2) ? wv : wo));
    uint4* hi = (t == 0) ? (uint4*)s_wq_hi : ((t == 1) ? (uint4*)s_wk_hi
              : ((t == 2) ? (uint4*)s_wv_hi : (uint4*)s_wo_hi));
    uint4* lo = (t == 0) ? (uint4*)s_wq_lo : ((t == 1) ? (uint4*)s_wk_lo
              : ((t == 2) ? (uint4*)s_wv_lo : (uint4*)s_wo_lo));
    int i = blockIdx.x * 256 + threadIdx.x;
    uint4 h, l;
    split4(src[i], h, l);
    hi[i] = h;
    lo[i] = l;
}

// ===================== GEMM (identical to R11) =====================
#define NCHUNK   (E_DIM / 16)
#define ROWB     80
#define AHI_OFF  0u
#define ALO_OFF  10240u
#define BHI_OFF  20480u
#define BLO_OFF  30720u
#define STAGE_B  40960u
#define GEMM_SMEM (2 * 40960)

__global__ __launch_bounds__(256, 2) void gemm_tc_kernel(
    const float* __restrict__ bq, const float* __restrict__ bk,
    const float* __restrict__ bv, const float* __restrict__ bo,
    float* __restrict__ out, int is_out)
{
    extern __shared__ char smem[];
    const int z = blockIdx.z;
    const uint32_t *Xhi, *Xlo, *Whi, *Wlo;
    const float* Bv;
    int mode;
    if (is_out) { Xhi = s_o_hi;  Xlo = s_o_lo;  Whi = s_wo_hi; Wlo = s_wo_lo; Bv = bo; mode = 3; }
    else if (z == 0) { Xhi = s_xq_hi; Xlo = s_xq_lo; Whi = s_wq_hi; Wlo = s_wq_lo; Bv = bq; mode = 0; }
    else if (z == 1) { Xhi = s_xk_hi; Xlo = s_xk_lo; Whi = s_wk_hi; Wlo = s_wk_lo; Bv = bk; mode = 1; }
    else             { Xhi = s_xv_hi; Xlo = s_xv_lo; Whi = s_wv_hi; Wlo = s_wv_lo; Bv = bv; mode = 2; }

    const int tid  = threadIdx.x;
    const int lane = tid & 31;
    const int wid  = tid >> 5;
    const int wm   = wid >> 2;
    const int wn   = wid & 3;
    const int m0 = blockIdx.y * 128;
    const int n0 = blockIdx.x * 128;

    const uint32_t sb = smem_u32(smem);

    const int prow = tid >> 2;
    const int pc4  = tid & 3;
    const size_t xoff = (size_t)(m0 + prow) * E_DIM + pc4 * 4;
    const size_t woff = (size_t)(n0 + prow) * E_DIM + pc4 * 4;
    const uint32_t pd = (uint32_t)prow * ROWB + (uint32_t)pc4 * 16;

    #define GCP_CHUNK(c, st) do {                                              \
        uint32_t base_ = sb + (uint32_t)(st) * STAGE_B + pd;                   \
        size_t ko_ = (size_t)(c) * 16;                                         \
        _Pragma("unroll")                                                      \
        for (int r = 0; r < 2; ++r) {                                          \
            size_t sx_ = xoff + (size_t)r * 64 * E_DIM + ko_;                  \
            size_t sw_ = woff + (size_t)r * 64 * E_DIM + ko_;                  \
            uint32_t dd_ = base_ + (uint32_t)r * 5120;                         \
            CP16(dd_ + AHI_OFF, Xhi + sx_);                                    \
            CP16(dd_ + ALO_OFF, Xlo + sx_);                                    \
            CP16(dd_ + BHI_OFF, Whi + sw_);                                    \
            CP16(dd_ + BLO_OFF, Wlo + sw_);                                    \
        }                                                                      \
    } while (0)

    GCP_CHUNK(0, 0); CPCOMMIT();
    GCP_CHUNK(1, 1); CPCOMMIT();

    const int i4 = lane >> 3, r8 = lane & 7;
    const uint32_t a_off = (uint32_t)(wm * 64 + ((i4 & 1) << 3) + r8) * ROWB
                         + (uint32_t)((i4 >> 1) << 4);
    const uint32_t b_off = (uint32_t)(wn * 32 + r8) * ROWB
                         + (uint32_t)((i4 & 1) << 4);

    float acc[4][4][4];
#pragma unroll
    for (int mt = 0; mt < 4; ++mt)
#pragma unroll
        for (int nt = 0; nt < 4; ++nt)
#pragma unroll
            for (int r = 0; r < 4; ++r) acc[mt][nt][r] = 0.f;

    for (int c = 0; c < NCHUNK; ++c) {
        CPWAIT1();
        __syncthreads();
        const uint32_t stb = sb + (uint32_t)(c & 1) * STAGE_B;

#pragma unroll
        for (int ks = 0; ks < 2; ++ks) {
            uint32_t bhv[4][2], blv[4][2];
#pragma unroll
            for (int nt = 0; nt < 4; ++nt) {
                const uint32_t ba = stb + b_off + nt * (8 * ROWB) + ks * 32;
                LDSM_X2(bhv[nt][0], bhv[nt][1], ba + BHI_OFF);
                LDSM_X2(blv[nt][0], blv[nt][1], ba + BLO_OFF);
            }
#pragma unroll
            for (int mt = 0; mt < 4; ++mt) {
                const uint32_t aa = stb + a_off + mt * (16 * ROWB) + ks * 32;
                uint32_t ah[4], al[4];
                LDSM_X4(ah[0], ah[1], ah[2], ah[3], aa + AHI_OFF);
                LDSM_X4(al[0], al[1], al[2], al[3], aa + ALO_OFF);
#pragma unroll
                for (int nt = 0; nt < 4; ++nt) {
                    MMA_TF32(acc[mt][nt], ah, blv[nt][0], blv[nt][1]);
                    MMA_TF32(acc[mt][nt], al, bhv[nt][0], bhv[nt][1]);
                    MMA_TF32(acc[mt][nt], ah, bhv[nt][0], bhv[nt][1]);
                }
            }
        }

        __syncthreads();
        if (c + 2 < NCHUNK) GCP_CHUNK(c + 2, c & 1);
        CPCOMMIT();
    }

    if (mode == 3) {
#pragma unroll
        for (int nt = 0; nt < 4; ++nt) {
            const int col = n0 + wn * 32 + nt * 8 + 2 * (lane & 3);
            const float bx = __ldg(&Bv[col]);
            const float by = __ldg(&Bv[col + 1]);
#pragma unroll
            for (int mt = 0; mt < 4; ++mt) {
                const int r0i = m0 + wm * 64 + mt * 16 + (lane >> 2);
                *(float2*)&out[(size_t)r0i * E_DIM + col] =
                    make_float2(acc[mt][nt][0] + bx, acc[mt][nt][1] + by);
                *(float2*)&out[(size_t)(r0i + 8) * E_DIM + col] =
                    make_float2(acc[mt][nt][2] + bx, acc[mt][nt][3] + by);
            }
        }
    } else if (mode == 2) {
        const int bq2 = m0 >> 11;
#pragma unroll
        for (int nt = 0; nt < 4; ++nt) {
            const int col = n0 + wn * 32 + nt * 8 + 2 * (lane & 3);
            const int hh = col >> 6, dd = col & 63;
            const float bx = __ldg(&Bv[col]);
            const float by = __ldg(&Bv[col + 1]);
            const size_t b0i = ((size_t)(bq2 * 16 + hh) * 64 + dd) * S_LEN;
            const size_t b1i = b0i + S_LEN;
#pragma unroll
            for (int mt = 0; mt < 4; ++mt) {
                const int s = (m0 & 2047) + wm * 64 + mt * 16 + (lane >> 2);
                uint32_t h0, l0, h1, l1;
                split2(acc[mt][nt][0] + bx, h0, l0);
                split2(acc[mt][nt][1] + by, h1, l1);
                s_vt_hi[b0i + s] = h0; s_vt_lo[b0i + s] = l0;
                s_vt_hi[b1i + s] = h1; s_vt_lo[b1i + s] = l1;
                split2(acc[mt][nt][2] + bx, h0, l0);
                split2(acc[mt][nt][3] + by, h1, l1);
                s_vt_hi[b0i + s + 8] = h0; s_vt_lo[b0i + s + 8] = l0;
                s_vt_hi[b1i + s + 8] = h1; s_vt_lo[b1i + s + 8] = l1;
            }
        }
    } else {
        uint32_t* Yh = (mode == 0) ? s_q_hi : s_k_hi;
        uint32_t* Yl = (mode == 0) ? s_q_lo : s_k_lo;
#pragma unroll
        for (int nt = 0; nt < 4; ++nt) {
            const int col = n0 + wn * 32 + nt * 8 + 2 * (lane & 3);
            const float bx = __ldg(&Bv[col]);
            const float by = __ldg(&Bv[col + 1]);
#pragma unroll
            for (int mt = 0; mt < 4; ++mt) {
                const int r0i = m0 + wm * 64 + mt * 16 + (lane >> 2);
                uint32_t h0, l0, h1, l1;
                split2(acc[mt][nt][0] + bx, h0, l0);
                split2(acc[mt][nt][1] + by, h1, l1);
                *(uint2*)&Yh[(size_t)r0i * E_DIM + col] = make_uint2(h0, h1);
                *(uint2*)&Yl[(size_t)r0i * E_DIM + col] = make_uint2(l0, l1);
                split2(acc[mt][nt][2] + bx, h0, l0);
                split2(acc[mt][nt][3] + by, h1, l1);
                *(uint2*)&Yh[(size_t)(r0i + 8) * E_DIM + col] = make_uint2(h0, h1);
                *(uint2*)&Yl[(size_t)(r0i + 8) * E_DIM + col] = make_uint2(l0, l1);
            }
        }
    }
}

// ===================== Causal flash attention: 128-row q-tiles =====================
// 8 warps: rg=w&3 (32 rows), cn=w>>2 (32 of 64 cols). K and VT both 2-stage.
// S = Qhi*(Khi+Klo): Q_lo term dropped (error ~2.4e-4 on logits, cancelled by the
// rounded-P denominator). P stored hi-only. B-side smem loads use LDSM_X4 packing
// (two n-tiles x two k-slots per instruction).
// smem: Qhi 32K | K 2st 64K | VT 2st 64K | Phi 32K | red 2K = 198656
#define AQH   0u
#define AKB   32768u      // + stage*32768; lo at +16384
#define AVB   98304u      // + stage*32768; lo at +16384
#define APH   163840u     // + rg*8192
#define ARED  196608u
#define ATTN_SMEM 198656

__global__ __launch_bounds__(256) void attn_tc_kernel(void)
{
    extern __shared__ char smem[];
    const uint32_t sb = smem_u32(smem);
    float* red_m = (float*)(smem + ARED);          // [2][128]
    float* red_l = (float*)(smem + ARED + 1024);   // [2][128]

    const int tid = threadIdx.x, lane = tid & 31, w = tid >> 5;
    const int rg = w & 3, cn = w >> 2;
    const int i = (int)gridDim.x - 1 - (int)blockIdx.x;   // heavy tiles first
    const int bh = blockIdx.y;
    const int b = bh >> 4, h = bh & 15;

    const size_t qbase  = ((size_t)b * S_LEN + i * 128) * E_DIM + h * 64;
    const size_t kbase  = (size_t)b * S_LEN * E_DIM + h * 64;
    const size_t vtbase = (size_t)bh * 64 * S_LEN;

    // Q: 128 rows x 16 slots, hi only (group 0)
#pragma unroll
    for (int l = 0; l < 8; ++l) {
        int idx = tid + l * 256, row = idx >> 4, sl = idx & 15;
        uint32_t sw = (uint32_t)(row * 256 + ((sl ^ (row & 7)) << 4));
        CP16(sb + AQH + sw, s_q_hi + qbase + (size_t)row * E_DIM + sl * 4);
    }

    #define ISSUE_K(j_, st_) do {                                              \
        uint32_t kb_ = sb + AKB + (uint32_t)(st_) * 32768u;                    \
        _Pragma("unroll")                                                      \
        for (int l = 0; l < 4; ++l) {                                          \
            int idx_ = tid + l * 256, row_ = idx_ >> 4, sl_ = idx_ & 15;       \
            uint32_t sw_ = (uint32_t)(row_ * 256 + ((sl_ ^ (row_ & 7)) << 4)); \
            size_t ks_ = kbase + (size_t)((j_) * 64 + row_) * E_DIM + sl_ * 4; \
            CP16(kb_ + sw_, s_k_hi + ks_);                                     \
            CP16(kb_ + 16384u + sw_, s_k_lo + ks_);                            \
        }                                                                      \
    } while (0)

    #define ISSUE_VT(j_, st_) do {                                             \
        uint32_t vb_ = sb + AVB + (uint32_t)(st_) * 32768u;                    \
        _Pragma("unroll")                                                      \
        for (int l = 0; l < 4; ++l) {                                          \
            int idx_ = tid + l * 256, row_ = idx_ >> 4, sl_ = idx_ & 15;       \
            uint32_t sw_ = (uint32_t)(row_ * 256 + ((sl_ ^ (row_ & 7)) << 4)); \
            size_t vs_ = vtbase + (size_t)row_ * S_LEN + (j_) * 64 + sl_ * 4;  \
            CP16(vb_ + sw_, s_vt_hi + vs_);                                    \
            CP16(vb_ + 16384u + sw_, s_vt_lo + vs_);                           \
        }                                                                      \
    } while (0)

    const int jmax = 2 * i + 1;

    ISSUE_K(0, 0);
    ISSUE_VT(0, 0);
    CPCOMMIT();                 // G0: Q + K0 + VT0
    ISSUE_K(1, 1);
    ISSUE_VT(1, 1);
    CPCOMMIT();                 // G1: K1 + VT1

    const int i4 = lane >> 3, r8 = lane & 7;
    const int lr = lane >> 2;
    const int lc0 = 2 * (lane & 3);
    const int arow = ((i4 & 1) << 3) + r8;
    const int aslot_hi = i4 >> 1;
    const int pslot_lo = (lane & 3) >> 1;
    const uint32_t pword = (uint32_t)((lane & 1) << 3);
    const uint32_t pgbase_h = sb + APH + (uint32_t)rg * 8192;
    // B-side x4 lane mapping: matrix m (lane group) -> row offset (m>>1)*8, slot bit m&1
    const int brow_off = ((i4 >> 1) << 3) + r8;
    const int bslot_lo = i4 & 1;

    float m_prev[2][2], lsum[2][2];
#pragma unroll
    for (int mt = 0; mt < 2; ++mt)
#pragma unroll
        for (int h2 = 0; h2 < 2; ++h2) { m_prev[mt][h2] = -INFINITY; lsum[mt][h2] = 0.f; }
    float o[2][4][4];
#pragma unroll
    for (int mt = 0; mt < 2; ++mt)
#pragma unroll
        for (int nt = 0; nt < 4; ++nt)
#pragma unroll
            for (int r = 0; r < 4; ++r) o[mt][nt][r] = 0.f;

    for (int j = 0; j <= jmax; ++j) {
        CPWAIT1();              // group j resident
        __syncthreads();
        const uint32_t kb  = sb + AKB + (uint32_t)(j & 1) * 32768u;
        const uint32_t vtb = sb + AVB + (uint32_t)(j & 1) * 32768u;

        // ---- S = Qhi * (Khi + Klo) ----
        float sacc[2][4][4];
#pragma unroll
        for (int mt = 0; mt < 2; ++mt)
#pragma unroll
            for (int nt = 0; nt < 4; ++nt)
#pragma unroll
                for (int r = 0; r < 4; ++r) sacc[mt][nt][r] = 0.f;

#pragma unroll
        for (int ks = 0; ks < 8; ++ks) {
            uint32_t khv[4][2], klv[4][2];
#pragma unroll
            for (int nt2 = 0; nt2 < 2; ++nt2) {
                const int brow = cn * 32 + nt2 * 16 + brow_off;
                const uint32_t boff = (uint32_t)(brow * 256
                    + ((((ks << 1) | bslot_lo) ^ (brow & 7)) << 4));
                LDSM_X4(khv[nt2 * 2][0], khv[nt2 * 2][1],
                        khv[nt2 * 2 + 1][0], khv[nt2 * 2 + 1][1], kb + boff);
                LDSM_X4(klv[nt2 * 2][0], klv[nt2 * 2][1],
                        klv[nt2 * 2 + 1][0], klv[nt2 * 2 + 1][1], kb + 16384u + boff);
            }
#pragma unroll
            for (int mt = 0; mt < 2; ++mt) {
                const int qrow = rg * 32 + mt * 16 + arow;
                const uint32_t aoff = (uint32_t)(qrow * 256
                    + ((((ks << 1) | aslot_hi) ^ (qrow & 7)) << 4));
                uint32_t ah[4];
                LDSM_X4(ah[0], ah[1], ah[2], ah[3], sb + AQH + aoff);
#pragma unroll
                for (int nt = 0; nt < 4; ++nt) {
                    MMA_TF32(sacc[mt][nt], ah, klv[nt][0], klv[nt][1]);
                    MMA_TF32(sacc[mt][nt], ah, khv[nt][0], khv[nt][1]);
                }
            }
        }

        // ---- mask + softmax ----
        float mloc[2][2] = {{-INFINITY, -INFINITY}, {-INFINITY, -INFINITY}};
#pragma unroll
        for (int mt = 0; mt < 2; ++mt) {
            const int qr0 = i * 128 + rg * 32 + mt * 16 + lr;
#pragma unroll
            for (int nt = 0; nt < 4; ++nt) {
                const int c0 = j * 64 + cn * 32 + (nt << 3) + lc0;
                float s0 = sacc[mt][nt][0] * 0.125f, s1 = sacc[mt][nt][1] * 0.125f;
                float s2 = sacc[mt][nt][2] * 0.125f, s3 = sacc[mt][nt][3] * 0.125f;
                if (c0     > qr0)     s0 = -INFINITY;
                if (c0 + 1 > qr0)     s1 = -INFINITY;
                if (c0     > qr0 + 8) s2 = -INFINITY;
                if (c0 + 1 > qr0 + 8) s3 = -INFINITY;
                sacc[mt][nt][0] = s0; sacc[mt][nt][1] = s1;
                sacc[mt][nt][2] = s2; sacc[mt][nt][3] = s3;
                mloc[mt][0] = fmaxf(mloc[mt][0], fmaxf(s0, s1));
                mloc[mt][1] = fmaxf(mloc[mt][1], fmaxf(s2, s3));
            }
#pragma unroll
            for (int h2 = 0; h2 < 2; ++h2) {
                mloc[mt][h2] = fmaxf(mloc[mt][h2], __shfl_xor_sync(0xffffffffu, mloc[mt][h2], 1));
                mloc[mt][h2] = fmaxf(mloc[mt][h2], __shfl_xor_sync(0xffffffffu, mloc[mt][h2], 2));
            }
        }
        if ((lane & 3) == 0) {
#pragma unroll
            for (int mt = 0; mt < 2; ++mt) {
                red_m[cn * 128 + rg * 32 + mt * 16 + lr]     = mloc[mt][0];
                red_m[cn * 128 + rg * 32 + mt * 16 + lr + 8] = mloc[mt][1];
            }
        }
        BARP(rg + 1);

        float fac[2][2], m_new[2][2];
#pragma unroll
        for (int mt = 0; mt < 2; ++mt)
#pragma unroll
            for (int h2 = 0; h2 < 2; ++h2) {
                const int row = rg * 32 + mt * 16 + lr + h2 * 8;
                const float mo = red_m[(cn ^ 1) * 128 + row];
                m_new[mt][h2] = fmaxf(m_prev[mt][h2], fmaxf(mloc[mt][h2], mo));
                fac[mt][h2] = (m_prev[mt][h2] == -INFINITY)
                            ? 0.f : __expf(m_prev[mt][h2] - m_new[mt][h2]);
                m_prev[mt][h2] = m_new[mt][h2];
            }

        // P rounded to tf32; denominator accumulated from the ROUNDED values.
        float ls[2][2] = {{0.f, 0.f}, {0.f, 0.f}};
#pragma unroll
        for (int mt = 0; mt < 2; ++mt) {
            const int rA = mt * 16 + lr, rB = rA + 8;
            const uint32_t rowA_h = pgbase_h + rA * 256, rowB_h = pgbase_h + rB * 256;
#pragma unroll
            for (int nt = 0; nt < 4; ++nt) {
                const uint32_t h0 = cvt_tf32(__expf(sacc[mt][nt][0] - m_new[mt][0]));
                const uint32_t h1 = cvt_tf32(__expf(sacc[mt][nt][1] - m_new[mt][0]));
                const uint32_t h2v = cvt_tf32(__expf(sacc[mt][nt][2] - m_new[mt][1]));
                const uint32_t h3 = cvt_tf32(__expf(sacc[mt][nt][3] - m_new[mt][1]));
                ls[mt][0] += __uint_as_float(h0) + __uint_as_float(h1);
                ls[mt][1] += __uint_as_float(h2v) + __uint_as_float(h3);
                const uint32_t slot = (uint32_t)((cn << 3) | (nt << 1) | pslot_lo);
                STS64(rowA_h + ((slot ^ (rA & 7)) << 4) + pword,
                      __uint_as_float(h0), __uint_as_float(h1));
                STS64(rowB_h + ((slot ^ (rB & 7)) << 4) + pword,
                      __uint_as_float(h2v), __uint_as_float(h3));
            }
#pragma unroll
            for (int h2 = 0; h2 < 2; ++h2) {
                ls[mt][h2] += __shfl_xor_sync(0xffffffffu, ls[mt][h2], 1);
                ls[mt][h2] += __shfl_xor_sync(0xffffffffu, ls[mt][h2], 2);
            }
        }
        if ((lane & 3) == 0) {
#pragma unroll
            for (int mt = 0; mt < 2; ++mt) {
                red_l[cn * 128 + rg * 32 + mt * 16 + lr]     = ls[mt][0];
                red_l[cn * 128 + rg * 32 + mt * 16 + lr + 8] = ls[mt][1];
            }
        }
        BARP(rg + 1);   // publishes red_l AND the pair's P tiles
#pragma unroll
        for (int mt = 0; mt < 2; ++mt)
#pragma unroll
            for (int h2 = 0; h2 < 2; ++h2) {
                const int row = rg * 32 + mt * 16 + lr + h2 * 8;
                lsum[mt][h2] = lsum[mt][h2] * fac[mt][h2] + red_l[row] + red_l[128 + row];
            }

#pragma unroll
        for (int mt = 0; mt < 2; ++mt)
#pragma unroll
            for (int nt = 0; nt < 4; ++nt) {
                o[mt][nt][0] *= fac[mt][0]; o[mt][nt][1] *= fac[mt][0];
                o[mt][nt][2] *= fac[mt][1]; o[mt][nt][3] *= fac[mt][1];
            }

        // ---- O += P V (P hi-only; V hi+lo) ----
#pragma unroll
        for (int ks = 0; ks < 8; ++ks) {
            uint32_t vhv[4][2], vlv[4][2];
#pragma unroll
            for (int nt2 = 0; nt2 < 2; ++nt2) {
                const int vrow = cn * 32 + nt2 * 16 + brow_off;
                const uint32_t voff = (uint32_t)(vrow * 256
                    + ((((ks << 1) | bslot_lo) ^ (vrow & 7)) << 4));
                LDSM_X4(vhv[nt2 * 2][0], vhv[nt2 * 2][1],
                        vhv[nt2 * 2 + 1][0], vhv[nt2 * 2 + 1][1], vtb + voff);
                LDSM_X4(vlv[nt2 * 2][0], vlv[nt2 * 2][1],
                        vlv[nt2 * 2 + 1][0], vlv[nt2 * 2 + 1][1], vtb + 16384u + voff);
            }
#pragma unroll
            for (int mt = 0; mt < 2; ++mt) {
                const int prow_ = mt * 16 + arow;
                const uint32_t poff = (uint32_t)(prow_ * 256
                    + ((((ks << 1) | aslot_hi) ^ (prow_ & 7)) << 4));
                uint32_t ph[4];
                LDSM_X4(ph[0], ph[1], ph[2], ph[3], pgbase_h + poff);
#pragma unroll
                for (int nt = 0; nt < 4; ++nt) {
                    MMA_TF32(o[mt][nt], ph, vlv[nt][0], vlv[nt][1]);
                    MMA_TF32(o[mt][nt], ph, vhv[nt][0], vhv[nt][1]);
                }
            }
        }

        __syncthreads();   // all reads of stage (j&1) done before refill
        if (j + 2 <= jmax) {
            ISSUE_K(j + 2, j & 1);
            ISSUE_VT(j + 2, j & 1);
        }
        CPCOMMIT();        // one group per iteration keeps wait_group counts aligned
    }

    // ---- epilogue: split O for out-projection ----
#pragma unroll
    for (int mt = 0; mt < 2; ++mt) {
        const float inv0 = 1.f / lsum[mt][0];
        const float inv1 = 1.f / lsum[mt][1];
        const size_t rowA = ((size_t)b * S_LEN + i * 128 + rg * 32 + mt * 16 + lr) * E_DIM;
        const size_t rowB = rowA + (size_t)8 * E_DIM;
#pragma unroll
        for (int nt = 0; nt < 4; ++nt) {
            const int col = h * 64 + cn * 32 + (nt << 3) + lc0;
            uint32_t h0, l0, h1, l1;
            split2(o[mt][nt][0] * inv0, h0, l0);
            split2(o[mt][nt][1] * inv0, h1, l1);
            *(uint2*)&s_o_hi[rowA + col] = make_uint2(h0, h1);
            *(uint2*)&s_o_lo[rowA + col] = make_uint2(l0, l1);
            split2(o[mt][nt][2] * inv1, h0, l0);
            split2(o[mt][nt][3] * inv1, h1, l1);
            *(uint2*)&s_o_hi[rowB + col] = make_uint2(h0, h1);
            *(uint2*)&s_o_lo[rowB + col] = make_uint2(l0, l1);
        }
    }
}

// ===================== launch =====================
extern "C" void kernel_launch(void* const* d_in, const int* in_sizes, int n_in,
                              void* d_out, int out_size)
{
    (void)in_sizes; (void)n_in; (void)out_size;
    const float* q  = (const float*)d_in[0];
    const float* k  = (const float*)d_in[1];
    const float* v  = (const float*)d_in[2];
    const float* Wq = (const float*)d_in[3];
    const float* bq = (const float*)d_in[4];
    const float* Wk = (const float*)d_in[5];
    const float* bk = (const float*)d_in[6];
    const float* Wv = (const float*)d_in[7];
    const float* bv = (const float*)d_in[8];
    const float* Wo = (const float*)d_in[9];
    const float* bo = (const float*)d_in[10];
    float* out = (float*)d_out;

    cudaFuncSetAttribute(gemm_tc_kernel, cudaFuncAttributeMaxDynamicSharedMemorySize, GEMM_SMEM);
    cudaFuncSetAttribute(attn_tc_kernel, cudaFuncAttributeMaxDynamicSharedMemorySize, ATTN_SMEM);

    // fused pre-split (2 launches)
    dim3 gridSM((unsigned)(ME / 4 / 256), 3);
    split_me_kernel<<<gridSM, 256>>>((const float4*)q, (const float4*)k, (const float4*)v);
    dim3 gridSW((unsigned)(EE / 4 / 256), 4);
    split_w_kernel<<<gridSW, 256>>>((const float4*)Wq, (const float4*)Wk,
                                    (const float4*)Wv, (const float4*)Wo);

    // Q/K/V projections (epilogues emit split attention operands)
    dim3 gridP(E_DIM / 128, M_ROWS / 128, 3);
    gemm_tc_kernel<<<gridP, 256, GEMM_SMEM>>>(bq, bk, bv, bo, out, 0);

    // causal flash attention, 128-row q-tiles (emits split O)
    dim3 gridA(S_LEN / 128, N_BATCH * N_HEADS);
    attn_tc_kernel<<<gridA, 256, ATTN_SMEM>>>();

    // output projection
    dim3 gridO(E_DIM / 128, M_ROWS / 128, 1);
    gemm_tc_kernel<<<gridO, 256, GEMM_SMEM>>>(bq, bk, bv, bo, out, 1);
}

// round 13
// speedup vs baseline: 1.5110x; 1.3423x over previous
#include <cuda_runtime.h>
#include <math.h>
#include <stdint.h>

#define E_DIM   1024
#define S_LEN   2048
#define N_BATCH 2
#define N_HEADS 16
#define H_DIM   64
#define M_ROWS  (N_BATCH * S_LEN)   // 4096
#define ME      ((size_t)M_ROWS * E_DIM)   // 4M elems
#define EE      ((size_t)E_DIM * E_DIM)    // 1M elems

// ---------- global scratch (allocation-free) ----------
// A-side operands are hi-only (2-MMA GEMM); B-side weights keep hi+lo.
__device__ uint32_t s_xq_hi[ME];
__device__ uint32_t s_xk_hi[ME];
__device__ uint32_t s_xv_hi[ME];
__device__ uint32_t s_wq_hi[EE], s_wq_lo[EE];
__device__ uint32_t s_wk_hi[EE], s_wk_lo[EE];
__device__ uint32_t s_wv_hi[EE], s_wv_lo[EE];
__device__ uint32_t s_wo_hi[EE], s_wo_lo[EE];
__device__ uint32_t s_q_hi[ME];
__device__ uint32_t s_k_hi[ME], s_k_lo[ME];
__device__ uint32_t s_vt_hi[ME], s_vt_lo[ME];   // [bh][d][s]
__device__ uint32_t s_o_hi[ME];

// ===================== helpers =====================
__device__ __forceinline__ uint32_t smem_u32(const void* p) {
    uint32_t a;
    asm("{ .reg .u64 t; cvta.to.shared.u64 t, %1; cvt.u32.u64 %0, t; }" : "=r"(a) : "l"(p));
    return a;
}
__device__ __forceinline__ uint32_t cvt_tf32(float f) {
    uint32_t u;
    asm("cvt.rna.tf32.f32 %0, %1;" : "=r"(u) : "f"(f));
    return u;
}
__device__ __forceinline__ void split2(float f, uint32_t& hi, uint32_t& lo) {
    hi = cvt_tf32(f);
    lo = cvt_tf32(f - __uint_as_float(hi));
}
__device__ __forceinline__ void split4(float4 v, uint4& hi, uint4& lo) {
    split2(v.x, hi.x, lo.x);
    split2(v.y, hi.y, lo.y);
    split2(v.z, hi.z, lo.z);
    split2(v.w, hi.w, lo.w);
}
__device__ __forceinline__ uint4 hi4(float4 v) {
    uint4 h;
    h.x = cvt_tf32(v.x); h.y = cvt_tf32(v.y);
    h.z = cvt_tf32(v.z); h.w = cvt_tf32(v.w);
    return h;
}

#define CP16(dst, src) \
    asm volatile("cp.async.cg.shared.global [%0], [%1], 16;" :: "r"(dst), "l"(src))
#define CPCOMMIT() asm volatile("cp.async.commit_group;" ::: "memory")
#define CPWAIT1()  asm volatile("cp.async.wait_group 1;" ::: "memory")

#define LDSM_X4(r0, r1, r2, r3, addr)                                          \
    asm volatile("ldmatrix.sync.aligned.m8n8.x4.shared.b16 {%0,%1,%2,%3}, [%4];" \
                 : "=r"(r0), "=r"(r1), "=r"(r2), "=r"(r3) : "r"(addr))
#define LDSM_X2(r0, r1, addr)                                                  \
    asm volatile("ldmatrix.sync.aligned.m8n8.x2.shared.b16 {%0,%1}, [%2];"     \
                 : "=r"(r0), "=r"(r1) : "r"(addr))

#define MMA_TF32(d, A, b0v, b1v)                                               \
    asm volatile("mma.sync.aligned.m16n8k8.row.col.f32.tf32.tf32.f32 "         \
                 "{%0,%1,%2,%3}, {%4,%5,%6,%7}, {%8,%9}, {%0,%1,%2,%3};"       \
                 : "+f"((d)[0]), "+f"((d)[1]), "+f"((d)[2]), "+f"((d)[3])      \
                 : "r"((A)[0]), "r"((A)[1]), "r"((A)[2]), "r"((A)[3]),         \
                   "r"(b0v), "r"(b1v))

#define STS64(addr, v0, v1) \
    asm volatile("st.shared.v2.f32 [%0], {%1,%2};" :: "r"(addr), "f"(v0), "f"(v1))
#define BARP(id) asm volatile("bar.sync %0, 64;" :: "r"(id) : "memory")

// ===================== fused pre-split kernels =====================
__global__ __launch_bounds__(256) void split_me_kernel(
    const float4* __restrict__ q, const float4* __restrict__ k, const float4* __restrict__ v)
{
    const int t = blockIdx.y;
    const float4* src = (t == 0) ? q : ((t == 1) ? k : v);
    uint4* hi = (t == 0) ? (uint4*)s_xq_hi : ((t == 1) ? (uint4*)s_xk_hi : (uint4*)s_xv_hi);
    int i = blockIdx.x * 256 + threadIdx.x;
    hi[i] = hi4(src[i]);
}
__global__ __launch_bounds__(256) void split_w_kernel(
    const float4* __restrict__ wq, const float4* __restrict__ wk,
    const float4* __restrict__ wv, const float4* __restrict__ wo)
{
    const int t = blockIdx.y;
    const float4* src = (t == 0) ? wq : ((t == 1) ? wk : ((t == 2) ? wv : wo));
    uint4* hi = (t == 0) ? (uint4*)s_wq_hi : ((t == 1) ? (uint4*)s_wk_hi
              : ((t == 2) ? (uint4*)s_wv_hi : (uint4*)s_wo_hi));
    uint4* lo = (t == 0) ? (uint4*)s_wq_lo : ((t == 1) ? (uint4*)s_wk_lo
              : ((t == 2) ? (uint4*)s_wv_lo : (uint4*)s_wo_lo));
    int i = blockIdx.x * 256 + threadIdx.x;
    uint4 h, l;
    split4(src[i], h, l);
    hi[i] = h;
    lo[i] = l;
}

// ===================== GEMM: Y = Xhi @ (Whi+Wlo)^T + b (2-MMA) =====================
// CTA 128x128, 8 warps (2m x 4n), K chunk 16, 2-stage cp.async.
// A-side hi only. smem stage: Ahi 10240 | Bhi 10240 | Blo 10240.
#define NCHUNK   (E_DIM / 16)
#define ROWB     80
#define AHI_OFF  0u
#define BHI_OFF  10240u
#define BLO_OFF  20480u
#define STAGE_B  30720u
#define GEMM_SMEM (2 * 30720)

__global__ __launch_bounds__(256, 2) void gemm_tc_kernel(
    const float* __restrict__ bq, const float* __restrict__ bk,
    const float* __restrict__ bv, const float* __restrict__ bo,
    float* __restrict__ out, int is_out)
{
    extern __shared__ char smem[];
    const int z = blockIdx.z;
    const uint32_t *Xhi, *Whi, *Wlo;
    const float* Bv;
    int mode;
    if (is_out) { Xhi = s_o_hi;  Whi = s_wo_hi; Wlo = s_wo_lo; Bv = bo; mode = 3; }
    else if (z == 0) { Xhi = s_xq_hi; Whi = s_wq_hi; Wlo = s_wq_lo; Bv = bq; mode = 0; }
    else if (z == 1) { Xhi = s_xk_hi; Whi = s_wk_hi; Wlo = s_wk_lo; Bv = bk; mode = 1; }
    else             { Xhi = s_xv_hi; Whi = s_wv_hi; Wlo = s_wv_lo; Bv = bv; mode = 2; }

    const int tid  = threadIdx.x;
    const int lane = tid & 31;
    const int wid  = tid >> 5;
    const int wm   = wid >> 2;
    const int wn   = wid & 3;
    const int m0 = blockIdx.y * 128;
    const int n0 = blockIdx.x * 128;

    const uint32_t sb = smem_u32(smem);

    const int prow = tid >> 2;
    const int pc4  = tid & 3;
    const size_t xoff = (size_t)(m0 + prow) * E_DIM + pc4 * 4;
    const size_t woff = (size_t)(n0 + prow) * E_DIM + pc4 * 4;
    const uint32_t pd = (uint32_t)prow * ROWB + (uint32_t)pc4 * 16;

    #define GCP_CHUNK(c, st) do {                                              \
        uint32_t base_ = sb + (uint32_t)(st) * STAGE_B + pd;                   \
        size_t ko_ = (size_t)(c) * 16;                                         \
        _Pragma("unroll")                                                      \
        for (int r = 0; r < 2; ++r) {                                          \
            size_t sx_ = xoff + (size_t)r * 64 * E_DIM + ko_;                  \
            size_t sw_ = woff + (size_t)r * 64 * E_DIM + ko_;                  \
            uint32_t dd_ = base_ + (uint32_t)r * 5120;                         \
            CP16(dd_ + AHI_OFF, Xhi + sx_);                                    \
            CP16(dd_ + BHI_OFF, Whi + sw_);                                    \
            CP16(dd_ + BLO_OFF, Wlo + sw_);                                    \
        }                                                                      \
    } while (0)

    GCP_CHUNK(0, 0); CPCOMMIT();
    GCP_CHUNK(1, 1); CPCOMMIT();

    const int i4 = lane >> 3, r8 = lane & 7;
    const uint32_t a_off = (uint32_t)(wm * 64 + ((i4 & 1) << 3) + r8) * ROWB
                         + (uint32_t)((i4 >> 1) << 4);
    const uint32_t b_off = (uint32_t)(wn * 32 + r8) * ROWB
                         + (uint32_t)((i4 & 1) << 4);

    float acc[4][4][4];
#pragma unroll
    for (int mt = 0; mt < 4; ++mt)
#pragma unroll
        for (int nt = 0; nt < 4; ++nt)
#pragma unroll
            for (int r = 0; r < 4; ++r) acc[mt][nt][r] = 0.f;

    for (int c = 0; c < NCHUNK; ++c) {
        CPWAIT1();
        __syncthreads();
        const uint32_t stb = sb + (uint32_t)(c & 1) * STAGE_B;

#pragma unroll
        for (int ks = 0; ks < 2; ++ks) {
            uint32_t bhv[4][2], blv[4][2];
#pragma unroll
            for (int nt = 0; nt < 4; ++nt) {
                const uint32_t ba = stb + b_off + nt * (8 * ROWB) + ks * 32;
                LDSM_X2(bhv[nt][0], bhv[nt][1], ba + BHI_OFF);
                LDSM_X2(blv[nt][0], blv[nt][1], ba + BLO_OFF);
            }
#pragma unroll
            for (int mt = 0; mt < 4; ++mt) {
                const uint32_t aa = stb + a_off + mt * (16 * ROWB) + ks * 32;
                uint32_t ah[4];
                LDSM_X4(ah[0], ah[1], ah[2], ah[3], aa + AHI_OFF);
#pragma unroll
                for (int nt = 0; nt < 4; ++nt) {
                    MMA_TF32(acc[mt][nt], ah, blv[nt][0], blv[nt][1]);
                    MMA_TF32(acc[mt][nt], ah, bhv[nt][0], bhv[nt][1]);
                }
            }
        }

        __syncthreads();
        if (c + 2 < NCHUNK) GCP_CHUNK(c + 2, c & 1);
        CPCOMMIT();
    }

    if (mode == 3) {
#pragma unroll
        for (int nt = 0; nt < 4; ++nt) {
            const int col = n0 + wn * 32 + nt * 8 + 2 * (lane & 3);
            const float bx = __ldg(&Bv[col]);
            const float by = __ldg(&Bv[col + 1]);
#pragma unroll
            for (int mt = 0; mt < 4; ++mt) {
                const int r0i = m0 + wm * 64 + mt * 16 + (lane >> 2);
                *(float2*)&out[(size_t)r0i * E_DIM + col] =
                    make_float2(acc[mt][nt][0] + bx, acc[mt][nt][1] + by);
                *(float2*)&out[(size_t)(r0i + 8) * E_DIM + col] =
                    make_float2(acc[mt][nt][2] + bx, acc[mt][nt][3] + by);
            }
        }
    } else if (mode == 2) {
        // V^T split epilogue (attention needs V hi+lo as B-side)
        const int bq2 = m0 >> 11;
#pragma unroll
        for (int nt = 0; nt < 4; ++nt) {
            const int col = n0 + wn * 32 + nt * 8 + 2 * (lane & 3);
            const int hh = col >> 6, dd = col & 63;
            const float bx = __ldg(&Bv[col]);
            const float by = __ldg(&Bv[col + 1]);
            const size_t b0i = ((size_t)(bq2 * 16 + hh) * 64 + dd) * S_LEN;
            const size_t b1i = b0i + S_LEN;
#pragma unroll
            for (int mt = 0; mt < 4; ++mt) {
                const int s = (m0 & 2047) + wm * 64 + mt * 16 + (lane >> 2);
                uint32_t h0, l0, h1, l1;
                split2(acc[mt][nt][0] + bx, h0, l0);
                split2(acc[mt][nt][1] + by, h1, l1);
                s_vt_hi[b0i + s] = h0; s_vt_lo[b0i + s] = l0;
                s_vt_hi[b1i + s] = h1; s_vt_lo[b1i + s] = l1;
                split2(acc[mt][nt][2] + bx, h0, l0);
                split2(acc[mt][nt][3] + by, h1, l1);
                s_vt_hi[b0i + s + 8] = h0; s_vt_lo[b0i + s + 8] = l0;
                s_vt_hi[b1i + s + 8] = h1; s_vt_lo[b1i + s + 8] = l1;
            }
        }
    } else if (mode == 1) {
        // K epilogue: hi + lo (attention S-phase B-side)
#pragma unroll
        for (int nt = 0; nt < 4; ++nt) {
            const int col = n0 + wn * 32 + nt * 8 + 2 * (lane & 3);
            const float bx = __ldg(&Bv[col]);
            const float by = __ldg(&Bv[col + 1]);
#pragma unroll
            for (int mt = 0; mt < 4; ++mt) {
                const int r0i = m0 + wm * 64 + mt * 16 + (lane >> 2);
                uint32_t h0, l0, h1, l1;
                split2(acc[mt][nt][0] + bx, h0, l0);
                split2(acc[mt][nt][1] + by, h1, l1);
                *(uint2*)&s_k_hi[(size_t)r0i * E_DIM + col] = make_uint2(h0, h1);
                *(uint2*)&s_k_lo[(size_t)r0i * E_DIM + col] = make_uint2(l0, l1);
                split2(acc[mt][nt][2] + bx, h0, l0);
                split2(acc[mt][nt][3] + by, h1, l1);
                *(uint2*)&s_k_hi[(size_t)(r0i + 8) * E_DIM + col] = make_uint2(h0, h1);
                *(uint2*)&s_k_lo[(size_t)(r0i + 8) * E_DIM + col] = make_uint2(l0, l1);
            }
        }
    } else {
        // Q epilogue: hi only
#pragma unroll
        for (int nt = 0; nt < 4; ++nt) {
            const int col = n0 + wn * 32 + nt * 8 + 2 * (lane & 3);
            const float bx = __ldg(&Bv[col]);
            const float by = __ldg(&Bv[col + 1]);
#pragma unroll
            for (int mt = 0; mt < 4; ++mt) {
                const int r0i = m0 + wm * 64 + mt * 16 + (lane >> 2);
                *(uint2*)&s_q_hi[(size_t)r0i * E_DIM + col] =
                    make_uint2(cvt_tf32(acc[mt][nt][0] + bx), cvt_tf32(acc[mt][nt][1] + by));
                *(uint2*)&s_q_hi[(size_t)(r0i + 8) * E_DIM + col] =
                    make_uint2(cvt_tf32(acc[mt][nt][2] + bx), cvt_tf32(acc[mt][nt][3] + by));
            }
        }
    }
}

// ===================== Causal flash attention (hot loop identical to R12) =====================
#define AQH   0u
#define AKB   32768u      // + stage*32768; lo at +16384
#define AVB   98304u      // + stage*32768; lo at +16384
#define APH   163840u     // + rg*8192
#define ARED  196608u
#define ATTN_SMEM 198656

__global__ __launch_bounds__(256) void attn_tc_kernel(void)
{
    extern __shared__ char smem[];
    const uint32_t sb = smem_u32(smem);
    float* red_m = (float*)(smem + ARED);          // [2][128]
    float* red_l = (float*)(smem + ARED + 1024);   // [2][128]

    const int tid = threadIdx.x, lane = tid & 31, w = tid >> 5;
    const int rg = w & 3, cn = w >> 2;
    const int i = (int)gridDim.x - 1 - (int)blockIdx.x;   // heavy tiles first
    const int bh = blockIdx.y;
    const int b = bh >> 4, h = bh & 15;

    const size_t qbase  = ((size_t)b * S_LEN + i * 128) * E_DIM + h * 64;
    const size_t kbase  = (size_t)b * S_LEN * E_DIM + h * 64;
    const size_t vtbase = (size_t)bh * 64 * S_LEN;

    // Q: 128 rows x 16 slots, hi only (group 0)
#pragma unroll
    for (int l = 0; l < 8; ++l) {
        int idx = tid + l * 256, row = idx >> 4, sl = idx & 15;
        uint32_t sw = (uint32_t)(row * 256 + ((sl ^ (row & 7)) << 4));
        CP16(sb + AQH + sw, s_q_hi + qbase + (size_t)row * E_DIM + sl * 4);
    }

    #define ISSUE_K(j_, st_) do {                                              \
        uint32_t kb_ = sb + AKB + (uint32_t)(st_) * 32768u;                    \
        _Pragma("unroll")                                                      \
        for (int l = 0; l < 4; ++l) {                                          \
            int idx_ = tid + l * 256, row_ = idx_ >> 4, sl_ = idx_ & 15;       \
            uint32_t sw_ = (uint32_t)(row_ * 256 + ((sl_ ^ (row_ & 7)) << 4)); \
            size_t ks_ = kbase + (size_t)((j_) * 64 + row_) * E_DIM + sl_ * 4; \
            CP16(kb_ + sw_, s_k_hi + ks_);                                     \
            CP16(kb_ + 16384u + sw_, s_k_lo + ks_);                            \
        }                                                                      \
    } while (0)

    #define ISSUE_VT(j_, st_) do {                                             \
        uint32_t vb_ = sb + AVB + (uint32_t)(st_) * 32768u;                    \
        _Pragma("unroll")                                                      \
        for (int l = 0; l < 4; ++l) {                                          \
            int idx_ = tid + l * 256, row_ = idx_ >> 4, sl_ = idx_ & 15;       \
            uint32_t sw_ = (uint32_t)(row_ * 256 + ((sl_ ^ (row_ & 7)) << 4)); \
            size_t vs_ = vtbase + (size_t)row_ * S_LEN + (j_) * 64 + sl_ * 4;  \
            CP16(vb_ + sw_, s_vt_hi + vs_);                                    \
            CP16(vb_ + 16384u + sw_, s_vt_lo + vs_);                           \
        }                                                                      \
    } while (0)

    const int jmax = 2 * i + 1;

    ISSUE_K(0, 0);
    ISSUE_VT(0, 0);
    CPCOMMIT();                 // G0: Q + K0 + VT0
    ISSUE_K(1, 1);
    ISSUE_VT(1, 1);
    CPCOMMIT();                 // G1: K1 + VT1

    const int i4 = lane >> 3, r8 = lane & 7;
    const int lr = lane >> 2;
    const int lc0 = 2 * (lane & 3);
    const int arow = ((i4 & 1) << 3) + r8;
    const int aslot_hi = i4 >> 1;
    const int pslot_lo = (lane & 3) >> 1;
    const uint32_t pword = (uint32_t)((lane & 1) << 3);
    const uint32_t pgbase_h = sb + APH + (uint32_t)rg * 8192;
    const int brow_off = ((i4 >> 1) << 3) + r8;
    const int bslot_lo = i4 & 1;

    float m_prev[2][2], lsum[2][2];
#pragma unroll
    for (int mt = 0; mt < 2; ++mt)
#pragma unroll
        for (int h2 = 0; h2 < 2; ++h2) { m_prev[mt][h2] = -INFINITY; lsum[mt][h2] = 0.f; }
    float o[2][4][4];
#pragma unroll
    for (int mt = 0; mt < 2; ++mt)
#pragma unroll
        for (int nt = 0; nt < 4; ++nt)
#pragma unroll
            for (int r = 0; r < 4; ++r) o[mt][nt][r] = 0.f;

    for (int j = 0; j <= jmax; ++j) {
        CPWAIT1();              // group j resident
        __syncthreads();
        const uint32_t kb  = sb + AKB + (uint32_t)(j & 1) * 32768u;
        const uint32_t vtb = sb + AVB + (uint32_t)(j & 1) * 32768u;

        // ---- S = Qhi * (Khi + Klo) ----
        float sacc[2][4][4];
#pragma unroll
        for (int mt = 0; mt < 2; ++mt)
#pragma unroll
            for (int nt = 0; nt < 4; ++nt)
#pragma unroll
                for (int r = 0; r < 4; ++r) sacc[mt][nt][r] = 0.f;

#pragma unroll
        for (int ks = 0; ks < 8; ++ks) {
            uint32_t khv[4][2], klv[4][2];
#pragma unroll
            for (int nt2 = 0; nt2 < 2; ++nt2) {
                const int brow = cn * 32 + nt2 * 16 + brow_off;
                const uint32_t boff = (uint32_t)(brow * 256
                    + ((((ks << 1) | bslot_lo) ^ (brow & 7)) << 4));
                LDSM_X4(khv[nt2 * 2][0], khv[nt2 * 2][1],
                        khv[nt2 * 2 + 1][0], khv[nt2 * 2 + 1][1], kb + boff);
                LDSM_X4(klv[nt2 * 2][0], klv[nt2 * 2][1],
                        klv[nt2 * 2 + 1][0], klv[nt2 * 2 + 1][1], kb + 16384u + boff);
            }
#pragma unroll
            for (int mt = 0; mt < 2; ++mt) {
                const int qrow = rg * 32 + mt * 16 + arow;
                const uint32_t aoff = (uint32_t)(qrow * 256
                    + ((((ks << 1) | aslot_hi) ^ (qrow & 7)) << 4));
                uint32_t ah[4];
                LDSM_X4(ah[0], ah[1], ah[2], ah[3], sb + AQH + aoff);
#pragma unroll
                for (int nt = 0; nt < 4; ++nt) {
                    MMA_TF32(sacc[mt][nt], ah, klv[nt][0], klv[nt][1]);
                    MMA_TF32(sacc[mt][nt], ah, khv[nt][0], khv[nt][1]);
                }
            }
        }

        // ---- mask + softmax ----
        float mloc[2][2] = {{-INFINITY, -INFINITY}, {-INFINITY, -INFINITY}};
#pragma unroll
        for (int mt = 0; mt < 2; ++mt) {
            const int qr0 = i * 128 + rg * 32 + mt * 16 + lr;
#pragma unroll
            for (int nt = 0; nt < 4; ++nt) {
                const int c0 = j * 64 + cn * 32 + (nt << 3) + lc0;
                float s0 = sacc[mt][nt][0] * 0.125f, s1 = sacc[mt][nt][1] * 0.125f;
                float s2 = sacc[mt][nt][2] * 0.125f, s3 = sacc[mt][nt][3] * 0.125f;
                if (c0     > qr0)     s0 = -INFINITY;
                if (c0 + 1 > qr0)     s1 = -INFINITY;
                if (c0     > qr0 + 8) s2 = -INFINITY;
                if (c0 + 1 > qr0 + 8) s3 = -INFINITY;
                sacc[mt][nt][0] = s0; sacc[mt][nt][1] = s1;
                sacc[mt][nt][2] = s2; sacc[mt][nt][3] = s3;
                mloc[mt][0] = fmaxf(mloc[mt][0], fmaxf(s0, s1));
                mloc[mt][1] = fmaxf(mloc[mt][1], fmaxf(s2, s3));
            }
#pragma unroll
            for (int h2 = 0; h2 < 2; ++h2) {
                mloc[mt][h2] = fmaxf(mloc[mt][h2], __shfl_xor_sync(0xffffffffu, mloc[mt][h2], 1));
                mloc[mt][h2] = fmaxf(mloc[mt][h2], __shfl_xor_sync(0xffffffffu, mloc[mt][h2], 2));
            }
        }
        if ((lane & 3) == 0) {
#pragma unroll
            for (int mt = 0; mt < 2; ++mt) {
                red_m[cn * 128 + rg * 32 + mt * 16 + lr]     = mloc[mt][0];
                red_m[cn * 128 + rg * 32 + mt * 16 + lr + 8] = mloc[mt][1];
            }
        }
        BARP(rg + 1);

        float fac[2][2], m_new[2][2];
#pragma unroll
        for (int mt = 0; mt < 2; ++mt)
#pragma unroll
            for (int h2 = 0; h2 < 2; ++h2) {
                const int row = rg * 32 + mt * 16 + lr + h2 * 8;
                const float mo = red_m[(cn ^ 1) * 128 + row];
                m_new[mt][h2] = fmaxf(m_prev[mt][h2], fmaxf(mloc[mt][h2], mo));
                fac[mt][h2] = (m_prev[mt][h2] == -INFINITY)
                            ? 0.f : __expf(m_prev[mt][h2] - m_new[mt][h2]);
                m_prev[mt][h2] = m_new[mt][h2];
            }

        // P rounded to tf32; denominator accumulated from the ROUNDED values.
        float ls[2][2] = {{0.f, 0.f}, {0.f, 0.f}};
#pragma unroll
        for (int mt = 0; mt < 2; ++mt) {
            const int rA = mt * 16 + lr, rB = rA + 8;
            const uint32_t rowA_h = pgbase_h + rA * 256, rowB_h = pgbase_h + rB * 256;
#pragma unroll
            for (int nt = 0; nt < 4; ++nt) {
                const uint32_t h0 = cvt_tf32(__expf(sacc[mt][nt][0] - m_new[mt][0]));
                const uint32_t h1 = cvt_tf32(__expf(sacc[mt][nt][1] - m_new[mt][0]));
                const uint32_t h2v = cvt_tf32(__expf(sacc[mt][nt][2] - m_new[mt][1]));
                const uint32_t h3 = cvt_tf32(__expf(sacc[mt][nt][3] - m_new[mt][1]));
                ls[mt][0] += __uint_as_float(h0) + __uint_as_float(h1);
                ls[mt][1] += __uint_as_float(h2v) + __uint_as_float(h3);
                const uint32_t slot = (uint32_t)((cn << 3) | (nt << 1) | pslot_lo);
                STS64(rowA_h + ((slot ^ (rA & 7)) << 4) + pword,
                      __uint_as_float(h0), __uint_as_float(h1));
                STS64(rowB_h + ((slot ^ (rB & 7)) << 4) + pword,
                      __uint_as_float(h2v), __uint_as_float(h3));
            }
#pragma unroll
            for (int h2 = 0; h2 < 2; ++h2) {
                ls[mt][h2] += __shfl_xor_sync(0xffffffffu, ls[mt][h2], 1);
                ls[mt][h2] += __shfl_xor_sync(0xffffffffu, ls[mt][h2], 2);
            }
        }
        if ((lane & 3) == 0) {
#pragma unroll
            for (int mt = 0; mt < 2; ++mt) {
                red_l[cn * 128 + rg * 32 + mt * 16 + lr]     = ls[mt][0];
                red_l[cn * 128 + rg * 32 + mt * 16 + lr + 8] = ls[mt][1];
            }
        }
        BARP(rg + 1);   // publishes red_l AND the pair's P tiles
#pragma unroll
        for (int mt = 0; mt < 2; ++mt)
#pragma unroll
            for (int h2 = 0; h2 < 2; ++h2) {
                const int row = rg * 32 + mt * 16 + lr + h2 * 8;
                lsum[mt][h2] = lsum[mt][h2] * fac[mt][h2] + red_l[row] + red_l[128 + row];
            }

#pragma unroll
        for (int mt = 0; mt < 2; ++mt)
#pragma unroll
            for (int nt = 0; nt < 4; ++nt) {
                o[mt][nt][0] *= fac[mt][0]; o[mt][nt][1] *= fac[mt][0];
                o[mt][nt][2] *= fac[mt][1]; o[mt][nt][3] *= fac[mt][1];
            }

        // ---- O += P V (P hi-only; V hi+lo) ----
#pragma unroll
        for (int ks = 0; ks < 8; ++ks) {
            uint32_t vhv[4][2], vlv[4][2];
#pragma unroll
            for (int nt2 = 0; nt2 < 2; ++nt2) {
                const int vrow = cn * 32 + nt2 * 16 + brow_off;
                const uint32_t voff = (uint32_t)(vrow * 256
                    + ((((ks << 1) | bslot_lo) ^ (vrow & 7)) << 4));
                LDSM_X4(vhv[nt2 * 2][0], vhv[nt2 * 2][1],
                        vhv[nt2 * 2 + 1][0], vhv[nt2 * 2 + 1][1], vtb + voff);
                LDSM_X4(vlv[nt2 * 2][0], vlv[nt2 * 2][1],
                        vlv[nt2 * 2 + 1][0], vlv[nt2 * 2 + 1][1], vtb + 16384u + voff);
            }
#pragma unroll
            for (int mt = 0; mt < 2; ++mt) {
                const int prow_ = mt * 16 + arow;
                const uint32_t poff = (uint32_t)(prow_ * 256
                    + ((((ks << 1) | aslot_hi) ^ (prow_ & 7)) << 4));
                uint32_t ph[4];
                LDSM_X4(ph[0], ph[1], ph[2], ph[3], pgbase_h + poff);
#pragma unroll
                for (int nt = 0; nt < 4; ++nt) {
                    MMA_TF32(o[mt][nt], ph, vlv[nt][0], vlv[nt][1]);
                    MMA_TF32(o[mt][nt], ph, vhv[nt][0], vhv[nt][1]);
                }
            }
        }

        __syncthreads();   // all reads of stage (j&1) done before refill
        if (j + 2 <= jmax) {
            ISSUE_K(j + 2, j & 1);
            ISSUE_VT(j + 2, j & 1);
        }
        CPCOMMIT();        // one group per iteration keeps wait_group counts aligned
    }

    // ---- epilogue: O hi only (out-proj A-side is hi-only) ----
#pragma unroll
    for (int mt = 0; mt < 2; ++mt) {
        const float inv0 = 1.f / lsum[mt][0];
        const float inv1 = 1.f / lsum[mt][1];
        const size_t rowA = ((size_t)b * S_LEN + i * 128 + rg * 32 + mt * 16 + lr) * E_DIM;
        const size_t rowB = rowA + (size_t)8 * E_DIM;
#pragma unroll
        for (int nt = 0; nt < 4; ++nt) {
            const int col = h * 64 + cn * 32 + (nt << 3) + lc0;
            *(uint2*)&s_o_hi[rowA + col] =
                make_uint2(cvt_tf32(o[mt][nt][0] * inv0), cvt_tf32(o[mt][nt][1] * inv0));
            *(uint2*)&s_o_hi[rowB + col] =
                make_uint2(cvt_tf32(o[mt][nt][2] * inv1), cvt_tf32(o[mt][nt][3] * inv1));
        }
    }
}

// ===================== launch =====================
extern "C" void kernel_launch(void* const* d_in, const int* in_sizes, int n_in,
                              void* d_out, int out_size)
{
    (void)in_sizes; (void)n_in; (void)out_size;
    const float* q  = (const float*)d_in[0];
    const float* k  = (const float*)d_in[1];
    const float* v  = (const float*)d_in[2];
    const float* Wq = (const float*)d_in[3];
    const float* bq = (const float*)d_in[4];
    const float* Wk = (const float*)d_in[5];
    const float* bk = (const float*)d_in[6];
    const float* Wv = (const float*)d_in[7];
    const float* bv = (const float*)d_in[8];
    const float* Wo = (const float*)d_in[9];
    const float* bo = (const float*)d_in[10];
    float* out = (float*)d_out;

    cudaFuncSetAttribute(gemm_tc_kernel, cudaFuncAttributeMaxDynamicSharedMemorySize, GEMM_SMEM);
    cudaFuncSetAttribute(attn_tc_kernel, cudaFuncAttributeMaxDynamicSharedMemorySize, ATTN_SMEM);

    // fused pre-split (2 launches; inputs hi-only, weights hi+lo)
    dim3 gridSM((unsigned)(ME / 4 / 256), 3);
    split_me_kernel<<<gridSM, 256>>>((const float4*)q, (const float4*)k, (const float4*)v);
    dim3 gridSW((unsigned)(EE / 4 / 256), 4);
    split_w_kernel<<<gridSW, 256>>>((const float4*)Wq, (const float4*)Wk,
                                    (const float4*)Wv, (const float4*)Wo);

    // Q/K/V projections (epilogues emit attention operands)
    dim3 gridP(E_DIM / 128, M_ROWS / 128, 3);
    gemm_tc_kernel<<<gridP, 256, GEMM_SMEM>>>(bq, bk, bv, bo, out, 0);

    // causal flash attention, 128-row q-tiles (emits O hi)
    dim3 gridA(S_LEN / 128, N_BATCH * N_HEADS);
    attn_tc_kernel<<<gridA, 256, ATTN_SMEM>>>();

    // output projection
    dim3 gridO(E_DIM / 128, M_ROWS / 128, 1);
    gemm_tc_kernel<<<gridO, 256, GEMM_SMEM>>>(bq, bk, bv, bo, out, 1);
}

// round 14
// speedup vs baseline: 1.7322x; 1.1464x over previous
#include <cuda_runtime.h>
#include <math.h>
#include <stdint.h>

#define E_DIM   1024
#define S_LEN   2048
#define N_BATCH 2
#define N_HEADS 16
#define H_DIM   64
#define M_ROWS  (N_BATCH * S_LEN)   // 4096
#define ME      ((size_t)M_ROWS * E_DIM)   // 4M elems
#define EE      ((size_t)E_DIM * E_DIM)    // 1M elems

// ---------- global scratch (allocation-free) ----------
// A-side operands hi-only; GEMM B-side weights hi+lo; attention K/VT hi-only.
__device__ uint32_t s_xq_hi[ME];
__device__ uint32_t s_xk_hi[ME];
__device__ uint32_t s_xv_hi[ME];
__device__ uint32_t s_wq_hi[EE], s_wq_lo[EE];
__device__ uint32_t s_wk_hi[EE], s_wk_lo[EE];
__device__ uint32_t s_wv_hi[EE], s_wv_lo[EE];
__device__ uint32_t s_wo_hi[EE], s_wo_lo[EE];
__device__ uint32_t s_q_hi[ME];
__device__ uint32_t s_k_hi[ME];
__device__ uint32_t s_vt_hi[ME];   // [bh][d][s]
__device__ uint32_t s_o_hi[ME];

// ===================== helpers =====================
__device__ __forceinline__ uint32_t smem_u32(const void* p) {
    uint32_t a;
    asm("{ .reg .u64 t; cvta.to.shared.u64 t, %1; cvt.u32.u64 %0, t; }" : "=r"(a) : "l"(p));
    return a;
}
__device__ __forceinline__ uint32_t cvt_tf32(float f) {
    uint32_t u;
    asm("cvt.rna.tf32.f32 %0, %1;" : "=r"(u) : "f"(f));
    return u;
}
__device__ __forceinline__ void split2(float f, uint32_t& hi, uint32_t& lo) {
    hi = cvt_tf32(f);
    lo = cvt_tf32(f - __uint_as_float(hi));
}
__device__ __forceinline__ void split4(float4 v, uint4& hi, uint4& lo) {
    split2(v.x, hi.x, lo.x);
    split2(v.y, hi.y, lo.y);
    split2(v.z, hi.z, lo.z);
    split2(v.w, hi.w, lo.w);
}
__device__ __forceinline__ uint4 hi4(float4 v) {
    uint4 h;
    h.x = cvt_tf32(v.x); h.y = cvt_tf32(v.y);
    h.z = cvt_tf32(v.z); h.w = cvt_tf32(v.w);
    return h;
}

#define CP16(dst, src) \
    asm volatile("cp.async.cg.shared.global [%0], [%1], 16;" :: "r"(dst), "l"(src))
#define CPCOMMIT() asm volatile("cp.async.commit_group;" ::: "memory")
#define CPWAIT1()  asm volatile("cp.async.wait_group 1;" ::: "memory")

#define LDSM_X4(r0, r1, r2, r3, addr)                                          \
    asm volatile("ldmatrix.sync.aligned.m8n8.x4.shared.b16 {%0,%1,%2,%3}, [%4];" \
                 : "=r"(r0), "=r"(r1), "=r"(r2), "=r"(r3) : "r"(addr))
#define LDSM_X2(r0, r1, addr)                                                  \
    asm volatile("ldmatrix.sync.aligned.m8n8.x2.shared.b16 {%0,%1}, [%2];"     \
                 : "=r"(r0), "=r"(r1) : "r"(addr))

#define MMA_TF32(d, A, b0v, b1v)                                               \
    asm volatile("mma.sync.aligned.m16n8k8.row.col.f32.tf32.tf32.f32 "         \
                 "{%0,%1,%2,%3}, {%4,%5,%6,%7}, {%8,%9}, {%0,%1,%2,%3};"       \
                 : "+f"((d)[0]), "+f"((d)[1]), "+f"((d)[2]), "+f"((d)[3])      \
                 : "r"((A)[0]), "r"((A)[1]), "r"((A)[2]), "r"((A)[3]),         \
                   "r"(b0v), "r"(b1v))

#define STS64(addr, v0, v1) \
    asm volatile("st.shared.v2.f32 [%0], {%1,%2};" :: "r"(addr), "f"(v0), "f"(v1))
#define BARP(id) asm volatile("bar.sync %0, 64;" :: "r"(id) : "memory")

// ===================== fused pre-split kernels =====================
__global__ __launch_bounds__(256) void split_me_kernel(
    const float4* __restrict__ q, const float4* __restrict__ k, const float4* __restrict__ v)
{
    const int t = blockIdx.y;
    const float4* src = (t == 0) ? q : ((t == 1) ? k : v);
    uint4* hi = (t == 0) ? (uint4*)s_xq_hi : ((t == 1) ? (uint4*)s_xk_hi : (uint4*)s_xv_hi);
    int i = blockIdx.x * 256 + threadIdx.x;
    hi[i] = hi4(src[i]);
}
__global__ __launch_bounds__(256) void split_w_kernel(
    const float4* __restrict__ wq, const float4* __restrict__ wk,
    const float4* __restrict__ wv, const float4* __restrict__ wo)
{
    const int t = blockIdx.y;
    const float4* src = (t == 0) ? wq : ((t == 1) ? wk : ((t == 2) ? wv : wo));
    uint4* hi = (t == 0) ? (uint4*)s_wq_hi : ((t == 1) ? (uint4*)s_wk_hi
              : ((t == 2) ? (uint4*)s_wv_hi : (uint4*)s_wo_hi));
    uint4* lo = (t == 0) ? (uint4*)s_wq_lo : ((t == 1) ? (uint4*)s_wk_lo
              : ((t == 2) ? (uint4*)s_wv_lo : (uint4*)s_wo_lo));
    int i = blockIdx.x * 256 + threadIdx.x;
    uint4 h, l;
    split4(src[i], h, l);
    hi[i] = h;
    lo[i] = l;
}

// ===================== GEMM: Y = Xhi @ (Whi+Wlo)^T + b (2-MMA, identical to R13) =====================
#define NCHUNK   (E_DIM / 16)
#define ROWB     80
#define AHI_OFF  0u
#define BHI_OFF  10240u
#define BLO_OFF  20480u
#define STAGE_B  30720u
#define GEMM_SMEM (2 * 30720)

__global__ __launch_bounds__(256, 2) void gemm_tc_kernel(
    const float* __restrict__ bq, const float* __restrict__ bk,
    const float* __restrict__ bv, const float* __restrict__ bo,
    float* __restrict__ out, int is_out)
{
    extern __shared__ char smem[];
    const int z = blockIdx.z;
    const uint32_t *Xhi, *Whi, *Wlo;
    const float* Bv;
    int mode;
    if (is_out) { Xhi = s_o_hi;  Whi = s_wo_hi; Wlo = s_wo_lo; Bv = bo; mode = 3; }
    else if (z == 0) { Xhi = s_xq_hi; Whi = s_wq_hi; Wlo = s_wq_lo; Bv = bq; mode = 0; }
    else if (z == 1) { Xhi = s_xk_hi; Whi = s_wk_hi; Wlo = s_wk_lo; Bv = bk; mode = 1; }
    else             { Xhi = s_xv_hi; Whi = s_wv_hi; Wlo = s_wv_lo; Bv = bv; mode = 2; }

    const int tid  = threadIdx.x;
    const int lane = tid & 31;
    const int wid  = tid >> 5;
    const int wm   = wid >> 2;
    const int wn   = wid & 3;
    const int m0 = blockIdx.y * 128;
    const int n0 = blockIdx.x * 128;

    const uint32_t sb = smem_u32(smem);

    const int prow = tid >> 2;
    const int pc4  = tid & 3;
    const size_t xoff = (size_t)(m0 + prow) * E_DIM + pc4 * 4;
    const size_t woff = (size_t)(n0 + prow) * E_DIM + pc4 * 4;
    const uint32_t pd = (uint32_t)prow * ROWB + (uint32_t)pc4 * 16;

    #define GCP_CHUNK(c, st) do {                                              \
        uint32_t base_ = sb + (uint32_t)(st) * STAGE_B + pd;                   \
        size_t ko_ = (size_t)(c) * 16;                                         \
        _Pragma("unroll")                                                      \
        for (int r = 0; r < 2; ++r) {                                          \
            size_t sx_ = xoff + (size_t)r * 64 * E_DIM + ko_;                  \
            size_t sw_ = woff + (size_t)r * 64 * E_DIM + ko_;                  \
            uint32_t dd_ = base_ + (uint32_t)r * 5120;                         \
            CP16(dd_ + AHI_OFF, Xhi + sx_);                                    \
            CP16(dd_ + BHI_OFF, Whi + sw_);                                    \
            CP16(dd_ + BLO_OFF, Wlo + sw_);                                    \
        }                                                                      \
    } while (0)

    GCP_CHUNK(0, 0); CPCOMMIT();
    GCP_CHUNK(1, 1); CPCOMMIT();

    const int i4 = lane >> 3, r8 = lane & 7;
    const uint32_t a_off = (uint32_t)(wm * 64 + ((i4 & 1) << 3) + r8) * ROWB
                         + (uint32_t)((i4 >> 1) << 4);
    const uint32_t b_off = (uint32_t)(wn * 32 + r8) * ROWB
                         + (uint32_t)((i4 & 1) << 4);

    float acc[4][4][4];
#pragma unroll
    for (int mt = 0; mt < 4; ++mt)
#pragma unroll
        for (int nt = 0; nt < 4; ++nt)
#pragma unroll
            for (int r = 0; r < 4; ++r) acc[mt][nt][r] = 0.f;

    for (int c = 0; c < NCHUNK; ++c) {
        CPWAIT1();
        __syncthreads();
        const uint32_t stb = sb + (uint32_t)(c & 1) * STAGE_B;

#pragma unroll
        for (int ks = 0; ks < 2; ++ks) {
            uint32_t bhv[4][2], blv[4][2];
#pragma unroll
            for (int nt = 0; nt < 4; ++nt) {
                const uint32_t ba = stb + b_off + nt * (8 * ROWB) + ks * 32;
                LDSM_X2(bhv[nt][0], bhv[nt][1], ba + BHI_OFF);
                LDSM_X2(blv[nt][0], blv[nt][1], ba + BLO_OFF);
            }
#pragma unroll
            for (int mt = 0; mt < 4; ++mt) {
                const uint32_t aa = stb + a_off + mt * (16 * ROWB) + ks * 32;
                uint32_t ah[4];
                LDSM_X4(ah[0], ah[1], ah[2], ah[3], aa + AHI_OFF);
#pragma unroll
                for (int nt = 0; nt < 4; ++nt) {
                    MMA_TF32(acc[mt][nt], ah, blv[nt][0], blv[nt][1]);
                    MMA_TF32(acc[mt][nt], ah, bhv[nt][0], bhv[nt][1]);
                }
            }
        }

        __syncthreads();
        if (c + 2 < NCHUNK) GCP_CHUNK(c + 2, c & 1);
        CPCOMMIT();
    }

    if (mode == 3) {
#pragma unroll
        for (int nt = 0; nt < 4; ++nt) {
            const int col = n0 + wn * 32 + nt * 8 + 2 * (lane & 3);
            const float bx = __ldg(&Bv[col]);
            const float by = __ldg(&Bv[col + 1]);
#pragma unroll
            for (int mt = 0; mt < 4; ++mt) {
                const int r0i = m0 + wm * 64 + mt * 16 + (lane >> 2);
                *(float2*)&out[(size_t)r0i * E_DIM + col] =
                    make_float2(acc[mt][nt][0] + bx, acc[mt][nt][1] + by);
                *(float2*)&out[(size_t)(r0i + 8) * E_DIM + col] =
                    make_float2(acc[mt][nt][2] + bx, acc[mt][nt][3] + by);
            }
        }
    } else if (mode == 2) {
        // V^T epilogue: hi only
        const int bq2 = m0 >> 11;
#pragma unroll
        for (int nt = 0; nt < 4; ++nt) {
            const int col = n0 + wn * 32 + nt * 8 + 2 * (lane & 3);
            const int hh = col >> 6, dd = col & 63;
            const float bx = __ldg(&Bv[col]);
            const float by = __ldg(&Bv[col + 1]);
            const size_t b0i = ((size_t)(bq2 * 16 + hh) * 64 + dd) * S_LEN;
            const size_t b1i = b0i + S_LEN;
#pragma unroll
            for (int mt = 0; mt < 4; ++mt) {
                const int s = (m0 & 2047) + wm * 64 + mt * 16 + (lane >> 2);
                s_vt_hi[b0i + s]     = cvt_tf32(acc[mt][nt][0] + bx);
                s_vt_hi[b1i + s]     = cvt_tf32(acc[mt][nt][1] + by);
                s_vt_hi[b0i + s + 8] = cvt_tf32(acc[mt][nt][2] + bx);
                s_vt_hi[b1i + s + 8] = cvt_tf32(acc[mt][nt][3] + by);
            }
        }
    } else {
        // Q / K epilogue: hi only
        uint32_t* Yh = (mode == 0) ? s_q_hi : s_k_hi;
#pragma unroll
        for (int nt = 0; nt < 4; ++nt) {
            const int col = n0 + wn * 32 + nt * 8 + 2 * (lane & 3);
            const float bx = __ldg(&Bv[col]);
            const float by = __ldg(&Bv[col + 1]);
#pragma unroll
            for (int mt = 0; mt < 4; ++mt) {
                const int r0i = m0 + wm * 64 + mt * 16 + (lane >> 2);
                *(uint2*)&Yh[(size_t)r0i * E_DIM + col] =
                    make_uint2(cvt_tf32(acc[mt][nt][0] + bx), cvt_tf32(acc[mt][nt][1] + by));
                *(uint2*)&Yh[(size_t)(r0i + 8) * E_DIM + col] =
                    make_uint2(cvt_tf32(acc[mt][nt][2] + bx), cvt_tf32(acc[mt][nt][3] + by));
            }
        }
    }
}

// ===================== Causal flash attention: all-hi tf32 =====================
// 8 warps: rg=w&3 (32 rows), cn=w>>2 (32 of 64 cols). K and VT 2-stage, hi-only.
// S = Qhi*Khi (1 MMA), O += Phat*Vhi (1 MMA); denominator from rounded P.
// smem: Qhi 32K | K 2st 32K | VT 2st 32K | Phi 32K | red 2K = 133120
#define AQH   0u
#define AKB   32768u      // + stage*16384
#define AVB   65536u      // + stage*16384
#define APH   98304u      // + rg*8192
#define ARED  131072u
#define ATTN_SMEM 133120

__global__ __launch_bounds__(256) void attn_tc_kernel(void)
{
    extern __shared__ char smem[];
    const uint32_t sb = smem_u32(smem);
    float* red_m = (float*)(smem + ARED);          // [2][128]
    float* red_l = (float*)(smem + ARED + 1024);   // [2][128]

    const int tid = threadIdx.x, lane = tid & 31, w = tid >> 5;
    const int rg = w & 3, cn = w >> 2;
    const int i = (int)gridDim.x - 1 - (int)blockIdx.x;   // heavy tiles first
    const int bh = blockIdx.y;
    const int b = bh >> 4, h = bh & 15;

    const size_t qbase  = ((size_t)b * S_LEN + i * 128) * E_DIM + h * 64;
    const size_t kbase  = (size_t)b * S_LEN * E_DIM + h * 64;
    const size_t vtbase = (size_t)bh * 64 * S_LEN;

    // Q: 128 rows x 16 slots, hi only (group 0)
#pragma unroll
    for (int l = 0; l < 8; ++l) {
        int idx = tid + l * 256, row = idx >> 4, sl = idx & 15;
        uint32_t sw = (uint32_t)(row * 256 + ((sl ^ (row & 7)) << 4));
        CP16(sb + AQH + sw, s_q_hi + qbase + (size_t)row * E_DIM + sl * 4);
    }

    #define ISSUE_K(j_, st_) do {                                              \
        uint32_t kb_ = sb + AKB + (uint32_t)(st_) * 16384u;                    \
        _Pragma("unroll")                                                      \
        for (int l = 0; l < 4; ++l) {                                          \
            int idx_ = tid + l * 256, row_ = idx_ >> 4, sl_ = idx_ & 15;       \
            uint32_t sw_ = (uint32_t)(row_ * 256 + ((sl_ ^ (row_ & 7)) << 4)); \
            CP16(kb_ + sw_, s_k_hi + kbase + (size_t)((j_) * 64 + row_) * E_DIM + sl_ * 4); \
        }                                                                      \
    } while (0)

    #define ISSUE_VT(j_, st_) do {                                             \
        uint32_t vb_ = sb + AVB + (uint32_t)(st_) * 16384u;                    \
        _Pragma("unroll")                                                      \
        for (int l = 0; l < 4; ++l) {                                          \
            int idx_ = tid + l * 256, row_ = idx_ >> 4, sl_ = idx_ & 15;       \
            uint32_t sw_ = (uint32_t)(row_ * 256 + ((sl_ ^ (row_ & 7)) << 4)); \
            CP16(vb_ + sw_, s_vt_hi + vtbase + (size_t)row_ * S_LEN + (j_) * 64 + sl_ * 4); \
        }                                                                      \
    } while (0)

    const int jmax = 2 * i + 1;

    ISSUE_K(0, 0);
    ISSUE_VT(0, 0);
    CPCOMMIT();                 // G0: Q + K0 + VT0
    ISSUE_K(1, 1);
    ISSUE_VT(1, 1);
    CPCOMMIT();                 // G1: K1 + VT1

    const int i4 = lane >> 3, r8 = lane & 7;
    const int lr = lane >> 2;
    const int lc0 = 2 * (lane & 3);
    const int arow = ((i4 & 1) << 3) + r8;
    const int aslot_hi = i4 >> 1;
    const int pslot_lo = (lane & 3) >> 1;
    const uint32_t pword = (uint32_t)((lane & 1) << 3);
    const uint32_t pgbase_h = sb + APH + (uint32_t)rg * 8192;
    const int brow_off = ((i4 >> 1) << 3) + r8;
    const int bslot_lo = i4 & 1;

    float m_prev[2][2], lsum[2][2];
#pragma unroll
    for (int mt = 0; mt < 2; ++mt)
#pragma unroll
        for (int h2 = 0; h2 < 2; ++h2) { m_prev[mt][h2] = -INFINITY; lsum[mt][h2] = 0.f; }
    float o[2][4][4];
#pragma unroll
    for (int mt = 0; mt < 2; ++mt)
#pragma unroll
        for (int nt = 0; nt < 4; ++nt)
#pragma unroll
            for (int r = 0; r < 4; ++r) o[mt][nt][r] = 0.f;

    for (int j = 0; j <= jmax; ++j) {
        CPWAIT1();              // group j resident
        __syncthreads();
        const uint32_t kb  = sb + AKB + (uint32_t)(j & 1) * 16384u;
        const uint32_t vtb = sb + AVB + (uint32_t)(j & 1) * 16384u;

        // ---- S = Qhi * Khi ----
        float sacc[2][4][4];
#pragma unroll
        for (int mt = 0; mt < 2; ++mt)
#pragma unroll
            for (int nt = 0; nt < 4; ++nt)
#pragma unroll
                for (int r = 0; r < 4; ++r) sacc[mt][nt][r] = 0.f;

#pragma unroll
        for (int ks = 0; ks < 8; ++ks) {
            uint32_t khv[4][2];
#pragma unroll
            for (int nt2 = 0; nt2 < 2; ++nt2) {
                const int brow = cn * 32 + nt2 * 16 + brow_off;
                const uint32_t boff = (uint32_t)(brow * 256
                    + ((((ks << 1) | bslot_lo) ^ (brow & 7)) << 4));
                LDSM_X4(khv[nt2 * 2][0], khv[nt2 * 2][1],
                        khv[nt2 * 2 + 1][0], khv[nt2 * 2 + 1][1], kb + boff);
            }
#pragma unroll
            for (int mt = 0; mt < 2; ++mt) {
                const int qrow = rg * 32 + mt * 16 + arow;
                const uint32_t aoff = (uint32_t)(qrow * 256
                    + ((((ks << 1) | aslot_hi) ^ (qrow & 7)) << 4));
                uint32_t ah[4];
                LDSM_X4(ah[0], ah[1], ah[2], ah[3], sb + AQH + aoff);
#pragma unroll
                for (int nt = 0; nt < 4; ++nt)
                    MMA_TF32(sacc[mt][nt], ah, khv[nt][0], khv[nt][1]);
            }
        }

        // ---- mask + softmax ----
        float mloc[2][2] = {{-INFINITY, -INFINITY}, {-INFINITY, -INFINITY}};
#pragma unroll
        for (int mt = 0; mt < 2; ++mt) {
            const int qr0 = i * 128 + rg * 32 + mt * 16 + lr;
#pragma unroll
            for (int nt = 0; nt < 4; ++nt) {
                const int c0 = j * 64 + cn * 32 + (nt << 3) + lc0;
                float s0 = sacc[mt][nt][0] * 0.125f, s1 = sacc[mt][nt][1] * 0.125f;
                float s2 = sacc[mt][nt][2] * 0.125f, s3 = sacc[mt][nt][3] * 0.125f;
                if (c0     > qr0)     s0 = -INFINITY;
                if (c0 + 1 > qr0)     s1 = -INFINITY;
                if (c0     > qr0 + 8) s2 = -INFINITY;
                if (c0 + 1 > qr0 + 8) s3 = -INFINITY;
                sacc[mt][nt][0] = s0; sacc[mt][nt][1] = s1;
                sacc[mt][nt][2] = s2; sacc[mt][nt][3] = s3;
                mloc[mt][0] = fmaxf(mloc[mt][0], fmaxf(s0, s1));
                mloc[mt][1] = fmaxf(mloc[mt][1], fmaxf(s2, s3));
            }
#pragma unroll
            for (int h2 = 0; h2 < 2; ++h2) {
                mloc[mt][h2] = fmaxf(mloc[mt][h2], __shfl_xor_sync(0xffffffffu, mloc[mt][h2], 1));
                mloc[mt][h2] = fmaxf(mloc[mt][h2], __shfl_xor_sync(0xffffffffu, mloc[mt][h2], 2));
            }
        }
        if ((lane & 3) == 0) {
#pragma unroll
            for (int mt = 0; mt < 2; ++mt) {
                red_m[cn * 128 + rg * 32 + mt * 16 + lr]     = mloc[mt][0];
                red_m[cn * 128 + rg * 32 + mt * 16 + lr + 8] = mloc[mt][1];
            }
        }
        BARP(rg + 1);

        float fac[2][2], m_new[2][2];
#pragma unroll
        for (int mt = 0; mt < 2; ++mt)
#pragma unroll
            for (int h2 = 0; h2 < 2; ++h2) {
                const int row = rg * 32 + mt * 16 + lr + h2 * 8;
                const float mo = red_m[(cn ^ 1) * 128 + row];
                m_new[mt][h2] = fmaxf(m_prev[mt][h2], fmaxf(mloc[mt][h2], mo));
                fac[mt][h2] = (m_prev[mt][h2] == -INFINITY)
                            ? 0.f : __expf(m_prev[mt][h2] - m_new[mt][h2]);
                m_prev[mt][h2] = m_new[mt][h2];
            }

        // P rounded to tf32; denominator accumulated from the ROUNDED values.
        float ls[2][2] = {{0.f, 0.f}, {0.f, 0.f}};
#pragma unroll
        for (int mt = 0; mt < 2; ++mt) {
            const int rA = mt * 16 + lr, rB = rA + 8;
            const uint32_t rowA_h = pgbase_h + rA * 256, rowB_h = pgbase_h + rB * 256;
#pragma unroll
            for (int nt = 0; nt < 4; ++nt) {
                const uint32_t h0 = cvt_tf32(__expf(sacc[mt][nt][0] - m_new[mt][0]));
                const uint32_t h1 = cvt_tf32(__expf(sacc[mt][nt][1] - m_new[mt][0]));
                const uint32_t h2v = cvt_tf32(__expf(sacc[mt][nt][2] - m_new[mt][1]));
                const uint32_t h3 = cvt_tf32(__expf(sacc[mt][nt][3] - m_new[mt][1]));
                ls[mt][0] += __uint_as_float(h0) + __uint_as_float(h1);
                ls[mt][1] += __uint_as_float(h2v) + __uint_as_float(h3);
                const uint32_t slot = (uint32_t)((cn << 3) | (nt << 1) | pslot_lo);
                STS64(rowA_h + ((slot ^ (rA & 7)) << 4) + pword,
                      __uint_as_float(h0), __uint_as_float(h1));
                STS64(rowB_h + ((slot ^ (rB & 7)) << 4) + pword,
                      __uint_as_float(h2v), __uint_as_float(h3));
            }
#pragma unroll
            for (int h2 = 0; h2 < 2; ++h2) {
                ls[mt][h2] += __shfl_xor_sync(0xffffffffu, ls[mt][h2], 1);
                ls[mt][h2] += __shfl_xor_sync(0xffffffffu, ls[mt][h2], 2);
            }
        }
        if ((lane & 3) == 0) {
#pragma unroll
            for (int mt = 0; mt < 2; ++mt) {
                red_l[cn * 128 + rg * 32 + mt * 16 + lr]     = ls[mt][0];
                red_l[cn * 128 + rg * 32 + mt * 16 + lr + 8] = ls[mt][1];
            }
        }
        BARP(rg + 1);   // publishes red_l AND the pair's P tiles
#pragma unroll
        for (int mt = 0; mt < 2; ++mt)
#pragma unroll
            for (int h2 = 0; h2 < 2; ++h2) {
                const int row = rg * 32 + mt * 16 + lr + h2 * 8;
                lsum[mt][h2] = lsum[mt][h2] * fac[mt][h2] + red_l[row] + red_l[128 + row];
            }

#pragma unroll
        for (int mt = 0; mt < 2; ++mt)
#pragma unroll
            for (int nt = 0; nt < 4; ++nt) {
                o[mt][nt][0] *= fac[mt][0]; o[mt][nt][1] *= fac[mt][0];
                o[mt][nt][2] *= fac[mt][1]; o[mt][nt][3] *= fac[mt][1];
            }

        // ---- O += Phat * Vhi (1 MMA) ----
#pragma unroll
        for (int ks = 0; ks < 8; ++ks) {
            uint32_t vhv[4][2];
#pragma unroll
            for (int nt2 = 0; nt2 < 2; ++nt2) {
                const int vrow = cn * 32 + nt2 * 16 + brow_off;
                const uint32_t voff = (uint32_t)(vrow * 256
                    + ((((ks << 1) | bslot_lo) ^ (vrow & 7)) << 4));
                LDSM_X4(vhv[nt2 * 2][0], vhv[nt2 * 2][1],
                        vhv[nt2 * 2 + 1][0], vhv[nt2 * 2 + 1][1], vtb + voff);
            }
#pragma unroll
            for (int mt = 0; mt < 2; ++mt) {
                const int prow_ = mt * 16 + arow;
                const uint32_t poff = (uint32_t)(prow_ * 256
                    + ((((ks << 1) | aslot_hi) ^ (prow_ & 7)) << 4));
                uint32_t ph[4];
                LDSM_X4(ph[0], ph[1], ph[2], ph[3], pgbase_h + poff);
#pragma unroll
                for (int nt = 0; nt < 4; ++nt)
                    MMA_TF32(o[mt][nt], ph, vhv[nt][0], vhv[nt][1]);
            }
        }

        __syncthreads();   // all reads of stage (j&1) done before refill
        if (j + 2 <= jmax) {
            ISSUE_K(j + 2, j & 1);
            ISSUE_VT(j + 2, j & 1);
        }
        CPCOMMIT();        // one group per iteration keeps wait_group counts aligned
    }

    // ---- epilogue: O hi only (out-proj A-side is hi-only) ----
#pragma unroll
    for (int mt = 0; mt < 2; ++mt) {
        const float inv0 = 1.f / lsum[mt][0];
        const float inv1 = 1.f / lsum[mt][1];
        const size_t rowA = ((size_t)b * S_LEN + i * 128 + rg * 32 + mt * 16 + lr) * E_DIM;
        const size_t rowB = rowA + (size_t)8 * E_DIM;
#pragma unroll
        for (int nt = 0; nt < 4; ++nt) {
            const int col = h * 64 + cn * 32 + (nt << 3) + lc0;
            *(uint2*)&s_o_hi[rowA + col] =
                make_uint2(cvt_tf32(o[mt][nt][0] * inv0), cvt_tf32(o[mt][nt][1] * inv0));
            *(uint2*)&s_o_hi[rowB + col] =
                make_uint2(cvt_tf32(o[mt][nt][2] * inv1), cvt_tf32(o[mt][nt][3] * inv1));
        }
    }
}

// ===================== launch =====================
extern "C" void kernel_launch(void* const* d_in, const int* in_sizes, int n_in,
                              void* d_out, int out_size)
{
    (void)in_sizes; (void)n_in; (void)out_size;
    const float* q  = (const float*)d_in[0];
    const float* k  = (const float*)d_in[1];
    const float* v  = (const float*)d_in[2];
    const float* Wq = (const float*)d_in[3];
    const float* bq = (const float*)d_in[4];
    const float* Wk = (const float*)d_in[5];
    const float* bk = (const float*)d_in[6];
    const float* Wv = (const float*)d_in[7];
    const float* bv = (const float*)d_in[8];
    const float* Wo = (const float*)d_in[9];
    const float* bo = (const float*)d_in[10];
    float* out = (float*)d_out;

    cudaFuncSetAttribute(gemm_tc_kernel, cudaFuncAttributeMaxDynamicSharedMemorySize, GEMM_SMEM);
    cudaFuncSetAttribute(attn_tc_kernel, cudaFuncAttributeMaxDynamicSharedMemorySize, ATTN_SMEM);

    // fused pre-split (2 launches; inputs hi-only, weights hi+lo)
    dim3 gridSM((unsigned)(ME / 4 / 256), 3);
    split_me_kernel<<<gridSM, 256>>>((const float4*)q, (const float4*)k, (const float4*)v);
    dim3 gridSW((unsigned)(EE / 4 / 256), 4);
    split_w_kernel<<<gridSW, 256>>>((const float4*)Wq, (const float4*)Wk,
                                    (const float4*)Wv, (const float4*)Wo);

    // Q/K/V projections (epilogues emit attention operands, all hi-only)
    dim3 gridP(E_DIM / 128, M_ROWS / 128, 3);
    gemm_tc_kernel<<<gridP, 256, GEMM_SMEM>>>(bq, bk, bv, bo, out, 0);

    // causal flash attention, 128-row q-tiles (emits O hi)
    dim3 gridA(S_LEN / 128, N_BATCH * N_HEADS);
    attn_tc_kernel<<<gridA, 256, ATTN_SMEM>>>();

    // output projection
    dim3 gridO(E_DIM / 128, M_ROWS / 128, 1);
    gemm_tc_kernel<<<gridO, 256, GEMM_SMEM>>>(bq, bk, bv, bo, out, 1);
}

// round 15
// speedup vs baseline: 2.4063x; 1.3891x over previous
#include <cuda_runtime.h>
#include <math.h>
#include <stdint.h>

#define E_DIM   1024
#define S_LEN   2048
#define N_BATCH 2
#define N_HEADS 16
#define H_DIM   64
#define M_ROWS  (N_BATCH * S_LEN)   // 4096
#define ME      ((size_t)M_ROWS * E_DIM)   // 4M elems
#define EE      ((size_t)E_DIM * E_DIM)    // 1M elems

// ---------- global scratch (allocation-free) ----------
// Everything tf32-hi only (pure-tf32 pipeline, error budget calibrated R12-R14).
__device__ uint32_t s_xq_hi[ME];
__device__ uint32_t s_xk_hi[ME];
__device__ uint32_t s_xv_hi[ME];
__device__ uint32_t s_wq_hi[EE];
__device__ uint32_t s_wk_hi[EE];
__device__ uint32_t s_wv_hi[EE];
__device__ uint32_t s_wo_hi[EE];
__device__ uint32_t s_q_hi[ME];
__device__ uint32_t s_k_hi[ME];
__device__ uint32_t s_vt_hi[ME];   // [bh][d][s]
__device__ uint32_t s_o_hi[ME];

// ===================== helpers =====================
__device__ __forceinline__ uint32_t smem_u32(const void* p) {
    uint32_t a;
    asm("{ .reg .u64 t; cvta.to.shared.u64 t, %1; cvt.u32.u64 %0, t; }" : "=r"(a) : "l"(p));
    return a;
}
__device__ __forceinline__ uint32_t cvt_tf32(float f) {
    uint32_t u;
    asm("cvt.rna.tf32.f32 %0, %1;" : "=r"(u) : "f"(f));
    return u;
}
__device__ __forceinline__ uint4 hi4(float4 v) {
    uint4 h;
    h.x = cvt_tf32(v.x); h.y = cvt_tf32(v.y);
    h.z = cvt_tf32(v.z); h.w = cvt_tf32(v.w);
    return h;
}

#define CP16(dst, src) \
    asm volatile("cp.async.cg.shared.global [%0], [%1], 16;" :: "r"(dst), "l"(src))
#define CPCOMMIT() asm volatile("cp.async.commit_group;" ::: "memory")
#define CPWAIT1()  asm volatile("cp.async.wait_group 1;" ::: "memory")

#define LDSM_X4(r0, r1, r2, r3, addr)                                          \
    asm volatile("ldmatrix.sync.aligned.m8n8.x4.shared.b16 {%0,%1,%2,%3}, [%4];" \
                 : "=r"(r0), "=r"(r1), "=r"(r2), "=r"(r3) : "r"(addr))
#define LDSM_X2(r0, r1, addr)                                                  \
    asm volatile("ldmatrix.sync.aligned.m8n8.x2.shared.b16 {%0,%1}, [%2];"     \
                 : "=r"(r0), "=r"(r1) : "r"(addr))

#define MMA_TF32(d, A, b0v, b1v)                                               \
    asm volatile("mma.sync.aligned.m16n8k8.row.col.f32.tf32.tf32.f32 "         \
                 "{%0,%1,%2,%3}, {%4,%5,%6,%7}, {%8,%9}, {%0,%1,%2,%3};"       \
                 : "+f"((d)[0]), "+f"((d)[1]), "+f"((d)[2]), "+f"((d)[3])      \
                 : "r"((A)[0]), "r"((A)[1]), "r"((A)[2]), "r"((A)[3]),         \
                   "r"(b0v), "r"(b1v))

#define STS64(addr, v0, v1) \
    asm volatile("st.shared.v2.f32 [%0], {%1,%2};" :: "r"(addr), "f"(v0), "f"(v1))
#define BARP(id) asm volatile("bar.sync %0, 64;" :: "r"(id) : "memory")

// ===================== fused pre-split kernels (hi only) =====================
__global__ __launch_bounds__(256) void split_me_kernel(
    const float4* __restrict__ q, const float4* __restrict__ k, const float4* __restrict__ v)
{
    const int t = blockIdx.y;
    const float4* src = (t == 0) ? q : ((t == 1) ? k : v);
    uint4* hi = (t == 0) ? (uint4*)s_xq_hi : ((t == 1) ? (uint4*)s_xk_hi : (uint4*)s_xv_hi);
    int i = blockIdx.x * 256 + threadIdx.x;
    hi[i] = hi4(src[i]);
}
__global__ __launch_bounds__(256) void split_w_kernel(
    const float4* __restrict__ wq, const float4* __restrict__ wk,
    const float4* __restrict__ wv, const float4* __restrict__ wo)
{
    const int t = blockIdx.y;
    const float4* src = (t == 0) ? wq : ((t == 1) ? wk : ((t == 2) ? wv : wo));
    uint4* hi = (t == 0) ? (uint4*)s_wq_hi : ((t == 1) ? (uint4*)s_wk_hi
              : ((t == 2) ? (uint4*)s_wv_hi : (uint4*)s_wo_hi));
    int i = blockIdx.x * 256 + threadIdx.x;
    hi[i] = hi4(src[i]);
}

// ===================== GEMM: Y = Xhi @ Whi^T + b (pure tf32, 1 MMA) =====================
// CTA 128x128, 8 warps (2m x 4n), K chunk 16, 2-stage cp.async.
// smem stage: Ahi 10240 | Bhi 10240.
#define NCHUNK   (E_DIM / 16)
#define ROWB     80
#define AHI_OFF  0u
#define BHI_OFF  10240u
#define STAGE_B  20480u
#define GEMM_SMEM (2 * 20480)

__global__ __launch_bounds__(256, 2) void gemm_tc_kernel(
    const float* __restrict__ bq, const float* __restrict__ bk,
    const float* __restrict__ bv, const float* __restrict__ bo,
    float* __restrict__ out, int is_out)
{
    extern __shared__ char smem[];
    const int z = blockIdx.z;
    const uint32_t *Xhi, *Whi;
    const float* Bv;
    int mode;
    if (is_out) { Xhi = s_o_hi;  Whi = s_wo_hi; Bv = bo; mode = 3; }
    else if (z == 0) { Xhi = s_xq_hi; Whi = s_wq_hi; Bv = bq; mode = 0; }
    else if (z == 1) { Xhi = s_xk_hi; Whi = s_wk_hi; Bv = bk; mode = 1; }
    else             { Xhi = s_xv_hi; Whi = s_wv_hi; Bv = bv; mode = 2; }

    const int tid  = threadIdx.x;
    const int lane = tid & 31;
    const int wid  = tid >> 5;
    const int wm   = wid >> 2;
    const int wn   = wid & 3;
    const int m0 = blockIdx.y * 128;
    const int n0 = blockIdx.x * 128;

    const uint32_t sb = smem_u32(smem);

    const int prow = tid >> 2;
    const int pc4  = tid & 3;
    const size_t xoff = (size_t)(m0 + prow) * E_DIM + pc4 * 4;
    const size_t woff = (size_t)(n0 + prow) * E_DIM + pc4 * 4;
    const uint32_t pd = (uint32_t)prow * ROWB + (uint32_t)pc4 * 16;

    #define GCP_CHUNK(c, st) do {                                              \
        uint32_t base_ = sb + (uint32_t)(st) * STAGE_B + pd;                   \
        size_t ko_ = (size_t)(c) * 16;                                         \
        _Pragma("unroll")                                                      \
        for (int r = 0; r < 2; ++r) {                                          \
            size_t sx_ = xoff + (size_t)r * 64 * E_DIM + ko_;                  \
            size_t sw_ = woff + (size_t)r * 64 * E_DIM + ko_;                  \
            uint32_t dd_ = base_ + (uint32_t)r * 5120;                         \
            CP16(dd_ + AHI_OFF, Xhi + sx_);                                    \
            CP16(dd_ + BHI_OFF, Whi + sw_);                                    \
        }                                                                      \
    } while (0)

    GCP_CHUNK(0, 0); CPCOMMIT();
    GCP_CHUNK(1, 1); CPCOMMIT();

    const int i4 = lane >> 3, r8 = lane & 7;
    const uint32_t a_off = (uint32_t)(wm * 64 + ((i4 & 1) << 3) + r8) * ROWB
                         + (uint32_t)((i4 >> 1) << 4);
    const uint32_t b_off = (uint32_t)(wn * 32 + r8) * ROWB
                         + (uint32_t)((i4 & 1) << 4);

    float acc[4][4][4];
#pragma unroll
    for (int mt = 0; mt < 4; ++mt)
#pragma unroll
        for (int nt = 0; nt < 4; ++nt)
#pragma unroll
            for (int r = 0; r < 4; ++r) acc[mt][nt][r] = 0.f;

    for (int c = 0; c < NCHUNK; ++c) {
        CPWAIT1();
        __syncthreads();
        const uint32_t stb = sb + (uint32_t)(c & 1) * STAGE_B;

#pragma unroll
        for (int ks = 0; ks < 2; ++ks) {
            uint32_t bhv[4][2];
#pragma unroll
            for (int nt = 0; nt < 4; ++nt) {
                const uint32_t ba = stb + b_off + nt * (8 * ROWB) + ks * 32;
                LDSM_X2(bhv[nt][0], bhv[nt][1], ba + BHI_OFF);
            }
#pragma unroll
            for (int mt = 0; mt < 4; ++mt) {
                const uint32_t aa = stb + a_off + mt * (16 * ROWB) + ks * 32;
                uint32_t ah[4];
                LDSM_X4(ah[0], ah[1], ah[2], ah[3], aa + AHI_OFF);
#pragma unroll
                for (int nt = 0; nt < 4; ++nt)
                    MMA_TF32(acc[mt][nt], ah, bhv[nt][0], bhv[nt][1]);
            }
        }

        __syncthreads();
        if (c + 2 < NCHUNK) GCP_CHUNK(c + 2, c & 1);
        CPCOMMIT();
    }

    if (mode == 3) {
#pragma unroll
        for (int nt = 0; nt < 4; ++nt) {
            const int col = n0 + wn * 32 + nt * 8 + 2 * (lane & 3);
            const float bx = __ldg(&Bv[col]);
            const float by = __ldg(&Bv[col + 1]);
#pragma unroll
            for (int mt = 0; mt < 4; ++mt) {
                const int r0i = m0 + wm * 64 + mt * 16 + (lane >> 2);
                *(float2*)&out[(size_t)r0i * E_DIM + col] =
                    make_float2(acc[mt][nt][0] + bx, acc[mt][nt][1] + by);
                *(float2*)&out[(size_t)(r0i + 8) * E_DIM + col] =
                    make_float2(acc[mt][nt][2] + bx, acc[mt][nt][3] + by);
            }
        }
    } else if (mode == 2) {
        // V^T epilogue: hi only
        const int bq2 = m0 >> 11;
#pragma unroll
        for (int nt = 0; nt < 4; ++nt) {
            const int col = n0 + wn * 32 + nt * 8 + 2 * (lane & 3);
            const int hh = col >> 6, dd = col & 63;
            const float bx = __ldg(&Bv[col]);
            const float by = __ldg(&Bv[col + 1]);
            const size_t b0i = ((size_t)(bq2 * 16 + hh) * 64 + dd) * S_LEN;
            const size_t b1i = b0i + S_LEN;
#pragma unroll
            for (int mt = 0; mt < 4; ++mt) {
                const int s = (m0 & 2047) + wm * 64 + mt * 16 + (lane >> 2);
                s_vt_hi[b0i + s]     = cvt_tf32(acc[mt][nt][0] + bx);
                s_vt_hi[b1i + s]     = cvt_tf32(acc[mt][nt][1] + by);
                s_vt_hi[b0i + s + 8] = cvt_tf32(acc[mt][nt][2] + bx);
                s_vt_hi[b1i + s + 8] = cvt_tf32(acc[mt][nt][3] + by);
            }
        }
    } else {
        // Q / K epilogue: hi only
        uint32_t* Yh = (mode == 0) ? s_q_hi : s_k_hi;
#pragma unroll
        for (int nt = 0; nt < 4; ++nt) {
            const int col = n0 + wn * 32 + nt * 8 + 2 * (lane & 3);
            const float bx = __ldg(&Bv[col]);
            const float by = __ldg(&Bv[col + 1]);
#pragma unroll
            for (int mt = 0; mt < 4; ++mt) {
                const int r0i = m0 + wm * 64 + mt * 16 + (lane >> 2);
                *(uint2*)&Yh[(size_t)r0i * E_DIM + col] =
                    make_uint2(cvt_tf32(acc[mt][nt][0] + bx), cvt_tf32(acc[mt][nt][1] + by));
                *(uint2*)&Yh[(size_t)(r0i + 8) * E_DIM + col] =
                    make_uint2(cvt_tf32(acc[mt][nt][2] + bx), cvt_tf32(acc[mt][nt][3] + by));
            }
        }
    }
}

// ===================== Causal flash attention (identical to R14) =====================
#define AQH   0u
#define AKB   32768u      // + stage*16384
#define AVB   65536u      // + stage*16384
#define APH   98304u      // + rg*8192
#define ARED  131072u
#define ATTN_SMEM 133120

__global__ __launch_bounds__(256) void attn_tc_kernel(void)
{
    extern __shared__ char smem[];
    const uint32_t sb = smem_u32(smem);
    float* red_m = (float*)(smem + ARED);          // [2][128]
    float* red_l = (float*)(smem + ARED + 1024);   // [2][128]

    const int tid = threadIdx.x, lane = tid & 31, w = tid >> 5;
    const int rg = w & 3, cn = w >> 2;
    const int i = (int)gridDim.x - 1 - (int)blockIdx.x;   // heavy tiles first
    const int bh = blockIdx.y;
    const int b = bh >> 4, h = bh & 15;

    const size_t qbase  = ((size_t)b * S_LEN + i * 128) * E_DIM + h * 64;
    const size_t kbase  = (size_t)b * S_LEN * E_DIM + h * 64;
    const size_t vtbase = (size_t)bh * 64 * S_LEN;

    // Q: 128 rows x 16 slots, hi only (group 0)
#pragma unroll
    for (int l = 0; l < 8; ++l) {
        int idx = tid + l * 256, row = idx >> 4, sl = idx & 15;
        uint32_t sw = (uint32_t)(row * 256 + ((sl ^ (row & 7)) << 4));
        CP16(sb + AQH + sw, s_q_hi + qbase + (size_t)row * E_DIM + sl * 4);
    }

    #define ISSUE_K(j_, st_) do {                                              \
        uint32_t kb_ = sb + AKB + (uint32_t)(st_) * 16384u;                    \
        _Pragma("unroll")                                                      \
        for (int l = 0; l < 4; ++l) {                                          \
            int idx_ = tid + l * 256, row_ = idx_ >> 4, sl_ = idx_ & 15;       \
            uint32_t sw_ = (uint32_t)(row_ * 256 + ((sl_ ^ (row_ & 7)) << 4)); \
            CP16(kb_ + sw_, s_k_hi + kbase + (size_t)((j_) * 64 + row_) * E_DIM + sl_ * 4); \
        }                                                                      \
    } while (0)

    #define ISSUE_VT(j_, st_) do {                                             \
        uint32_t vb_ = sb + AVB + (uint32_t)(st_) * 16384u;                    \
        _Pragma("unroll")                                                      \
        for (int l = 0; l < 4; ++l) {                                          \
            int idx_ = tid + l * 256, row_ = idx_ >> 4, sl_ = idx_ & 15;       \
            uint32_t sw_ = (uint32_t)(row_ * 256 + ((sl_ ^ (row_ & 7)) << 4)); \
            CP16(vb_ + sw_, s_vt_hi + vtbase + (size_t)row_ * S_LEN + (j_) * 64 + sl_ * 4); \
        }                                                                      \
    } while (0)

    const int jmax = 2 * i + 1;

    ISSUE_K(0, 0);
    ISSUE_VT(0, 0);
    CPCOMMIT();                 // G0: Q + K0 + VT0
    ISSUE_K(1, 1);
    ISSUE_VT(1, 1);
    CPCOMMIT();                 // G1: K1 + VT1

    const int i4 = lane >> 3, r8 = lane & 7;
    const int lr = lane >> 2;
    const int lc0 = 2 * (lane & 3);
    const int arow = ((i4 & 1) << 3) + r8;
    const int aslot_hi = i4 >> 1;
    const int pslot_lo = (lane & 3) >> 1;
    const uint32_t pword = (uint32_t)((lane & 1) << 3);
    const uint32_t pgbase_h = sb + APH + (uint32_t)rg * 8192;
    const int brow_off = ((i4 >> 1) << 3) + r8;
    const int bslot_lo = i4 & 1;

    float m_prev[2][2], lsum[2][2];
#pragma unroll
    for (int mt = 0; mt < 2; ++mt)
#pragma unroll
        for (int h2 = 0; h2 < 2; ++h2) { m_prev[mt][h2] = -INFINITY; lsum[mt][h2] = 0.f; }
    float o[2][4][4];
#pragma unroll
    for (int mt = 0; mt < 2; ++mt)
#pragma unroll
        for (int nt = 0; nt < 4; ++nt)
#pragma unroll
            for (int r = 0; r < 4; ++r) o[mt][nt][r] = 0.f;

    for (int j = 0; j <= jmax; ++j) {
        CPWAIT1();              // group j resident
        __syncthreads();
        const uint32_t kb  = sb + AKB + (uint32_t)(j & 1) * 16384u;
        const uint32_t vtb = sb + AVB + (uint32_t)(j & 1) * 16384u;

        // ---- S = Qhi * Khi ----
        float sacc[2][4][4];
#pragma unroll
        for (int mt = 0; mt < 2; ++mt)
#pragma unroll
            for (int nt = 0; nt < 4; ++nt)
#pragma unroll
                for (int r = 0; r < 4; ++r) sacc[mt][nt][r] = 0.f;

#pragma unroll
        for (int ks = 0; ks < 8; ++ks) {
            uint32_t khv[4][2];
#pragma unroll
            for (int nt2 = 0; nt2 < 2; ++nt2) {
                const int brow = cn * 32 + nt2 * 16 + brow_off;
                const uint32_t boff = (uint32_t)(brow * 256
                    + ((((ks << 1) | bslot_lo) ^ (brow & 7)) << 4));
                LDSM_X4(khv[nt2 * 2][0], khv[nt2 * 2][1],
                        khv[nt2 * 2 + 1][0], khv[nt2 * 2 + 1][1], kb + boff);
            }
#pragma unroll
            for (int mt = 0; mt < 2; ++mt) {
                const int qrow = rg * 32 + mt * 16 + arow;
                const uint32_t aoff = (uint32_t)(qrow * 256
                    + ((((ks << 1) | aslot_hi) ^ (qrow & 7)) << 4));
                uint32_t ah[4];
                LDSM_X4(ah[0], ah[1], ah[2], ah[3], sb + AQH + aoff);
#pragma unroll
                for (int nt = 0; nt < 4; ++nt)
                    MMA_TF32(sacc[mt][nt], ah, khv[nt][0], khv[nt][1]);
            }
        }

        // ---- mask + softmax ----
        float mloc[2][2] = {{-INFINITY, -INFINITY}, {-INFINITY, -INFINITY}};
#pragma unroll
        for (int mt = 0; mt < 2; ++mt) {
            const int qr0 = i * 128 + rg * 32 + mt * 16 + lr;
#pragma unroll
            for (int nt = 0; nt < 4; ++nt) {
                const int c0 = j * 64 + cn * 32 + (nt << 3) + lc0;
                float s0 = sacc[mt][nt][0] * 0.125f, s1 = sacc[mt][nt][1] * 0.125f;
                float s2 = sacc[mt][nt][2] * 0.125f, s3 = sacc[mt][nt][3] * 0.125f;
                if (c0     > qr0)     s0 = -INFINITY;
                if (c0 + 1 > qr0)     s1 = -INFINITY;
                if (c0     > qr0 + 8) s2 = -INFINITY;
                if (c0 + 1 > qr0 + 8) s3 = -INFINITY;
                sacc[mt][nt][0] = s0; sacc[mt][nt][1] = s1;
                sacc[mt][nt][2] = s2; sacc[mt][nt][3] = s3;
                mloc[mt][0] = fmaxf(mloc[mt][0], fmaxf(s0, s1));
                mloc[mt][1] = fmaxf(mloc[mt][1], fmaxf(s2, s3));
            }
#pragma unroll
            for (int h2 = 0; h2 < 2; ++h2) {
                mloc[mt][h2] = fmaxf(mloc[mt][h2], __shfl_xor_sync(0xffffffffu, mloc[mt][h2], 1));
                mloc[mt][h2] = fmaxf(mloc[mt][h2], __shfl_xor_sync(0xffffffffu, mloc[mt][h2], 2));
            }
        }
        if ((lane & 3) == 0) {
#pragma unroll
            for (int mt = 0; mt < 2; ++mt) {
                red_m[cn * 128 + rg * 32 + mt * 16 + lr]     = mloc[mt][0];
                red_m[cn * 128 + rg * 32 + mt * 16 + lr + 8] = mloc[mt][1];
            }
        }
        BARP(rg + 1);

        float fac[2][2], m_new[2][2];
#pragma unroll
        for (int mt = 0; mt < 2; ++mt)
#pragma unroll
            for (int h2 = 0; h2 < 2; ++h2) {
                const int row = rg * 32 + mt * 16 + lr + h2 * 8;
                const float mo = red_m[(cn ^ 1) * 128 + row];
                m_new[mt][h2] = fmaxf(m_prev[mt][h2], fmaxf(mloc[mt][h2], mo));
                fac[mt][h2] = (m_prev[mt][h2] == -INFINITY)
                            ? 0.f : __expf(m_prev[mt][h2] - m_new[mt][h2]);
                m_prev[mt][h2] = m_new[mt][h2];
            }

        // P rounded to tf32; denominator accumulated from the ROUNDED values.
        float ls[2][2] = {{0.f, 0.f}, {0.f, 0.f}};
#pragma unroll
        for (int mt = 0; mt < 2; ++mt) {
            const int rA = mt * 16 + lr, rB = rA + 8;
            const uint32_t rowA_h = pgbase_h + rA * 256, rowB_h = pgbase_h + rB * 256;
#pragma unroll
            for (int nt = 0; nt < 4; ++nt) {
                const uint32_t h0 = cvt_tf32(__expf(sacc[mt][nt][0] - m_new[mt][0]));
                const uint32_t h1 = cvt_tf32(__expf(sacc[mt][nt][1] - m_new[mt][0]));
                const uint32_t h2v = cvt_tf32(__expf(sacc[mt][nt][2] - m_new[mt][1]));
                const uint32_t h3 = cvt_tf32(__expf(sacc[mt][nt][3] - m_new[mt][1]));
                ls[mt][0] += __uint_as_float(h0) + __uint_as_float(h1);
                ls[mt][1] += __uint_as_float(h2v) + __uint_as_float(h3);
                const uint32_t slot = (uint32_t)((cn << 3) | (nt << 1) | pslot_lo);
                STS64(rowA_h + ((slot ^ (rA & 7)) << 4) + pword,
                      __uint_as_float(h0), __uint_as_float(h1));
                STS64(rowB_h + ((slot ^ (rB & 7)) << 4) + pword,
                      __uint_as_float(h2v), __uint_as_float(h3));
            }
#pragma unroll
            for (int h2 = 0; h2 < 2; ++h2) {
                ls[mt][h2] += __shfl_xor_sync(0xffffffffu, ls[mt][h2], 1);
                ls[mt][h2] += __shfl_xor_sync(0xffffffffu, ls[mt][h2], 2);
            }
        }
        if ((lane & 3) == 0) {
#pragma unroll
            for (int mt = 0; mt < 2; ++mt) {
                red_l[cn * 128 + rg * 32 + mt * 16 + lr]     = ls[mt][0];
                red_l[cn * 128 + rg * 32 + mt * 16 + lr + 8] = ls[mt][1];
            }
        }
        BARP(rg + 1);   // publishes red_l AND the pair's P tiles
#pragma unroll
        for (int mt = 0; mt < 2; ++mt)
#pragma unroll
            for (int h2 = 0; h2 < 2; ++h2) {
                const int row = rg * 32 + mt * 16 + lr + h2 * 8;
                lsum[mt][h2] = lsum[mt][h2] * fac[mt][h2] + red_l[row] + red_l[128 + row];
            }

#pragma unroll
        for (int mt = 0; mt < 2; ++mt)
#pragma unroll
            for (int nt = 0; nt < 4; ++nt) {
                o[mt][nt][0] *= fac[mt][0]; o[mt][nt][1] *= fac[mt][0];
                o[mt][nt][2] *= fac[mt][1]; o[mt][nt][3] *= fac[mt][1];
            }

        // ---- O += Phat * Vhi (1 MMA) ----
#pragma unroll
        for (int ks = 0; ks < 8; ++ks) {
            uint32_t vhv[4][2];
#pragma unroll
            for (int nt2 = 0; nt2 < 2; ++nt2) {
                const int vrow = cn * 32 + nt2 * 16 + brow_off;
                const uint32_t voff = (uint32_t)(vrow * 256
                    + ((((ks << 1) | bslot_lo) ^ (vrow & 7)) << 4));
                LDSM_X4(vhv[nt2 * 2][0], vhv[nt2 * 2][1],
                        vhv[nt2 * 2 + 1][0], vhv[nt2 * 2 + 1][1], vtb + voff);
            }
#pragma unroll
            for (int mt = 0; mt < 2; ++mt) {
                const int prow_ = mt * 16 + arow;
                const uint32_t poff = (uint32_t)(prow_ * 256
                    + ((((ks << 1) | aslot_hi) ^ (prow_ & 7)) << 4));
                uint32_t ph[4];
                LDSM_X4(ph[0], ph[1], ph[2], ph[3], pgbase_h + poff);
#pragma unroll
                for (int nt = 0; nt < 4; ++nt)
                    MMA_TF32(o[mt][nt], ph, vhv[nt][0], vhv[nt][1]);
            }
        }

        __syncthreads();   // all reads of stage (j&1) done before refill
        if (j + 2 <= jmax) {
            ISSUE_K(j + 2, j & 1);
            ISSUE_VT(j + 2, j & 1);
        }
        CPCOMMIT();        // one group per iteration keeps wait_group counts aligned
    }

    // ---- epilogue: O hi only ----
#pragma unroll
    for (int mt = 0; mt < 2; ++mt) {
        const float inv0 = 1.f / lsum[mt][0];
        const float inv1 = 1.f / lsum[mt][1];
        const size_t rowA = ((size_t)b * S_LEN + i * 128 + rg * 32 + mt * 16 + lr) * E_DIM;
        const size_t rowB = rowA + (size_t)8 * E_DIM;
#pragma unroll
        for (int nt = 0; nt < 4; ++nt) {
            const int col = h * 64 + cn * 32 + (nt << 3) + lc0;
            *(uint2*)&s_o_hi[rowA + col] =
                make_uint2(cvt_tf32(o[mt][nt][0] * inv0), cvt_tf32(o[mt][nt][1] * inv0));
            *(uint2*)&s_o_hi[rowB + col] =
                make_uint2(cvt_tf32(o[mt][nt][2] * inv1), cvt_tf32(o[mt][nt][3] * inv1));
        }
    }
}

// ===================== launch =====================
extern "C" void kernel_launch(void* const* d_in, const int* in_sizes, int n_in,
                              void* d_out, int out_size)
{
    (void)in_sizes; (void)n_in; (void)out_size;
    const float* q  = (const float*)d_in[0];
    const float* k  = (const float*)d_in[1];
    const float* v  = (const float*)d_in[2];
    const float* Wq = (const float*)d_in[3];
    const float* bq = (const float*)d_in[4];
    const float* Wk = (const float*)d_in[5];
    const float* bk = (const float*)d_in[6];
    const float* Wv = (const float*)d_in[7];
    const float* bv = (const float*)d_in[8];
    const float* Wo = (const float*)d_in[9];
    const float* bo = (const float*)d_in[10];
    float* out = (float*)d_out;

    cudaFuncSetAttribute(gemm_tc_kernel, cudaFuncAttributeMaxDynamicSharedMemorySize, GEMM_SMEM);
    cudaFuncSetAttribute(attn_tc_kernel, cudaFuncAttributeMaxDynamicSharedMemorySize, ATTN_SMEM);

    // fused pre-split (2 launches; everything hi-only)
    dim3 gridSM((unsigned)(ME / 4 / 256), 3);
    split_me_kernel<<<gridSM, 256>>>((const float4*)q, (const float4*)k, (const float4*)v);
    dim3 gridSW((unsigned)(EE / 4 / 256), 4);
    split_w_kernel<<<gridSW, 256>>>((const float4*)Wq, (const float4*)Wk,
                                    (const float4*)Wv, (const float4*)Wo);

    // Q/K/V projections (epilogues emit attention operands, all hi-only)
    dim3 gridP(E_DIM / 128, M_ROWS / 128, 3);
    gemm_tc_kernel<<<gridP, 256, GEMM_SMEM>>>(bq, bk, bv, bo, out, 0);

    // causal flash attention, 128-row q-tiles (emits O hi)
    dim3 gridA(S_LEN / 128, N_BATCH * N_HEADS);
    attn_tc_kernel<<<gridA, 256, ATTN_SMEM>>>();

    // output projection
    dim3 gridO(E_DIM / 128, M_ROWS / 128, 1);
    gemm_tc_kernel<<<gridO, 256, GEMM_SMEM>>>(bq, bk, bv, bo, out, 1);
}

// round 16
// speedup vs baseline: 2.4513x; 1.0187x over previous
#include <cuda_runtime.h>
#include <math.h>
#include <stdint.h>

#define E_DIM   1024
#define S_LEN   2048
#define N_BATCH 2
#define N_HEADS 16
#define H_DIM   64
#define M_ROWS  (N_BATCH * S_LEN)   // 4096
#define ME      ((size_t)M_ROWS * E_DIM)   // 4M elems
#define EE      ((size_t)E_DIM * E_DIM)    // 1M elems

// ---------- global scratch (allocation-free) ----------
// Everything tf32-hi only (pure-tf32 pipeline, error budget calibrated R12-R15).
__device__ uint32_t s_xq_hi[ME];
__device__ uint32_t s_xk_hi[ME];
__device__ uint32_t s_xv_hi[ME];
__device__ uint32_t s_wq_hi[EE];
__device__ uint32_t s_wk_hi[EE];
__device__ uint32_t s_wv_hi[EE];
__device__ uint32_t s_wo_hi[EE];
__device__ uint32_t s_q_hi[ME];
__device__ uint32_t s_k_hi[ME];
__device__ uint32_t s_vt_hi[ME];   // [bh][d][s]
__device__ uint32_t s_o_hi[ME];

// ===================== helpers =====================
__device__ __forceinline__ uint32_t smem_u32(const void* p) {
    uint32_t a;
    asm("{ .reg .u64 t; cvta.to.shared.u64 t, %1; cvt.u32.u64 %0, t; }" : "=r"(a) : "l"(p));
    return a;
}
__device__ __forceinline__ uint32_t cvt_tf32(float f) {
    uint32_t u;
    asm("cvt.rna.tf32.f32 %0, %1;" : "=r"(u) : "f"(f));
    return u;
}
__device__ __forceinline__ uint4 hi4(float4 v) {
    uint4 h;
    h.x = cvt_tf32(v.x); h.y = cvt_tf32(v.y);
    h.z = cvt_tf32(v.z); h.w = cvt_tf32(v.w);
    return h;
}

#define CP16(dst, src) \
    asm volatile("cp.async.cg.shared.global [%0], [%1], 16;" :: "r"(dst), "l"(src))
#define CPCOMMIT() asm volatile("cp.async.commit_group;" ::: "memory")
#define CPWAIT1()  asm volatile("cp.async.wait_group 1;" ::: "memory")
#define CPWAIT0()  asm volatile("cp.async.wait_group 0;" ::: "memory")

#define LDSM_X4(r0, r1, r2, r3, addr)                                          \
    asm volatile("ldmatrix.sync.aligned.m8n8.x4.shared.b16 {%0,%1,%2,%3}, [%4];" \
                 : "=r"(r0), "=r"(r1), "=r"(r2), "=r"(r3) : "r"(addr))
#define LDSM_X2(r0, r1, addr)                                                  \
    asm volatile("ldmatrix.sync.aligned.m8n8.x2.shared.b16 {%0,%1}, [%2];"     \
                 : "=r"(r0), "=r"(r1) : "r"(addr))

#define MMA_TF32(d, A, b0v, b1v)                                               \
    asm volatile("mma.sync.aligned.m16n8k8.row.col.f32.tf32.tf32.f32 "         \
                 "{%0,%1,%2,%3}, {%4,%5,%6,%7}, {%8,%9}, {%0,%1,%2,%3};"       \
                 : "+f"((d)[0]), "+f"((d)[1]), "+f"((d)[2]), "+f"((d)[3])      \
                 : "r"((A)[0]), "r"((A)[1]), "r"((A)[2]), "r"((A)[3]),         \
                   "r"(b0v), "r"(b1v))

#define STS64(addr, v0, v1) \
    asm volatile("st.shared.v2.f32 [%0], {%1,%2};" :: "r"(addr), "f"(v0), "f"(v1))
#define BARP(id) asm volatile("bar.sync %0, 64;" :: "r"(id) : "memory")

// ===================== fused pre-split kernels (hi only) =====================
__global__ __launch_bounds__(256) void split_me_kernel(
    const float4* __restrict__ q, const float4* __restrict__ k, const float4* __restrict__ v)
{
    const int t = blockIdx.y;
    const float4* src = (t == 0) ? q : ((t == 1) ? k : v);
    uint4* hi = (t == 0) ? (uint4*)s_xq_hi : ((t == 1) ? (uint4*)s_xk_hi : (uint4*)s_xv_hi);
    int i = blockIdx.x * 256 + threadIdx.x;
    hi[i] = hi4(src[i]);
}
__global__ __launch_bounds__(256) void split_w_kernel(
    const float4* __restrict__ wq, const float4* __restrict__ wk,
    const float4* __restrict__ wv, const float4* __restrict__ wo)
{
    const int t = blockIdx.y;
    const float4* src = (t == 0) ? wq : ((t == 1) ? wk : ((t == 2) ? wv : wo));
    uint4* hi = (t == 0) ? (uint4*)s_wq_hi : ((t == 1) ? (uint4*)s_wk_hi
              : ((t == 2) ? (uint4*)s_wv_hi : (uint4*)s_wo_hi));
    int i = blockIdx.x * 256 + threadIdx.x;
    hi[i] = hi4(src[i]);
}

// ===================== GEMM: Y = Xhi @ Whi^T + b (pure tf32, identical to R15) =====================
#define NCHUNK   (E_DIM / 16)
#define ROWB     80
#define AHI_OFF  0u
#define BHI_OFF  10240u
#define STAGE_B  20480u
#define GEMM_SMEM (2 * 20480)

__global__ __launch_bounds__(256, 2) void gemm_tc_kernel(
    const float* __restrict__ bq, const float* __restrict__ bk,
    const float* __restrict__ bv, const float* __restrict__ bo,
    float* __restrict__ out, int is_out)
{
    extern __shared__ char smem[];
    const int z = blockIdx.z;
    const uint32_t *Xhi, *Whi;
    const float* Bv;
    int mode;
    if (is_out) { Xhi = s_o_hi;  Whi = s_wo_hi; Bv = bo; mode = 3; }
    else if (z == 0) { Xhi = s_xq_hi; Whi = s_wq_hi; Bv = bq; mode = 0; }
    else if (z == 1) { Xhi = s_xk_hi; Whi = s_wk_hi; Bv = bk; mode = 1; }
    else             { Xhi = s_xv_hi; Whi = s_wv_hi; Bv = bv; mode = 2; }

    const int tid  = threadIdx.x;
    const int lane = tid & 31;
    const int wid  = tid >> 5;
    const int wm   = wid >> 2;
    const int wn   = wid & 3;
    const int m0 = blockIdx.y * 128;
    const int n0 = blockIdx.x * 128;

    const uint32_t sb = smem_u32(smem);

    const int prow = tid >> 2;
    const int pc4  = tid & 3;
    const size_t xoff = (size_t)(m0 + prow) * E_DIM + pc4 * 4;
    const size_t woff = (size_t)(n0 + prow) * E_DIM + pc4 * 4;
    const uint32_t pd = (uint32_t)prow * ROWB + (uint32_t)pc4 * 16;

    #define GCP_CHUNK(c, st) do {                                              \
        uint32_t base_ = sb + (uint32_t)(st) * STAGE_B + pd;                   \
        size_t ko_ = (size_t)(c) * 16;                                         \
        _Pragma("unroll")                                                      \
        for (int r = 0; r < 2; ++r) {                                          \
            size_t sx_ = xoff + (size_t)r * 64 * E_DIM + ko_;                  \
            size_t sw_ = woff + (size_t)r * 64 * E_DIM + ko_;                  \
            uint32_t dd_ = base_ + (uint32_t)r * 5120;                         \
            CP16(dd_ + AHI_OFF, Xhi + sx_);                                    \
            CP16(dd_ + BHI_OFF, Whi + sw_);                                    \
        }                                                                      \
    } while (0)

    GCP_CHUNK(0, 0); CPCOMMIT();
    GCP_CHUNK(1, 1); CPCOMMIT();

    const int i4 = lane >> 3, r8 = lane & 7;
    const uint32_t a_off = (uint32_t)(wm * 64 + ((i4 & 1) << 3) + r8) * ROWB
                         + (uint32_t)((i4 >> 1) << 4);
    const uint32_t b_off = (uint32_t)(wn * 32 + r8) * ROWB
                         + (uint32_t)((i4 & 1) << 4);

    float acc[4][4][4];
#pragma unroll
    for (int mt = 0; mt < 4; ++mt)
#pragma unroll
        for (int nt = 0; nt < 4; ++nt)
#pragma unroll
            for (int r = 0; r < 4; ++r) acc[mt][nt][r] = 0.f;

    for (int c = 0; c < NCHUNK; ++c) {
        CPWAIT1();
        __syncthreads();
        const uint32_t stb = sb + (uint32_t)(c & 1) * STAGE_B;

#pragma unroll
        for (int ks = 0; ks < 2; ++ks) {
            uint32_t bhv[4][2];
#pragma unroll
            for (int nt = 0; nt < 4; ++nt) {
                const uint32_t ba = stb + b_off + nt * (8 * ROWB) + ks * 32;
                LDSM_X2(bhv[nt][0], bhv[nt][1], ba + BHI_OFF);
            }
#pragma unroll
            for (int mt = 0; mt < 4; ++mt) {
                const uint32_t aa = stb + a_off + mt * (16 * ROWB) + ks * 32;
                uint32_t ah[4];
                LDSM_X4(ah[0], ah[1], ah[2], ah[3], aa + AHI_OFF);
#pragma unroll
                for (int nt = 0; nt < 4; ++nt)
                    MMA_TF32(acc[mt][nt], ah, bhv[nt][0], bhv[nt][1]);
            }
        }

        __syncthreads();
        if (c + 2 < NCHUNK) GCP_CHUNK(c + 2, c & 1);
        CPCOMMIT();
    }

    if (mode == 3) {
#pragma unroll
        for (int nt = 0; nt < 4; ++nt) {
            const int col = n0 + wn * 32 + nt * 8 + 2 * (lane & 3);
            const float bx = __ldg(&Bv[col]);
            const float by = __ldg(&Bv[col + 1]);
#pragma unroll
            for (int mt = 0; mt < 4; ++mt) {
                const int r0i = m0 + wm * 64 + mt * 16 + (lane >> 2);
                *(float2*)&out[(size_t)r0i * E_DIM + col] =
                    make_float2(acc[mt][nt][0] + bx, acc[mt][nt][1] + by);
                *(float2*)&out[(size_t)(r0i + 8) * E_DIM + col] =
                    make_float2(acc[mt][nt][2] + bx, acc[mt][nt][3] + by);
            }
        }
    } else if (mode == 2) {
        // V^T epilogue: hi only
        const int bq2 = m0 >> 11;
#pragma unroll
        for (int nt = 0; nt < 4; ++nt) {
            const int col = n0 + wn * 32 + nt * 8 + 2 * (lane & 3);
            const int hh = col >> 6, dd = col & 63;
            const float bx = __ldg(&Bv[col]);
            const float by = __ldg(&Bv[col + 1]);
            const size_t b0i = ((size_t)(bq2 * 16 + hh) * 64 + dd) * S_LEN;
            const size_t b1i = b0i + S_LEN;
#pragma unroll
            for (int mt = 0; mt < 4; ++mt) {
                const int s = (m0 & 2047) + wm * 64 + mt * 16 + (lane >> 2);
                s_vt_hi[b0i + s]     = cvt_tf32(acc[mt][nt][0] + bx);
                s_vt_hi[b1i + s]     = cvt_tf32(acc[mt][nt][1] + by);
                s_vt_hi[b0i + s + 8] = cvt_tf32(acc[mt][nt][2] + bx);
                s_vt_hi[b1i + s + 8] = cvt_tf32(acc[mt][nt][3] + by);
            }
        }
    } else {
        // Q / K epilogue: hi only
        uint32_t* Yh = (mode == 0) ? s_q_hi : s_k_hi;
#pragma unroll
        for (int nt = 0; nt < 4; ++nt) {
            const int col = n0 + wn * 32 + nt * 8 + 2 * (lane & 3);
            const float bx = __ldg(&Bv[col]);
            const float by = __ldg(&Bv[col + 1]);
#pragma unroll
            for (int mt = 0; mt < 4; ++mt) {
                const int r0i = m0 + wm * 64 + mt * 16 + (lane >> 2);
                *(uint2*)&Yh[(size_t)r0i * E_DIM + col] =
                    make_uint2(cvt_tf32(acc[mt][nt][0] + bx), cvt_tf32(acc[mt][nt][1] + by));
                *(uint2*)&Yh[(size_t)(r0i + 8) * E_DIM + col] =
                    make_uint2(cvt_tf32(acc[mt][nt][2] + bx), cvt_tf32(acc[mt][nt][3] + by));
            }
        }
    }
}

// ===================== Causal flash attention: 2 CTAs/SM =====================
// Same math as R14/R15. K and VT single-stage (loads for j+1 issued at iteration
// end, waited at top; the co-resident CTA hides the exposed latency).
// smem: Qhi 32K | K 16K | VT 16K | Phi 32K | red 2K = 100352; x2 CTAs = 196K.
#define AQH   0u
#define AKB   32768u
#define AVB   49152u
#define APH   65536u      // + rg*8192
#define ARED  98304u
#define ATTN_SMEM 100352

__global__ __launch_bounds__(256, 2) void attn_tc_kernel(void)
{
    extern __shared__ char smem[];
    const uint32_t sb = smem_u32(smem);
    float* red_m = (float*)(smem + ARED);          // [2][128]
    float* red_l = (float*)(smem + ARED + 1024);   // [2][128]

    const int tid = threadIdx.x, lane = tid & 31, w = tid >> 5;
    const int rg = w & 3, cn = w >> 2;
    const int i = (int)gridDim.x - 1 - (int)blockIdx.x;   // heavy tiles first
    const int bh = blockIdx.y;
    const int b = bh >> 4, h = bh & 15;

    const size_t qbase  = ((size_t)b * S_LEN + i * 128) * E_DIM + h * 64;
    const size_t kbase  = (size_t)b * S_LEN * E_DIM + h * 64;
    const size_t vtbase = (size_t)bh * 64 * S_LEN;

    // Q: 128 rows x 16 slots, hi only
#pragma unroll
    for (int l = 0; l < 8; ++l) {
        int idx = tid + l * 256, row = idx >> 4, sl = idx & 15;
        uint32_t sw = (uint32_t)(row * 256 + ((sl ^ (row & 7)) << 4));
        CP16(sb + AQH + sw, s_q_hi + qbase + (size_t)row * E_DIM + sl * 4);
    }

    #define ISSUE_K(j_) do {                                                   \
        _Pragma("unroll")                                                      \
        for (int l = 0; l < 4; ++l) {                                          \
            int idx_ = tid + l * 256, row_ = idx_ >> 4, sl_ = idx_ & 15;       \
            uint32_t sw_ = (uint32_t)(row_ * 256 + ((sl_ ^ (row_ & 7)) << 4)); \
            CP16(sb + AKB + sw_, s_k_hi + kbase + (size_t)((j_) * 64 + row_) * E_DIM + sl_ * 4); \
        }                                                                      \
    } while (0)

    #define ISSUE_VT(j_) do {                                                  \
        _Pragma("unroll")                                                      \
        for (int l = 0; l < 4; ++l) {                                          \
            int idx_ = tid + l * 256, row_ = idx_ >> 4, sl_ = idx_ & 15;       \
            uint32_t sw_ = (uint32_t)(row_ * 256 + ((sl_ ^ (row_ & 7)) << 4)); \
            CP16(sb + AVB + sw_, s_vt_hi + vtbase + (size_t)row_ * S_LEN + (j_) * 64 + sl_ * 4); \
        }                                                                      \
    } while (0)

    const int jmax = 2 * i + 1;

    ISSUE_K(0);
    ISSUE_VT(0);
    CPCOMMIT();                 // G0: Q + K0 + VT0

    const int i4 = lane >> 3, r8 = lane & 7;
    const int lr = lane >> 2;
    const int lc0 = 2 * (lane & 3);
    const int arow = ((i4 & 1) << 3) + r8;
    const int aslot_hi = i4 >> 1;
    const int pslot_lo = (lane & 3) >> 1;
    const uint32_t pword = (uint32_t)((lane & 1) << 3);
    const uint32_t pgbase_h = sb + APH + (uint32_t)rg * 8192;
    const int brow_off = ((i4 >> 1) << 3) + r8;
    const int bslot_lo = i4 & 1;

    float m_prev[2][2], lsum[2][2];
#pragma unroll
    for (int mt = 0; mt < 2; ++mt)
#pragma unroll
        for (int h2 = 0; h2 < 2; ++h2) { m_prev[mt][h2] = -INFINITY; lsum[mt][h2] = 0.f; }
    float o[2][4][4];
#pragma unroll
    for (int mt = 0; mt < 2; ++mt)
#pragma unroll
        for (int nt = 0; nt < 4; ++nt)
#pragma unroll
            for (int r = 0; r < 4; ++r) o[mt][nt][r] = 0.f;

    for (int j = 0; j <= jmax; ++j) {
        CPWAIT0();              // K(j), VT(j) resident (j=0 also covers Q)
        __syncthreads();

        // ---- S = Qhi * Khi ----
        float sacc[2][4][4];
#pragma unroll
        for (int mt = 0; mt < 2; ++mt)
#pragma unroll
            for (int nt = 0; nt < 4; ++nt)
#pragma unroll
                for (int r = 0; r < 4; ++r) sacc[mt][nt][r] = 0.f;

#pragma unroll
        for (int ks = 0; ks < 8; ++ks) {
            uint32_t khv[4][2];
#pragma unroll
            for (int nt2 = 0; nt2 < 2; ++nt2) {
                const int brow = cn * 32 + nt2 * 16 + brow_off;
                const uint32_t boff = (uint32_t)(brow * 256
                    + ((((ks << 1) | bslot_lo) ^ (brow & 7)) << 4));
                LDSM_X4(khv[nt2 * 2][0], khv[nt2 * 2][1],
                        khv[nt2 * 2 + 1][0], khv[nt2 * 2 + 1][1], sb + AKB + boff);
            }
#pragma unroll
            for (int mt = 0; mt < 2; ++mt) {
                const int qrow = rg * 32 + mt * 16 + arow;
                const uint32_t aoff = (uint32_t)(qrow * 256
                    + ((((ks << 1) | aslot_hi) ^ (qrow & 7)) << 4));
                uint32_t ah[4];
                LDSM_X4(ah[0], ah[1], ah[2], ah[3], sb + AQH + aoff);
#pragma unroll
                for (int nt = 0; nt < 4; ++nt)
                    MMA_TF32(sacc[mt][nt], ah, khv[nt][0], khv[nt][1]);
            }
        }

        // ---- mask + softmax ----
        float mloc[2][2] = {{-INFINITY, -INFINITY}, {-INFINITY, -INFINITY}};
#pragma unroll
        for (int mt = 0; mt < 2; ++mt) {
            const int qr0 = i * 128 + rg * 32 + mt * 16 + lr;
#pragma unroll
            for (int nt = 0; nt < 4; ++nt) {
                const int c0 = j * 64 + cn * 32 + (nt << 3) + lc0;
                float s0 = sacc[mt][nt][0] * 0.125f, s1 = sacc[mt][nt][1] * 0.125f;
                float s2 = sacc[mt][nt][2] * 0.125f, s3 = sacc[mt][nt][3] * 0.125f;
                if (c0     > qr0)     s0 = -INFINITY;
                if (c0 + 1 > qr0)     s1 = -INFINITY;
                if (c0     > qr0 + 8) s2 = -INFINITY;
                if (c0 + 1 > qr0 + 8) s3 = -INFINITY;
                sacc[mt][nt][0] = s0; sacc[mt][nt][1] = s1;
                sacc[mt][nt][2] = s2; sacc[mt][nt][3] = s3;
                mloc[mt][0] = fmaxf(mloc[mt][0], fmaxf(s0, s1));
                mloc[mt][1] = fmaxf(mloc[mt][1], fmaxf(s2, s3));
            }
#pragma unroll
            for (int h2 = 0; h2 < 2; ++h2) {
                mloc[mt][h2] = fmaxf(mloc[mt][h2], __shfl_xor_sync(0xffffffffu, mloc[mt][h2], 1));
                mloc[mt][h2] = fmaxf(mloc[mt][h2], __shfl_xor_sync(0xffffffffu, mloc[mt][h2], 2));
            }
        }
        if ((lane & 3) == 0) {
#pragma unroll
            for (int mt = 0; mt < 2; ++mt) {
                red_m[cn * 128 + rg * 32 + mt * 16 + lr]     = mloc[mt][0];
                red_m[cn * 128 + rg * 32 + mt * 16 + lr + 8] = mloc[mt][1];
            }
        }
        BARP(rg + 1);

        float fac[2][2], m_new[2][2];
#pragma unroll
        for (int mt = 0; mt < 2; ++mt)
#pragma unroll
            for (int h2 = 0; h2 < 2; ++h2) {
                const int row = rg * 32 + mt * 16 + lr + h2 * 8;
                const float mo = red_m[(cn ^ 1) * 128 + row];
                m_new[mt][h2] = fmaxf(m_prev[mt][h2], fmaxf(mloc[mt][h2], mo));
                fac[mt][h2] = (m_prev[mt][h2] == -INFINITY)
                            ? 0.f : __expf(m_prev[mt][h2] - m_new[mt][h2]);
                m_prev[mt][h2] = m_new[mt][h2];
            }

        // P rounded to tf32; denominator accumulated from the ROUNDED values.
        float ls[2][2] = {{0.f, 0.f}, {0.f, 0.f}};
#pragma unroll
        for (int mt = 0; mt < 2; ++mt) {
            const int rA = mt * 16 + lr, rB = rA + 8;
            const uint32_t rowA_h = pgbase_h + rA * 256, rowB_h = pgbase_h + rB * 256;
#pragma unroll
            for (int nt = 0; nt < 4; ++nt) {
                const uint32_t h0 = cvt_tf32(__expf(sacc[mt][nt][0] - m_new[mt][0]));
                const uint32_t h1 = cvt_tf32(__expf(sacc[mt][nt][1] - m_new[mt][0]));
                const uint32_t h2v = cvt_tf32(__expf(sacc[mt][nt][2] - m_new[mt][1]));
                const uint32_t h3 = cvt_tf32(__expf(sacc[mt][nt][3] - m_new[mt][1]));
                ls[mt][0] += __uint_as_float(h0) + __uint_as_float(h1);
                ls[mt][1] += __uint_as_float(h2v) + __uint_as_float(h3);
                const uint32_t slot = (uint32_t)((cn << 3) | (nt << 1) | pslot_lo);
                STS64(rowA_h + ((slot ^ (rA & 7)) << 4) + pword,
                      __uint_as_float(h0), __uint_as_float(h1));
                STS64(rowB_h + ((slot ^ (rB & 7)) << 4) + pword,
                      __uint_as_float(h2v), __uint_as_float(h3));
            }
#pragma unroll
            for (int h2 = 0; h2 < 2; ++h2) {
                ls[mt][h2] += __shfl_xor_sync(0xffffffffu, ls[mt][h2], 1);
                ls[mt][h2] += __shfl_xor_sync(0xffffffffu, ls[mt][h2], 2);
            }
        }
        if ((lane & 3) == 0) {
#pragma unroll
            for (int mt = 0; mt < 2; ++mt) {
                red_l[cn * 128 + rg * 32 + mt * 16 + lr]     = ls[mt][0];
                red_l[cn * 128 + rg * 32 + mt * 16 + lr + 8] = ls[mt][1];
            }
        }
        BARP(rg + 1);   // publishes red_l AND the pair's P tiles
#pragma unroll
        for (int mt = 0; mt < 2; ++mt)
#pragma unroll
            for (int h2 = 0; h2 < 2; ++h2) {
                const int row = rg * 32 + mt * 16 + lr + h2 * 8;
                lsum[mt][h2] = lsum[mt][h2] * fac[mt][h2] + red_l[row] + red_l[128 + row];
            }

#pragma unroll
        for (int mt = 0; mt < 2; ++mt)
#pragma unroll
            for (int nt = 0; nt < 4; ++nt) {
                o[mt][nt][0] *= fac[mt][0]; o[mt][nt][1] *= fac[mt][0];
                o[mt][nt][2] *= fac[mt][1]; o[mt][nt][3] *= fac[mt][1];
            }

        // ---- O += Phat * Vhi ----
#pragma unroll
        for (int ks = 0; ks < 8; ++ks) {
            uint32_t vhv[4][2];
#pragma unroll
            for (int nt2 = 0; nt2 < 2; ++nt2) {
                const int vrow = cn * 32 + nt2 * 16 + brow_off;
                const uint32_t voff = (uint32_t)(vrow * 256
                    + ((((ks << 1) | bslot_lo) ^ (vrow & 7)) << 4));
                LDSM_X4(vhv[nt2 * 2][0], vhv[nt2 * 2][1],
                        vhv[nt2 * 2 + 1][0], vhv[nt2 * 2 + 1][1], sb + AVB + voff);
            }
#pragma unroll
            for (int mt = 0; mt < 2; ++mt) {
                const int prow_ = mt * 16 + arow;
                const uint32_t poff = (uint32_t)(prow_ * 256
                    + ((((ks << 1) | aslot_hi) ^ (prow_ & 7)) << 4));
                uint32_t ph[4];
                LDSM_X4(ph[0], ph[1], ph[2], ph[3], pgbase_h + poff);
#pragma unroll
                for (int nt = 0; nt < 4; ++nt)
                    MMA_TF32(o[mt][nt], ph, vhv[nt][0], vhv[nt][1]);
            }
        }

        __syncthreads();   // all reads of K/VT done before single-buffer refill
        if (j < jmax) {
            ISSUE_K(j + 1);
            ISSUE_VT(j + 1);
            CPCOMMIT();
        }
    }

    // ---- epilogue: O hi only ----
#pragma unroll
    for (int mt = 0; mt < 2; ++mt) {
        const float inv0 = 1.f / lsum[mt][0];
        const float inv1 = 1.f / lsum[mt][1];
        const size_t rowA = ((size_t)b * S_LEN + i * 128 + rg * 32 + mt * 16 + lr) * E_DIM;
        const size_t rowB = rowA + (size_t)8 * E_DIM;
#pragma unroll
        for (int nt = 0; nt < 4; ++nt) {
            const int col = h * 64 + cn * 32 + (nt << 3) + lc0;
            *(uint2*)&s_o_hi[rowA + col] =
                make_uint2(cvt_tf32(o[mt][nt][0] * inv0), cvt_tf32(o[mt][nt][1] * inv0));
            *(uint2*)&s_o_hi[rowB + col] =
                make_uint2(cvt_tf32(o[mt][nt][2] * inv1), cvt_tf32(o[mt][nt][3] * inv1));
        }
    }
}

// ===================== launch =====================
extern "C" void kernel_launch(void* const* d_in, const int* in_sizes, int n_in,
                              void* d_out, int out_size)
{
    (void)in_sizes; (void)n_in; (void)out_size;
    const float* q  = (const float*)d_in[0];
    const float* k  = (const float*)d_in[1];
    const float* v  = (const float*)d_in[2];
    const float* Wq = (const float*)d_in[3];
    const float* bq = (const float*)d_in[4];
    const float* Wk = (const float*)d_in[5];
    const float* bk = (const float*)d_in[6];
    const float* Wv = (const float*)d_in[7];
    const float* bv = (const float*)d_in[8];
    const float* Wo = (const float*)d_in[9];
    const float* bo = (const float*)d_in[10];
    float* out = (float*)d_out;

    cudaFuncSetAttribute(gemm_tc_kernel, cudaFuncAttributeMaxDynamicSharedMemorySize, GEMM_SMEM);
    cudaFuncSetAttribute(attn_tc_kernel, cudaFuncAttributeMaxDynamicSharedMemorySize, ATTN_SMEM);

    // fused pre-split (2 launches; everything hi-only)
    dim3 gridSM((unsigned)(ME / 4 / 256), 3);
    split_me_kernel<<<gridSM, 256>>>((const float4*)q, (const float4*)k, (const float4*)v);
    dim3 gridSW((unsigned)(EE / 4 / 256), 4);
    split_w_kernel<<<gridSW, 256>>>((const float4*)Wq, (const float4*)Wk,
                                    (const float4*)Wv, (const float4*)Wo);

    // Q/K/V projections (epilogues emit attention operands, all hi-only)
    dim3 gridP(E_DIM / 128, M_ROWS / 128, 3);
    gemm_tc_kernel<<<gridP, 256, GEMM_SMEM>>>(bq, bk, bv, bo, out, 0);

    // causal flash attention, 128-row q-tiles, 2 CTAs/SM (emits O hi)
    dim3 gridA(S_LEN / 128, N_BATCH * N_HEADS);
    attn_tc_kernel<<<gridA, 256, ATTN_SMEM>>>();

    // output projection
    dim3 gridO(E_DIM / 128, M_ROWS / 128, 1);
    gemm_tc_kernel<<<gridO, 256, GEMM_SMEM>>>(bq, bk, bv, bo, out, 1);
}